// round 4
// baseline (speedup 1.0000x reference)
#include <cuda_runtime.h>
#include <math.h>
#include <stdint.h>

// ---------------------------------------------------------------------------
// Problem constants
//   inp0: (8, 2048, 768)   inp1: (8, 1024, 1536)   attn_mask: (8, 64)
//   Level 0 uses heads 0:6  -> W columns   0:384
//   Level 1 uses heads 6:12 -> W columns 384:768
//   Output: (8, 2048, 768) fp32  followed by mask (2, 2048) fp32
// ---------------------------------------------------------------------------
#define B        8
#define N0       2048
#define N1       1024
#define HD       384          // 6 heads * 64
#define D        64
#define NH       6
#define M0       (B * N0)     // 16384
#define M1       (B * N1)     // 8192
#define OUT_ELEMS ((size_t)B * N0 * 768)

// Scratch (device globals: allocation-free contract)
__device__ __align__(128) float g_q0[M0 * HD];
__device__ __align__(128) float g_k0[M0 * HD];
__device__ __align__(128) float g_v0[M0 * HD];
__device__ __align__(128) float g_q1[M1 * HD];
__device__ __align__(128) float g_k1[M1 * HD];
__device__ __align__(128) float g_v1[M1 * HD];
__device__ __align__(128) float g_o0[M0 * HD];
__device__ __align__(128) float g_o1[M1 * HD];

// ---------------------------------------------------------------------------
// 128x128x8 register-tiled SGEMM.
//   C[M, N] = A[M, K] @ W[K(rows), wOff + n]  (+ epilogue)
// mode 0: C = acc + bias[col]
// mode 1: C = (acc + bias[col]) * 0.125 + mask[(row/nseqA)*64 + (col&63)]
// mode 2: C[remapped row] += acc          (row remap: (r/nseqA)*nseqC + r%nseqA)
// All dims must be multiples of tile sizes (true for this problem).
// ---------------------------------------------------------------------------
__global__ __launch_bounds__(256) void sgemm128(
    const float* __restrict__ A, int K,
    const float* __restrict__ W, int ldw, int wOff,
    const float* __restrict__ bias,
    float* __restrict__ C, int ldc,
    int mode, const float* __restrict__ mask,
    int nseqA, int nseqC)
{
    __shared__ float As[8 * 128];
    __shared__ float Bs[8 * 128];

    const int tid = threadIdx.x;
    const int tx = tid & 15;
    const int ty = tid >> 4;
    const int m0 = blockIdx.y * 128;
    const int n0 = blockIdx.x * 128;

    const float* Ab = A + (size_t)m0 * K;
    const float* Wb = W + wOff + n0;

    float acc[8][8];
#pragma unroll
    for (int i = 0; i < 8; i++)
#pragma unroll
        for (int j = 0; j < 8; j++) acc[i][j] = 0.f;

    const int aRow = tid >> 1;           // 0..127
    const int aK4  = (tid & 1) << 2;     // 0 or 4
    const int bRow = tid >> 5;           // 0..7
    const int bCol = (tid & 31) << 2;    // 0..124

    for (int k0 = 0; k0 < K; k0 += 8) {
        float4 a4 = *(const float4*)(Ab + (size_t)aRow * K + k0 + aK4);
        As[(aK4 + 0) * 128 + aRow] = a4.x;
        As[(aK4 + 1) * 128 + aRow] = a4.y;
        As[(aK4 + 2) * 128 + aRow] = a4.z;
        As[(aK4 + 3) * 128 + aRow] = a4.w;
        *(float4*)&Bs[bRow * 128 + bCol] =
            *(const float4*)(Wb + (size_t)(k0 + bRow) * ldw + bCol);
        __syncthreads();

#pragma unroll
        for (int kk = 0; kk < 8; kk++) {
            float4 a0 = *(const float4*)&As[kk * 128 + ty * 8];
            float4 a1 = *(const float4*)&As[kk * 128 + ty * 8 + 4];
            float4 b0 = *(const float4*)&Bs[kk * 128 + tx * 8];
            float4 b1 = *(const float4*)&Bs[kk * 128 + tx * 8 + 4];
            float av[8] = {a0.x, a0.y, a0.z, a0.w, a1.x, a1.y, a1.z, a1.w};
            float bv[8] = {b0.x, b0.y, b0.z, b0.w, b1.x, b1.y, b1.z, b1.w};
#pragma unroll
            for (int i = 0; i < 8; i++)
#pragma unroll
                for (int j = 0; j < 8; j++)
                    acc[i][j] += av[i] * bv[j];
        }
        __syncthreads();
    }

    // Epilogue
#pragma unroll
    for (int i = 0; i < 8; i++) {
        int grow = m0 + ty * 8 + i;
        int orow = (grow / nseqA) * nseqC + (grow % nseqA);
        int bidx = (grow / nseqA) * 64;
#pragma unroll
        for (int j = 0; j < 8; j++) {
            int col = n0 + tx * 8 + j;
            float c = acc[i][j];
            if (mode == 0) {
                c += bias[col];
            } else if (mode == 1) {
                c = (c + bias[col]) * 0.125f + mask[bidx + (col & 63)];
            } else {  // mode 2: accumulate
                c += C[(size_t)orow * ldc + col];
            }
            C[(size_t)orow * ldc + col] = c;
        }
    }
}

// ---------------------------------------------------------------------------
// Flash attention, 64-row query tile per block, d = 64, 6 heads packed into
// [B, N, 384] buffers (col = h*64 + d). 256 threads, 4x4 register tile per
// thread for both S and O. Online softmax. Padded (68) smem rows for
// conflict-free float4 reads.
// ---------------------------------------------------------------------------
#define PAD 68
#define ATTN_SMEM_BYTES (4 * 64 * PAD * 4)

__global__ __launch_bounds__(256) void attn_kernel(
    const float* __restrict__ qm, const float* __restrict__ km,
    const float* __restrict__ vm, float* __restrict__ om, int Nq)
{
    extern __shared__ float sm[];
    float* Qs = sm;                  // [64][PAD]  rows = query, cols = d
    float* Ks = sm + 64 * PAD;       // [64][PAD]  rows = key,   cols = d
    float* Vt = sm + 2 * 64 * PAD;   // [64][PAD]  rows = d(out col), cols = m
    float* Ps = sm + 3 * 64 * PAD;   // [64][PAD]  rows = query, cols = m

    const int tid = threadIdx.x;
    const int tx = tid & 15;
    const int ty = tid >> 4;
    const int bh = blockIdx.y;
    const int b = bh / NH, h = bh % NH;
    const int n0 = blockIdx.x * 64;
    const size_t base = (size_t)b * Nq * HD + h * D;

    // load Q tile (float4)
    for (int i = tid; i < 1024; i += 256) {
        int r = i >> 4, c4 = (i & 15) << 2;
        *(float4*)&Qs[r * PAD + c4] =
            *(const float4*)(qm + base + (size_t)(n0 + r) * HD + c4);
    }

    const int r0 = ty * 4, c0 = tx * 4;
    float mrow[4], lrow[4], Oa[4][4];
#pragma unroll
    for (int i = 0; i < 4; i++) {
        mrow[i] = -1e30f;
        lrow[i] = 0.f;
#pragma unroll
        for (int j = 0; j < 4; j++) Oa[i][j] = 0.f;
    }

    for (int m0 = 0; m0 < Nq; m0 += 64) {
        // load K tile (row = key, col = d), V transposed (row = d, col = key)
        for (int i = tid; i < 1024; i += 256) {
            int r = i >> 4, c4 = (i & 15) << 2;
            *(float4*)&Ks[r * PAD + c4] =
                *(const float4*)(km + base + (size_t)(m0 + r) * HD + c4);
        }
        for (int i = tid; i < 4096; i += 256) {
            int c = i & 63, r = i >> 6;
            Vt[c * PAD + r] = vm[base + (size_t)(m0 + r) * HD + c];
        }
        __syncthreads();

        // S = Q K^T  (4x4 per thread)
        float s[4][4];
#pragma unroll
        for (int i = 0; i < 4; i++)
#pragma unroll
            for (int j = 0; j < 4; j++) s[i][j] = 0.f;

#pragma unroll 4
        for (int d4 = 0; d4 < 64; d4 += 4) {
            float4 qf[4], kf[4];
#pragma unroll
            for (int i = 0; i < 4; i++) qf[i] = *(const float4*)&Qs[(r0 + i) * PAD + d4];
#pragma unroll
            for (int j = 0; j < 4; j++) kf[j] = *(const float4*)&Ks[(c0 + j) * PAD + d4];
#pragma unroll
            for (int i = 0; i < 4; i++)
#pragma unroll
                for (int j = 0; j < 4; j++)
                    s[i][j] += qf[i].x * kf[j].x + qf[i].y * kf[j].y +
                               qf[i].z * kf[j].z + qf[i].w * kf[j].w;
        }

        // online softmax (row groups span one 16-lane half-warp: same ty)
#pragma unroll
        for (int i = 0; i < 4; i++) {
            float mx = fmaxf(fmaxf(s[i][0], s[i][1]), fmaxf(s[i][2], s[i][3]));
#pragma unroll
            for (int off = 8; off > 0; off >>= 1)
                mx = fmaxf(mx, __shfl_xor_sync(0xffffffffu, mx, off));
            float mnew = fmaxf(mrow[i], mx);
            float corr = __expf(mrow[i] - mnew);
            float rs = 0.f;
#pragma unroll
            for (int j = 0; j < 4; j++) {
                float p = __expf(s[i][j] - mnew);
                s[i][j] = p;
                rs += p;
            }
#pragma unroll
            for (int off = 8; off > 0; off >>= 1)
                rs += __shfl_xor_sync(0xffffffffu, rs, off);
            lrow[i] = lrow[i] * corr + rs;
            mrow[i] = mnew;
#pragma unroll
            for (int j = 0; j < 4; j++) Oa[i][j] *= corr;
        }

        // publish P tile
#pragma unroll
        for (int i = 0; i < 4; i++)
            *(float4*)&Ps[(r0 + i) * PAD + c0] =
                make_float4(s[i][0], s[i][1], s[i][2], s[i][3]);
        __syncthreads();

        // O += P @ V
#pragma unroll 4
        for (int m4 = 0; m4 < 64; m4 += 4) {
            float4 pf[4], vf[4];
#pragma unroll
            for (int i = 0; i < 4; i++) pf[i] = *(const float4*)&Ps[(r0 + i) * PAD + m4];
#pragma unroll
            for (int j = 0; j < 4; j++) vf[j] = *(const float4*)&Vt[(c0 + j) * PAD + m4];
#pragma unroll
            for (int i = 0; i < 4; i++)
#pragma unroll
                for (int j = 0; j < 4; j++)
                    Oa[i][j] += pf[i].x * vf[j].x + pf[i].y * vf[j].y +
                                pf[i].z * vf[j].z + pf[i].w * vf[j].w;
        }
        __syncthreads();
    }

    // normalize + store (merged layout: col = h*64 + d)
#pragma unroll
    for (int i = 0; i < 4; i++) {
        float inv = 1.f / lrow[i];
#pragma unroll
        for (int j = 0; j < 4; j++)
            om[base + (size_t)(n0 + r0 + i) * HD + c0 + j] = Oa[i][j] * inv;
    }
}

// ---------------------------------------------------------------------------
// Output mask: [2, 2048]; level 0 all ones, level 1 first 1024 ones.
// ---------------------------------------------------------------------------
__global__ void mask_kernel(float* __restrict__ out)
{
    int i = blockIdx.x * blockDim.x + threadIdx.x;
    if (i < 2 * N0) {
        int lvl = i >> 11, n = i & (N0 - 1);
        out[i] = (lvl == 0 || n < N1) ? 1.f : 0.f;
    }
}

// ---------------------------------------------------------------------------
extern "C" void kernel_launch(void* const* d_in, const int* in_sizes, int n_in,
                              void* d_out, int out_size)
{
    (void)in_sizes; (void)n_in; (void)out_size;
    const float* inp0  = (const float*)d_in[0];
    const float* inp1  = (const float*)d_in[1];
    const float* amask = (const float*)d_in[2];
    const float* Wq0 = (const float*)d_in[3];
    const float* bq0 = (const float*)d_in[4];
    const float* Wk0 = (const float*)d_in[5];
    const float* bk0 = (const float*)d_in[6];
    const float* Wv0 = (const float*)d_in[7];
    const float* bv0 = (const float*)d_in[8];
    const float* Wq1 = (const float*)d_in[9];
    const float* bq1 = (const float*)d_in[10];
    const float* Wk1 = (const float*)d_in[11];
    const float* bk1 = (const float*)d_in[12];
    const float* Wv1 = (const float*)d_in[13];
    const float* bv1 = (const float*)d_in[14];
    const float* Wo  = (const float*)d_in[15];
    const float* bo  = (const float*)d_in[16];
    float* out = (float*)d_out;

    float *q0, *k0, *v0, *q1, *k1, *v1, *o0, *o1;
    cudaGetSymbolAddress((void**)&q0, g_q0);
    cudaGetSymbolAddress((void**)&k0, g_k0);
    cudaGetSymbolAddress((void**)&v0, g_v0);
    cudaGetSymbolAddress((void**)&q1, g_q1);
    cudaGetSymbolAddress((void**)&k1, g_k1);
    cudaGetSymbolAddress((void**)&v1, g_v1);
    cudaGetSymbolAddress((void**)&o0, g_o0);
    cudaGetSymbolAddress((void**)&o1, g_o1);

    cudaFuncSetAttribute(attn_kernel,
                         cudaFuncAttributeMaxDynamicSharedMemorySize,
                         ATTN_SMEM_BYTES);

    dim3 blk(256);

    // Level-0 projections: (16384 x 768) @ W[:, 0:384]
    sgemm128<<<dim3(3, 128), blk>>>(inp0, 768, Wq0, 768, 0, bq0, q0, HD, 1, amask, N0, N0);
    sgemm128<<<dim3(3, 128), blk>>>(inp0, 768, Wk0, 768, 0, bk0, k0, HD, 0, nullptr, N0, N0);
    sgemm128<<<dim3(3, 128), blk>>>(inp0, 768, Wv0, 768, 0, bv0, v0, HD, 0, nullptr, N0, N0);
    // Level-1 projections: (8192 x 1536) @ W[:, 384:768]
    sgemm128<<<dim3(3, 64), blk>>>(inp1, 1536, Wq1, 768, 384, bq1 + 384, q1, HD, 1, amask, N1, N1);
    sgemm128<<<dim3(3, 64), blk>>>(inp1, 1536, Wk1, 768, 384, bk1 + 384, k1, HD, 0, nullptr, N1, N1);
    sgemm128<<<dim3(3, 64), blk>>>(inp1, 1536, Wv1, 768, 384, bv1 + 384, v1, HD, 0, nullptr, N1, N1);

    // Attention (per level)
    attn_kernel<<<dim3(N0 / 64, B * NH), blk, ATTN_SMEM_BYTES>>>(q0, k0, v0, o0, N0);
    attn_kernel<<<dim3(N1 / 64, B * NH), blk, ATTN_SMEM_BYTES>>>(q1, k1, v1, o1, N1);

    // Output projection: out = o0 @ Wo[0:384,:] + bo; rows n<1024 += o1 @ Wo[768:1152,:]
    sgemm128<<<dim3(6, 128), blk>>>(o0, HD, Wo, 768, 0, bo, out, 768, 0, nullptr, N0, N0);
    sgemm128<<<dim3(6, 64),  blk>>>(o1, HD, Wo + 768 * 768, 768, 0, nullptr, out, 768, 2, nullptr, N1, N0);

    // Mask tail
    mask_kernel<<<16, 256>>>(out + OUT_ELEMS);
}

// round 5
// speedup vs baseline: 3.0372x; 3.0372x over previous
#include <cuda_runtime.h>
#include <cuda_bf16.h>
#include <math.h>
#include <stdint.h>

#define B        8
#define N0       2048
#define N1       1024
#define HD       384
#define NH       6
#define M0       (B * N0)
#define M1       (B * N1)
#define OUT_ELEMS ((size_t)B * N0 * 768)

// Scratch: q/k/v stored pre-split (hi/lo bf16); o fp32.
__device__ __align__(128) __nv_bfloat16 g_qh0[M0 * HD];
__device__ __align__(128) __nv_bfloat16 g_ql0[M0 * HD];
__device__ __align__(128) __nv_bfloat16 g_kh0[M0 * HD];
__device__ __align__(128) __nv_bfloat16 g_kl0[M0 * HD];
__device__ __align__(128) __nv_bfloat16 g_vh0[M0 * HD];
__device__ __align__(128) __nv_bfloat16 g_vl0[M0 * HD];
__device__ __align__(128) __nv_bfloat16 g_qh1[M1 * HD];
__device__ __align__(128) __nv_bfloat16 g_ql1[M1 * HD];
__device__ __align__(128) __nv_bfloat16 g_kh1[M1 * HD];
__device__ __align__(128) __nv_bfloat16 g_kl1[M1 * HD];
__device__ __align__(128) __nv_bfloat16 g_vh1[M1 * HD];
__device__ __align__(128) __nv_bfloat16 g_vl1[M1 * HD];
__device__ __align__(128) float g_o0[M0 * HD];
__device__ __align__(128) float g_o1[M1 * HD];

__device__ __forceinline__ uint32_t sm_u32(const void* p) {
    return (uint32_t)__cvta_generic_to_shared(p);
}
__device__ __forceinline__ void ldsm4(uint32_t r[4], uint32_t a) {
    asm volatile("ldmatrix.sync.aligned.m8n8.x4.shared.b16 {%0,%1,%2,%3}, [%4];"
        : "=r"(r[0]), "=r"(r[1]), "=r"(r[2]), "=r"(r[3]) : "r"(a));
}
__device__ __forceinline__ void ldsm4t(uint32_t r[4], uint32_t a) {
    asm volatile("ldmatrix.sync.aligned.m8n8.x4.trans.shared.b16 {%0,%1,%2,%3}, [%4];"
        : "=r"(r[0]), "=r"(r[1]), "=r"(r[2]), "=r"(r[3]) : "r"(a));
}
__device__ __forceinline__ void mma16816(float d[4], const uint32_t a[4],
                                          uint32_t b0, uint32_t b1) {
    asm volatile(
        "mma.sync.aligned.m16n8k16.row.col.f32.bf16.bf16.f32 "
        "{%0,%1,%2,%3}, {%4,%5,%6,%7}, {%8,%9}, {%0,%1,%2,%3};"
        : "+f"(d[0]), "+f"(d[1]), "+f"(d[2]), "+f"(d[3])
        : "r"(a[0]), "r"(a[1]), "r"(a[2]), "r"(a[3]), "r"(b0), "r"(b1));
}
__device__ __forceinline__ uint32_t bpack(float lo, float hi) {
    __nv_bfloat162 t = __floats2bfloat162_rn(lo, hi);
    return *reinterpret_cast<uint32_t*>(&t);
}
__device__ __forceinline__ void fsplit(float x, float& h, float& l) {
    __nv_bfloat16 b = __float2bfloat16(x);
    h = __bfloat162float(b);
    l = x - h;
}

// ---------------------------------------------------------------------------
// Tensor-core GEMM: C[M,N] = A[M,K] @ W[K, wOff+n], bf16x3 split, CTA 128x128,
// 8 warps (2x4 of 64x32), k-stage 32, double-buffered smem.
// mode 0: fp32 out + bias      mode 1: q-epilogue -> split bf16
// mode 2: +bias -> split bf16  mode 3: fp32 accumulate w/ row remap
// ---------------------------------------------------------------------------
#define GAS 40
#define GBS 136
#define GEMM_SMEM ((2 * 128 * GAS * 2 + 2 * 32 * GBS * 2) * 2)

__global__ __launch_bounds__(256) void mma_gemm(
    const float* __restrict__ A, int K,
    const float* __restrict__ W, int ldw, int wOff,
    const float* __restrict__ bias,
    float* __restrict__ Cf,
    __nv_bfloat16* __restrict__ Ch, __nv_bfloat16* __restrict__ Cl,
    int ldc, int mode, const float* __restrict__ mask,
    int nseqA, int nseqC)
{
    extern __shared__ __nv_bfloat16 ds[];
    __nv_bfloat16* Ah = ds;
    __nv_bfloat16* Al = Ah + 2 * 128 * GAS;
    __nv_bfloat16* Bh = Al + 2 * 128 * GAS;
    __nv_bfloat16* Bl = Bh + 2 * 32 * GBS;

    const int tid = threadIdx.x, lane = tid & 31, warp = tid >> 5;
    const int m0 = blockIdx.y * 128, n0 = blockIdx.x * 128;
    const int mrow = (warp >> 2) * 64, ncol = (warp & 3) * 32;

    const float* Ag = A + (size_t)(m0 + (tid >> 1)) * K + ((tid & 1) << 4);
    const float* Wg = W + (size_t)(tid >> 3) * ldw + wOff + n0 + ((tid & 7) << 4);
    const int aoff = (tid >> 1) * GAS + ((tid & 1) << 4);
    const int boff = (tid >> 3) * GBS + ((tid & 7) << 4);

    float acc[4][4][4];
#pragma unroll
    for (int i = 0; i < 4; i++)
#pragma unroll
        for (int j = 0; j < 4; j++)
#pragma unroll
            for (int k = 0; k < 4; k++) acc[i][j][k] = 0.f;

    float ar[16], br[16];
#pragma unroll
    for (int i = 0; i < 4; i++) {
        *(float4*)&ar[i * 4] = *(const float4*)(Ag + i * 4);
        *(float4*)&br[i * 4] = *(const float4*)(Wg + i * 4);
    }

    auto stage = [&](int buf) {
        uint32_t hh[8], ll[8];
#pragma unroll
        for (int i = 0; i < 8; i++) {
            float h0, l0, h1, l1;
            fsplit(ar[2 * i], h0, l0);
            fsplit(ar[2 * i + 1], h1, l1);
            hh[i] = bpack(h0, h1);
            ll[i] = bpack(l0, l1);
        }
        __nv_bfloat16* pah = Ah + buf * 128 * GAS + aoff;
        __nv_bfloat16* pal = Al + buf * 128 * GAS + aoff;
        ((uint4*)pah)[0] = make_uint4(hh[0], hh[1], hh[2], hh[3]);
        ((uint4*)pah)[1] = make_uint4(hh[4], hh[5], hh[6], hh[7]);
        ((uint4*)pal)[0] = make_uint4(ll[0], ll[1], ll[2], ll[3]);
        ((uint4*)pal)[1] = make_uint4(ll[4], ll[5], ll[6], ll[7]);
#pragma unroll
        for (int i = 0; i < 8; i++) {
            float h0, l0, h1, l1;
            fsplit(br[2 * i], h0, l0);
            fsplit(br[2 * i + 1], h1, l1);
            hh[i] = bpack(h0, h1);
            ll[i] = bpack(l0, l1);
        }
        __nv_bfloat16* pbh = Bh + buf * 32 * GBS + boff;
        __nv_bfloat16* pbl = Bl + buf * 32 * GBS + boff;
        ((uint4*)pbh)[0] = make_uint4(hh[0], hh[1], hh[2], hh[3]);
        ((uint4*)pbh)[1] = make_uint4(hh[4], hh[5], hh[6], hh[7]);
        ((uint4*)pbl)[0] = make_uint4(ll[0], ll[1], ll[2], ll[3]);
        ((uint4*)pbl)[1] = make_uint4(ll[4], ll[5], ll[6], ll[7]);
    };
    stage(0);
    __syncthreads();

    int buf = 0;
    for (int k0 = 0; k0 < K; k0 += 32) {
        const bool pf = (k0 + 32) < K;
        if (pf) {
#pragma unroll
            for (int i = 0; i < 4; i++) {
                *(float4*)&ar[i * 4] = *(const float4*)(Ag + (k0 + 32) + i * 4);
                *(float4*)&br[i * 4] =
                    *(const float4*)(Wg + (size_t)(k0 + 32) * ldw + i * 4);
            }
        }
        const uint32_t aBH = sm_u32(Ah + buf * 128 * GAS);
        const uint32_t aBL = sm_u32(Al + buf * 128 * GAS);
        const uint32_t bBH = sm_u32(Bh + buf * 32 * GBS);
        const uint32_t bBL = sm_u32(Bl + buf * 32 * GBS);

#pragma unroll
        for (int kk = 0; kk < 32; kk += 16) {
            uint32_t ah[4][4], al[4][4];
#pragma unroll
            for (int im = 0; im < 4; im++) {
                uint32_t ad = (uint32_t)((mrow + im * 16 + (lane & 15)) * GAS +
                                         kk + ((lane >> 4) << 3)) * 2;
                ldsm4(ah[im], aBH + ad);
                ldsm4(al[im], aBL + ad);
            }
#pragma unroll
            for (int nf = 0; nf < 2; nf++) {
                uint32_t bd = (uint32_t)((kk + (lane & 15)) * GBS + ncol +
                                         nf * 16 + ((lane >> 4) << 3)) * 2;
                uint32_t bh4[4], bl4[4];
                ldsm4t(bh4, bBH + bd);
                ldsm4t(bl4, bBL + bd);
#pragma unroll
                for (int im = 0; im < 4; im++) {
#pragma unroll
                    for (int j = 0; j < 2; j++) {
                        float* d = acc[im][nf * 2 + j];
                        mma16816(d, ah[im], bh4[2 * j], bh4[2 * j + 1]);
                        mma16816(d, ah[im], bl4[2 * j], bl4[2 * j + 1]);
                        mma16816(d, al[im], bh4[2 * j], bh4[2 * j + 1]);
                    }
                }
            }
        }
        if (pf) stage(buf ^ 1);
        __syncthreads();
        buf ^= 1;
    }

#pragma unroll
    for (int im = 0; im < 4; im++) {
        int r0g = m0 + mrow + im * 16 + (lane >> 2);
#pragma unroll
        for (int f = 0; f < 4; f++) {
            int gcol = n0 + ncol + f * 8 + ((lane & 3) << 1);
            float* d = acc[im][f];
#pragma unroll
            for (int hf = 0; hf < 2; hf++) {
                int rr = r0g + hf * 8;
                float v0 = d[hf * 2], v1 = d[hf * 2 + 1];
                if (mode == 0) {
                    Cf[(size_t)rr * ldc + gcol]     = v0 + bias[gcol];
                    Cf[(size_t)rr * ldc + gcol + 1] = v1 + bias[gcol + 1];
                } else if (mode == 3) {
                    int orow = (rr / nseqA) * nseqC + (rr % nseqA);
                    Cf[(size_t)orow * ldc + gcol]     += v0;
                    Cf[(size_t)orow * ldc + gcol + 1] += v1;
                } else {
                    float x0 = v0 + bias[gcol], x1 = v1 + bias[gcol + 1];
                    if (mode == 1) {
                        const float* mk = mask + (rr / nseqA) * 64;
                        x0 = x0 * 0.125f + mk[gcol & 63];
                        x1 = x1 * 0.125f + mk[(gcol + 1) & 63];
                    }
                    size_t o = (size_t)rr * ldc + gcol;
                    __nv_bfloat16 b0 = __float2bfloat16(x0);
                    Ch[o] = b0;
                    Cl[o] = __float2bfloat16(x0 - __bfloat162float(b0));
                    __nv_bfloat16 b1 = __float2bfloat16(x1);
                    Ch[o + 1] = b1;
                    Cl[o + 1] = __float2bfloat16(x1 - __bfloat162float(b1));
                }
            }
        }
    }
}

// ---------------------------------------------------------------------------
// Tensor-core flash attention: CTA = 128 q-rows x (b,h); 8 warps, each m16.
// Q frags register-resident; KV (hi/lo) staged in smem per 64-key tile;
// P frags built in registers. Online softmax fp32.
// ---------------------------------------------------------------------------
#define AS 72

__global__ __launch_bounds__(256) void attn_mma(
    const __nv_bfloat16* __restrict__ qh, const __nv_bfloat16* __restrict__ ql,
    const __nv_bfloat16* __restrict__ kh, const __nv_bfloat16* __restrict__ kl,
    const __nv_bfloat16* __restrict__ vh, const __nv_bfloat16* __restrict__ vl,
    float* __restrict__ om, int Nq)
{
    __shared__ __align__(16) __nv_bfloat16 smem[4 * 64 * AS];
    __nv_bfloat16* sKh = smem;
    __nv_bfloat16* sKl = smem + 64 * AS;
    __nv_bfloat16* sVh = smem + 2 * 64 * AS;
    __nv_bfloat16* sVl = smem + 3 * 64 * AS;

    const int tid = threadIdx.x, lane = tid & 31, warp = tid >> 5;
    const int b = blockIdx.y / NH, h = blockIdx.y % NH;
    const int q0 = blockIdx.x * 128;
    const size_t gb = (size_t)b * Nq * HD + (size_t)h * 64;
    const int mrow = warp * 16;

    {   // stage Q (hi into sKh area, lo into sVh area), pull frags, release
        const __nv_bfloat16* Qh = qh + gb + (size_t)q0 * HD;
        const __nv_bfloat16* Ql = ql + gb + (size_t)q0 * HD;
#pragma unroll
        for (int it = 0; it < 4; it++) {
            int i = tid + it * 256;
            int r = i >> 3, u = (i & 7) * 8;
            *(uint4*)&smem[r * AS + u] = *(const uint4*)&Qh[(size_t)r * HD + u];
            *(uint4*)&smem[2 * 64 * AS + r * AS + u] =
                *(const uint4*)&Ql[(size_t)r * HD + u];
        }
    }
    __syncthreads();
    uint32_t qfh[4][4], qfl[4][4];
    {
        const uint32_t bh_ = sm_u32(smem);
        const uint32_t bl_ = sm_u32(smem + 2 * 64 * AS);
        int row = mrow + (lane & 15);
#pragma unroll
        for (int kk = 0; kk < 4; kk++) {
            uint32_t off = (uint32_t)(row * AS + kk * 16 + ((lane >> 4) << 3)) * 2;
            ldsm4(qfh[kk], bh_ + off);
            ldsm4(qfl[kk], bl_ + off);
        }
    }
    __syncthreads();

    float o[8][4];
#pragma unroll
    for (int f = 0; f < 8; f++)
#pragma unroll
        for (int k = 0; k < 4; k++) o[f][k] = 0.f;
    float mr0 = -1e30f, mr1 = -1e30f, lr0 = 0.f, lr1 = 0.f;

    const uint32_t kBH = sm_u32(sKh), kBL = sm_u32(sKl);
    const uint32_t vBH = sm_u32(sVh), vBL = sm_u32(sVl);

    for (int kv = 0; kv < Nq; kv += 64) {
        {
            const __nv_bfloat16* Kh = kh + gb + (size_t)kv * HD;
            const __nv_bfloat16* Kl = kl + gb + (size_t)kv * HD;
            const __nv_bfloat16* Vh = vh + gb + (size_t)kv * HD;
            const __nv_bfloat16* Vl = vl + gb + (size_t)kv * HD;
#pragma unroll
            for (int it = 0; it < 2; it++) {
                int i = tid + it * 256;
                int r = i >> 3, u = (i & 7) * 8;
                size_t go = (size_t)r * HD + u;
                int so = r * AS + u;
                *(uint4*)&sKh[so] = *(const uint4*)&Kh[go];
                *(uint4*)&sKl[so] = *(const uint4*)&Kl[go];
                *(uint4*)&sVh[so] = *(const uint4*)&Vh[go];
                *(uint4*)&sVl[so] = *(const uint4*)&Vl[go];
            }
        }
        __syncthreads();

        // S = Q @ K^T
        float s[8][4];
#pragma unroll
        for (int f = 0; f < 8; f++)
#pragma unroll
            for (int k = 0; k < 4; k++) s[f][k] = 0.f;
#pragma unroll
        for (int kk = 0; kk < 4; kk++) {
#pragma unroll
            for (int nf = 0; nf < 4; nf++) {
                uint32_t ad = (uint32_t)((nf * 16 + (lane & 15)) * AS + kk * 16 +
                                         ((lane >> 4) << 3)) * 2;
                uint32_t kb[4], kl4[4];
                ldsm4(kb, kBH + ad);
                ldsm4(kl4, kBL + ad);
                mma16816(s[nf * 2],     qfh[kk], kb[0],  kb[2]);
                mma16816(s[nf * 2],     qfh[kk], kl4[0], kl4[2]);
                mma16816(s[nf * 2],     qfl[kk], kb[0],  kb[2]);
                mma16816(s[nf * 2 + 1], qfh[kk], kb[1],  kb[3]);
                mma16816(s[nf * 2 + 1], qfh[kk], kl4[1], kl4[3]);
                mma16816(s[nf * 2 + 1], qfl[kk], kb[1],  kb[3]);
            }
        }

        // online softmax: rows lane/4 (0-regs) and lane/4+8 (2-regs)
        float mx0 = -1e30f, mx1 = -1e30f;
#pragma unroll
        for (int f = 0; f < 8; f++) {
            mx0 = fmaxf(mx0, fmaxf(s[f][0], s[f][1]));
            mx1 = fmaxf(mx1, fmaxf(s[f][2], s[f][3]));
        }
        mx0 = fmaxf(mx0, __shfl_xor_sync(0xffffffffu, mx0, 1));
        mx0 = fmaxf(mx0, __shfl_xor_sync(0xffffffffu, mx0, 2));
        mx1 = fmaxf(mx1, __shfl_xor_sync(0xffffffffu, mx1, 1));
        mx1 = fmaxf(mx1, __shfl_xor_sync(0xffffffffu, mx1, 2));
        float mn0 = fmaxf(mr0, mx0), mn1 = fmaxf(mr1, mx1);
        float c0 = __expf(mr0 - mn0), c1 = __expf(mr1 - mn1);
        float rs0 = 0.f, rs1 = 0.f;
#pragma unroll
        for (int f = 0; f < 8; f++) {
            s[f][0] = __expf(s[f][0] - mn0);
            s[f][1] = __expf(s[f][1] - mn0);
            s[f][2] = __expf(s[f][2] - mn1);
            s[f][3] = __expf(s[f][3] - mn1);
            rs0 += s[f][0] + s[f][1];
            rs1 += s[f][2] + s[f][3];
        }
        rs0 += __shfl_xor_sync(0xffffffffu, rs0, 1);
        rs0 += __shfl_xor_sync(0xffffffffu, rs0, 2);
        rs1 += __shfl_xor_sync(0xffffffffu, rs1, 1);
        rs1 += __shfl_xor_sync(0xffffffffu, rs1, 2);
        lr0 = lr0 * c0 + rs0;
        lr1 = lr1 * c1 + rs1;
        mr0 = mn0;
        mr1 = mn1;
#pragma unroll
        for (int f = 0; f < 8; f++) {
            o[f][0] *= c0; o[f][1] *= c0; o[f][2] *= c1; o[f][3] *= c1;
        }

        // O += P @ V (P frags from registers, split hi/lo)
#pragma unroll
        for (int kk2 = 0; kk2 < 4; kk2++) {
            uint32_t pah[4], pal[4];
            {
                int f0 = kk2 * 2;
                float h0, l0, h1, l1;
                fsplit(s[f0][0], h0, l0);     fsplit(s[f0][1], h1, l1);
                pah[0] = bpack(h0, h1);       pal[0] = bpack(l0, l1);
                fsplit(s[f0][2], h0, l0);     fsplit(s[f0][3], h1, l1);
                pah[1] = bpack(h0, h1);       pal[1] = bpack(l0, l1);
                fsplit(s[f0 + 1][0], h0, l0); fsplit(s[f0 + 1][1], h1, l1);
                pah[2] = bpack(h0, h1);       pal[2] = bpack(l0, l1);
                fsplit(s[f0 + 1][2], h0, l0); fsplit(s[f0 + 1][3], h1, l1);
                pah[3] = bpack(h0, h1);       pal[3] = bpack(l0, l1);
            }
#pragma unroll
            for (int nf = 0; nf < 4; nf++) {
                uint32_t ad = (uint32_t)((kk2 * 16 + (lane & 15)) * AS + nf * 16 +
                                         ((lane >> 4) << 3)) * 2;
                uint32_t vb[4], vl4[4];
                ldsm4t(vb, vBH + ad);
                ldsm4t(vl4, vBL + ad);
                mma16816(o[nf * 2],     pah, vb[0],  vb[1]);
                mma16816(o[nf * 2],     pah, vl4[0], vl4[1]);
                mma16816(o[nf * 2],     pal, vb[0],  vb[1]);
                mma16816(o[nf * 2 + 1], pah, vb[2],  vb[3]);
                mma16816(o[nf * 2 + 1], pah, vl4[2], vl4[3]);
                mma16816(o[nf * 2 + 1], pal, vb[2],  vb[3]);
            }
        }
        __syncthreads();
    }

    float i0 = 1.f / lr0, i1 = 1.f / lr1;
    int rg = q0 + mrow + (lane >> 2);
#pragma unroll
    for (int f = 0; f < 8; f++) {
        int cc = f * 8 + ((lane & 3) << 1);
        *(float2*)&om[gb + (size_t)rg * HD + cc] =
            make_float2(o[f][0] * i0, o[f][1] * i0);
        *(float2*)&om[gb + (size_t)(rg + 8) * HD + cc] =
            make_float2(o[f][2] * i1, o[f][3] * i1);
    }
}

__global__ void mask_kernel(float* __restrict__ out)
{
    int i = blockIdx.x * blockDim.x + threadIdx.x;
    if (i < 2 * N0) {
        int lvl = i >> 11, n = i & (N0 - 1);
        out[i] = (lvl == 0 || n < N1) ? 1.f : 0.f;
    }
}

extern "C" void kernel_launch(void* const* d_in, const int* in_sizes, int n_in,
                              void* d_out, int out_size)
{
    (void)in_sizes; (void)n_in; (void)out_size;
    const float* inp0  = (const float*)d_in[0];
    const float* inp1  = (const float*)d_in[1];
    const float* amask = (const float*)d_in[2];
    const float* Wq0 = (const float*)d_in[3];
    const float* bq0 = (const float*)d_in[4];
    const float* Wk0 = (const float*)d_in[5];
    const float* bk0 = (const float*)d_in[6];
    const float* Wv0 = (const float*)d_in[7];
    const float* bv0 = (const float*)d_in[8];
    const float* Wq1 = (const float*)d_in[9];
    const float* bq1 = (const float*)d_in[10];
    const float* Wk1 = (const float*)d_in[11];
    const float* bk1 = (const float*)d_in[12];
    const float* Wv1 = (const float*)d_in[13];
    const float* bv1 = (const float*)d_in[14];
    const float* Wo  = (const float*)d_in[15];
    const float* bo  = (const float*)d_in[16];
    float* out = (float*)d_out;

    __nv_bfloat16 *qh0, *ql0, *kh0, *kl0, *vh0, *vl0;
    __nv_bfloat16 *qh1, *ql1, *kh1, *kl1, *vh1, *vl1;
    float *o0, *o1;
    cudaGetSymbolAddress((void**)&qh0, g_qh0);
    cudaGetSymbolAddress((void**)&ql0, g_ql0);
    cudaGetSymbolAddress((void**)&kh0, g_kh0);
    cudaGetSymbolAddress((void**)&kl0, g_kl0);
    cudaGetSymbolAddress((void**)&vh0, g_vh0);
    cudaGetSymbolAddress((void**)&vl0, g_vl0);
    cudaGetSymbolAddress((void**)&qh1, g_qh1);
    cudaGetSymbolAddress((void**)&ql1, g_ql1);
    cudaGetSymbolAddress((void**)&kh1, g_kh1);
    cudaGetSymbolAddress((void**)&kl1, g_kl1);
    cudaGetSymbolAddress((void**)&vh1, g_vh1);
    cudaGetSymbolAddress((void**)&vl1, g_vl1);
    cudaGetSymbolAddress((void**)&o0, g_o0);
    cudaGetSymbolAddress((void**)&o1, g_o1);

    cudaFuncSetAttribute(mma_gemm, cudaFuncAttributeMaxDynamicSharedMemorySize,
                         GEMM_SMEM);
    dim3 blk(256);
    const int GS = GEMM_SMEM;

    // Projections (level 0: K=768 cols 0:384; level 1: K=1536 cols 384:768)
    mma_gemm<<<dim3(3, 128), blk, GS>>>(inp0, 768, Wq0, 768, 0, bq0,
                                        nullptr, qh0, ql0, HD, 1, amask, N0, N0);
    mma_gemm<<<dim3(3, 128), blk, GS>>>(inp0, 768, Wk0, 768, 0, bk0,
                                        nullptr, kh0, kl0, HD, 2, nullptr, N0, N0);
    mma_gemm<<<dim3(3, 128), blk, GS>>>(inp0, 768, Wv0, 768, 0, bv0,
                                        nullptr, vh0, vl0, HD, 2, nullptr, N0, N0);
    mma_gemm<<<dim3(3, 64), blk, GS>>>(inp1, 1536, Wq1, 768, 384, bq1 + 384,
                                       nullptr, qh1, ql1, HD, 1, amask, N1, N1);
    mma_gemm<<<dim3(3, 64), blk, GS>>>(inp1, 1536, Wk1, 768, 384, bk1 + 384,
                                       nullptr, kh1, kl1, HD, 2, nullptr, N1, N1);
    mma_gemm<<<dim3(3, 64), blk, GS>>>(inp1, 1536, Wv1, 768, 384, bv1 + 384,
                                       nullptr, vh1, vl1, HD, 2, nullptr, N1, N1);

    // Attention
    attn_mma<<<dim3(N0 / 128, B * NH), blk>>>(qh0, ql0, kh0, kl0, vh0, vl0, o0, N0);
    attn_mma<<<dim3(N1 / 128, B * NH), blk>>>(qh1, ql1, kh1, kl1, vh1, vl1, o1, N1);

    // Output projection: o0 @ Wo[0:384,:] + bo; rows n<1024 += o1 @ Wo[768:1152,:]
    mma_gemm<<<dim3(6, 128), blk, GS>>>(o0, HD, Wo, 768, 0, bo,
                                        out, nullptr, nullptr, 768, 0, nullptr, N0, N0);
    mma_gemm<<<dim3(6, 64), blk, GS>>>(o1, HD, Wo + 768 * 768, 768, 0, nullptr,
                                       out, nullptr, nullptr, 768, 3, nullptr, N1, N0);

    mask_kernel<<<16, 256>>>(out + OUT_ELEMS);
}

// round 7
// speedup vs baseline: 4.0023x; 1.3178x over previous
#include <cuda_runtime.h>
#include <cuda_bf16.h>
#include <math.h>
#include <stdint.h>

#define B        8
#define N0       2048
#define N1       1024
#define HD       384
#define NH       6
#define M0       (B * N0)
#define M1       (B * N1)
#define OUT_ELEMS ((size_t)B * N0 * 768)

// Scratch: q/k/v stored pre-split (hi/lo bf16); o fp32.
__device__ __align__(128) __nv_bfloat16 g_qh0[M0 * HD];
__device__ __align__(128) __nv_bfloat16 g_ql0[M0 * HD];
__device__ __align__(128) __nv_bfloat16 g_kh0[M0 * HD];
__device__ __align__(128) __nv_bfloat16 g_kl0[M0 * HD];
__device__ __align__(128) __nv_bfloat16 g_vh0[M0 * HD];
__device__ __align__(128) __nv_bfloat16 g_vl0[M0 * HD];
__device__ __align__(128) __nv_bfloat16 g_qh1[M1 * HD];
__device__ __align__(128) __nv_bfloat16 g_ql1[M1 * HD];
__device__ __align__(128) __nv_bfloat16 g_kh1[M1 * HD];
__device__ __align__(128) __nv_bfloat16 g_kl1[M1 * HD];
__device__ __align__(128) __nv_bfloat16 g_vh1[M1 * HD];
__device__ __align__(128) __nv_bfloat16 g_vl1[M1 * HD];
__device__ __align__(128) float g_o0[M0 * HD];
__device__ __align__(128) float g_o1[M1 * HD];

__device__ __forceinline__ uint32_t sm_u32(const void* p) {
    return (uint32_t)__cvta_generic_to_shared(p);
}
__device__ __forceinline__ void ldsm4(uint32_t r[4], uint32_t a) {
    asm volatile("ldmatrix.sync.aligned.m8n8.x4.shared.b16 {%0,%1,%2,%3}, [%4];"
        : "=r"(r[0]), "=r"(r[1]), "=r"(r[2]), "=r"(r[3]) : "r"(a));
}
__device__ __forceinline__ void ldsm4t(uint32_t r[4], uint32_t a) {
    asm volatile("ldmatrix.sync.aligned.m8n8.x4.trans.shared.b16 {%0,%1,%2,%3}, [%4];"
        : "=r"(r[0]), "=r"(r[1]), "=r"(r[2]), "=r"(r[3]) : "r"(a));
}
__device__ __forceinline__ void mma16816(float d[4], const uint32_t a[4],
                                          uint32_t b0, uint32_t b1) {
    asm volatile(
        "mma.sync.aligned.m16n8k16.row.col.f32.bf16.bf16.f32 "
        "{%0,%1,%2,%3}, {%4,%5,%6,%7}, {%8,%9}, {%0,%1,%2,%3};"
        : "+f"(d[0]), "+f"(d[1]), "+f"(d[2]), "+f"(d[3])
        : "r"(a[0]), "r"(a[1]), "r"(a[2]), "r"(a[3]), "r"(b0), "r"(b1));
}
__device__ __forceinline__ uint32_t bpack(float lo, float hi) {
    __nv_bfloat162 t = __floats2bfloat162_rn(lo, hi);
    return *reinterpret_cast<uint32_t*>(&t);
}
__device__ __forceinline__ void fsplit(float x, float& h, float& l) {
    __nv_bfloat16 b = __float2bfloat16(x);
    h = __bfloat162float(b);
    l = x - h;
}

// ---------------------------------------------------------------------------
// Shared GEMM-core pieces (CTA 128x128, 8 warps 2x4 of 64x32, k-stage 32,
// double-buffered smem, bf16 hi/lo split -> 3 MMAs per k16 step).
// ---------------------------------------------------------------------------
#define GAS 40
#define GBS 136
#define GEMM_SMEM ((2 * 128 * GAS * 2 + 2 * 32 * GBS * 2) * 2)

__device__ __forceinline__ void stage_tile(
    const float ar[16], const float br[16],
    __nv_bfloat16* pah, __nv_bfloat16* pal,
    __nv_bfloat16* pbh, __nv_bfloat16* pbl)
{
    uint32_t hh[8], ll[8];
#pragma unroll
    for (int i = 0; i < 8; i++) {
        float h0, l0, h1, l1;
        fsplit(ar[2 * i], h0, l0);
        fsplit(ar[2 * i + 1], h1, l1);
        hh[i] = bpack(h0, h1);
        ll[i] = bpack(l0, l1);
    }
    ((uint4*)pah)[0] = make_uint4(hh[0], hh[1], hh[2], hh[3]);
    ((uint4*)pah)[1] = make_uint4(hh[4], hh[5], hh[6], hh[7]);
    ((uint4*)pal)[0] = make_uint4(ll[0], ll[1], ll[2], ll[3]);
    ((uint4*)pal)[1] = make_uint4(ll[4], ll[5], ll[6], ll[7]);
#pragma unroll
    for (int i = 0; i < 8; i++) {
        float h0, l0, h1, l1;
        fsplit(br[2 * i], h0, l0);
        fsplit(br[2 * i + 1], h1, l1);
        hh[i] = bpack(h0, h1);
        ll[i] = bpack(l0, l1);
    }
    ((uint4*)pbh)[0] = make_uint4(hh[0], hh[1], hh[2], hh[3]);
    ((uint4*)pbh)[1] = make_uint4(hh[4], hh[5], hh[6], hh[7]);
    ((uint4*)pbl)[0] = make_uint4(ll[0], ll[1], ll[2], ll[3]);
    ((uint4*)pbl)[1] = make_uint4(ll[4], ll[5], ll[6], ll[7]);
}

__device__ __forceinline__ void mma_ktile(
    uint32_t aBH, uint32_t aBL, uint32_t bBH, uint32_t bBL,
    int mrow, int ncol, int lane, float acc[4][4][4])
{
#pragma unroll
    for (int kk = 0; kk < 32; kk += 16) {
        uint32_t ah[4][4], al[4][4];
#pragma unroll
        for (int im = 0; im < 4; im++) {
            uint32_t ad = (uint32_t)((mrow + im * 16 + (lane & 15)) * GAS +
                                     kk + ((lane >> 4) << 3)) * 2;
            ldsm4(ah[im], aBH + ad);
            ldsm4(al[im], aBL + ad);
        }
#pragma unroll
        for (int nf = 0; nf < 2; nf++) {
            uint32_t bd = (uint32_t)((kk + (lane & 15)) * GBS + ncol +
                                     nf * 16 + ((lane >> 4) << 3)) * 2;
            uint32_t bh4[4], bl4[4];
            ldsm4t(bh4, bBH + bd);
            ldsm4t(bl4, bBL + bd);
#pragma unroll
            for (int im = 0; im < 4; im++) {
#pragma unroll
                for (int j = 0; j < 2; j++) {
                    float* d = acc[im][nf * 2 + j];
                    mma16816(d, ah[im], bh4[2 * j], bh4[2 * j + 1]);
                    mma16816(d, ah[im], bl4[2 * j], bl4[2 * j + 1]);
                    mma16816(d, al[im], bh4[2 * j], bh4[2 * j + 1]);
                }
            }
        }
    }
}

// ---------------------------------------------------------------------------
// Fused Q/K/V projection (one level). grid = (9, M/128):
//   sel = bx/3 picks {q,k,v}; n0 = (bx%3)*128 within the 384-wide output.
// ---------------------------------------------------------------------------
__global__ __launch_bounds__(256, 2) void qkv_gemm(
    const float* __restrict__ A, int K,
    const float* __restrict__ Wq, const float* __restrict__ Wk,
    const float* __restrict__ Wv, int wOff,
    const float* __restrict__ bq, const float* __restrict__ bk,
    const float* __restrict__ bv,
    __nv_bfloat16* __restrict__ qh, __nv_bfloat16* __restrict__ ql,
    __nv_bfloat16* __restrict__ kh, __nv_bfloat16* __restrict__ kl,
    __nv_bfloat16* __restrict__ vh, __nv_bfloat16* __restrict__ vl,
    const float* __restrict__ mask, int nseq)
{
    extern __shared__ __nv_bfloat16 ds[];
    __nv_bfloat16* Ah = ds;
    __nv_bfloat16* Al = Ah + 2 * 128 * GAS;
    __nv_bfloat16* Bh = Al + 2 * 128 * GAS;
    __nv_bfloat16* Bl = Bh + 2 * 32 * GBS;

    const int tid = threadIdx.x, lane = tid & 31, warp = tid >> 5;
    const int sel = blockIdx.x / 3;
    const int n0 = (blockIdx.x % 3) * 128;
    const int m0 = blockIdx.y * 128;
    const int mrow = (warp >> 2) * 64, ncol = (warp & 3) * 32;

    const float* W = (sel == 0) ? Wq : ((sel == 1) ? Wk : Wv);
    const float* bias = (sel == 0) ? bq : ((sel == 1) ? bk : bv);
    __nv_bfloat16* Ch = (sel == 0) ? qh : ((sel == 1) ? kh : vh);
    __nv_bfloat16* Cl = (sel == 0) ? ql : ((sel == 1) ? kl : vl);

    const float* Ag = A + (size_t)(m0 + (tid >> 1)) * K + ((tid & 1) << 4);
    const float* Wg = W + (size_t)(tid >> 3) * 768 + wOff + n0 + ((tid & 7) << 4);
    const int aoff = (tid >> 1) * GAS + ((tid & 1) << 4);
    const int boff = (tid >> 3) * GBS + ((tid & 7) << 4);

    float acc[4][4][4];
#pragma unroll
    for (int i = 0; i < 4; i++)
#pragma unroll
        for (int j = 0; j < 4; j++)
#pragma unroll
            for (int k = 0; k < 4; k++) acc[i][j][k] = 0.f;

    float ar[16], br[16];
#pragma unroll
    for (int i = 0; i < 4; i++) {
        *(float4*)&ar[i * 4] = *(const float4*)(Ag + i * 4);
        *(float4*)&br[i * 4] = *(const float4*)(Wg + i * 4);
    }
    stage_tile(ar, br, Ah + aoff, Al + aoff, Bh + boff, Bl + boff);
    __syncthreads();

    int buf = 0;
    for (int k0 = 0; k0 < K; k0 += 32) {
        const bool pf = (k0 + 32) < K;
        if (pf) {
#pragma unroll
            for (int i = 0; i < 4; i++) {
                *(float4*)&ar[i * 4] = *(const float4*)(Ag + (k0 + 32) + i * 4);
                *(float4*)&br[i * 4] =
                    *(const float4*)(Wg + (size_t)(k0 + 32) * 768 + i * 4);
            }
        }
        mma_ktile(sm_u32(Ah + buf * 128 * GAS), sm_u32(Al + buf * 128 * GAS),
                  sm_u32(Bh + buf * 32 * GBS), sm_u32(Bl + buf * 32 * GBS),
                  mrow, ncol, lane, acc);
        if (pf) {
            int nb = buf ^ 1;
            stage_tile(ar, br, Ah + nb * 128 * GAS + aoff, Al + nb * 128 * GAS + aoff,
                       Bh + nb * 32 * GBS + boff, Bl + nb * 32 * GBS + boff);
        }
        __syncthreads();
        buf ^= 1;
    }

#pragma unroll
    for (int im = 0; im < 4; im++) {
        int r0g = m0 + mrow + im * 16 + (lane >> 2);
#pragma unroll
        for (int f = 0; f < 4; f++) {
            int gcol = n0 + ncol + f * 8 + ((lane & 3) << 1);
            float* d = acc[im][f];
#pragma unroll
            for (int hf = 0; hf < 2; hf++) {
                int rr = r0g + hf * 8;
                float x0 = d[hf * 2] + bias[gcol];
                float x1 = d[hf * 2 + 1] + bias[gcol + 1];
                if (sel == 0) {
                    const float* mk = mask + (rr / nseq) * 64;
                    x0 = x0 * 0.125f + mk[gcol & 63];
                    x1 = x1 * 0.125f + mk[(gcol + 1) & 63];
                }
                size_t o = (size_t)rr * HD + gcol;
                __nv_bfloat16 b0 = __float2bfloat16(x0);
                Ch[o] = b0;
                Cl[o] = __float2bfloat16(x0 - __bfloat162float(b0));
                __nv_bfloat16 b1 = __float2bfloat16(x1);
                Ch[o + 1] = b1;
                Cl[o + 1] = __float2bfloat16(x1 - __bfloat162float(b1));
            }
        }
    }
}

// ---------------------------------------------------------------------------
// Fused output projection. grid = (6, 128). Rows n<1024 consume K=768
// (o0 @ Wo[0:384] then o1 @ Wo[768:1152]); rows n>=1024 only K=384 from o0.
// ---------------------------------------------------------------------------
__global__ __launch_bounds__(256, 2) void out_gemm(
    const float* __restrict__ o0, const float* __restrict__ o1,
    const float* __restrict__ Wo, const float* __restrict__ bo,
    float* __restrict__ out)
{
    extern __shared__ __nv_bfloat16 ds[];
    __nv_bfloat16* Ah = ds;
    __nv_bfloat16* Al = Ah + 2 * 128 * GAS;
    __nv_bfloat16* Bh = Al + 2 * 128 * GAS;
    __nv_bfloat16* Bl = Bh + 2 * 32 * GBS;

    const int tid = threadIdx.x, lane = tid & 31, warp = tid >> 5;
    const int n0 = blockIdx.x * 128;
    const int m0 = blockIdx.y * 128;
    const int mrow = (warp >> 2) * 64, ncol = (warp & 3) * 32;

    const bool lower = (m0 & 2047) < 1024;
    const int nkt = lower ? 24 : 12;
    const int o1r0 = (m0 >> 11) * 1024 + (m0 & 2047);

    const int aoff = (tid >> 1) * GAS + ((tid & 1) << 4);
    const int boff = (tid >> 3) * GBS + ((tid & 7) << 4);

    float acc[4][4][4];
#pragma unroll
    for (int i = 0; i < 4; i++)
#pragma unroll
        for (int j = 0; j < 4; j++)
#pragma unroll
            for (int k = 0; k < 4; k++) acc[i][j][k] = 0.f;

    auto loadTile = [&](int t, float ar[16], float br[16]) {
        const float* As;
        int kcol, wrow;
        if (t < 12) {
            As = o0 + (size_t)(m0 + (tid >> 1)) * HD;
            kcol = t * 32;
            wrow = t * 32;
        } else {
            As = o1 + (size_t)(o1r0 + (tid >> 1)) * HD;
            kcol = (t - 12) * 32;
            wrow = 768 + (t - 12) * 32;   // FIX: o1 block lives at Wo rows 768:1152
        }
        const float* ap = As + kcol + ((tid & 1) << 4);
        const float* wp = Wo + (size_t)(wrow + (tid >> 3)) * 768 + n0 + ((tid & 7) << 4);
#pragma unroll
        for (int i = 0; i < 4; i++) {
            *(float4*)&ar[i * 4] = *(const float4*)(ap + i * 4);
            *(float4*)&br[i * 4] = *(const float4*)(wp + i * 4);
        }
    };

    float ar[16], br[16];
    loadTile(0, ar, br);
    stage_tile(ar, br, Ah + aoff, Al + aoff, Bh + boff, Bl + boff);
    __syncthreads();

    int buf = 0;
    for (int t = 0; t < nkt; t++) {
        const bool pf = (t + 1) < nkt;
        if (pf) loadTile(t + 1, ar, br);
        mma_ktile(sm_u32(Ah + buf * 128 * GAS), sm_u32(Al + buf * 128 * GAS),
                  sm_u32(Bh + buf * 32 * GBS), sm_u32(Bl + buf * 32 * GBS),
                  mrow, ncol, lane, acc);
        if (pf) {
            int nb = buf ^ 1;
            stage_tile(ar, br, Ah + nb * 128 * GAS + aoff, Al + nb * 128 * GAS + aoff,
                       Bh + nb * 32 * GBS + boff, Bl + nb * 32 * GBS + boff);
        }
        __syncthreads();
        buf ^= 1;
    }

#pragma unroll
    for (int im = 0; im < 4; im++) {
        int r0g = m0 + mrow + im * 16 + (lane >> 2);
#pragma unroll
        for (int f = 0; f < 4; f++) {
            int gcol = n0 + ncol + f * 8 + ((lane & 3) << 1);
            float* d = acc[im][f];
#pragma unroll
            for (int hf = 0; hf < 2; hf++) {
                int rr = r0g + hf * 8;
                out[(size_t)rr * 768 + gcol]     = d[hf * 2] + bo[gcol];
                out[(size_t)rr * 768 + gcol + 1] = d[hf * 2 + 1] + bo[gcol + 1];
            }
        }
    }
}

// ---------------------------------------------------------------------------
// Tensor-core flash attention (unchanged).
// ---------------------------------------------------------------------------
#define AS 72

__global__ __launch_bounds__(256) void attn_mma(
    const __nv_bfloat16* __restrict__ qh, const __nv_bfloat16* __restrict__ ql,
    const __nv_bfloat16* __restrict__ kh, const __nv_bfloat16* __restrict__ kl,
    const __nv_bfloat16* __restrict__ vh, const __nv_bfloat16* __restrict__ vl,
    float* __restrict__ om, int Nq)
{
    __shared__ __align__(16) __nv_bfloat16 smem[4 * 64 * AS];
    __nv_bfloat16* sKh = smem;
    __nv_bfloat16* sKl = smem + 64 * AS;
    __nv_bfloat16* sVh = smem + 2 * 64 * AS;
    __nv_bfloat16* sVl = smem + 3 * 64 * AS;

    const int tid = threadIdx.x, lane = tid & 31, warp = tid >> 5;
    const int b = blockIdx.y / NH, h = blockIdx.y % NH;
    const int q0 = blockIdx.x * 128;
    const size_t gb = (size_t)b * Nq * HD + (size_t)h * 64;
    const int mrow = warp * 16;

    {
        const __nv_bfloat16* Qh = qh + gb + (size_t)q0 * HD;
        const __nv_bfloat16* Ql = ql + gb + (size_t)q0 * HD;
#pragma unroll
        for (int it = 0; it < 4; it++) {
            int i = tid + it * 256;
            int r = i >> 3, u = (i & 7) * 8;
            *(uint4*)&smem[r * AS + u] = *(const uint4*)&Qh[(size_t)r * HD + u];
            *(uint4*)&smem[2 * 64 * AS + r * AS + u] =
                *(const uint4*)&Ql[(size_t)r * HD + u];
        }
    }
    __syncthreads();
    uint32_t qfh[4][4], qfl[4][4];
    {
        const uint32_t bh_ = sm_u32(smem);
        const uint32_t bl_ = sm_u32(smem + 2 * 64 * AS);
        int row = mrow + (lane & 15);
#pragma unroll
        for (int kk = 0; kk < 4; kk++) {
            uint32_t off = (uint32_t)(row * AS + kk * 16 + ((lane >> 4) << 3)) * 2;
            ldsm4(qfh[kk], bh_ + off);
            ldsm4(qfl[kk], bl_ + off);
        }
    }
    __syncthreads();

    float o[8][4];
#pragma unroll
    for (int f = 0; f < 8; f++)
#pragma unroll
        for (int k = 0; k < 4; k++) o[f][k] = 0.f;
    float mr0 = -1e30f, mr1 = -1e30f, lr0 = 0.f, lr1 = 0.f;

    const uint32_t kBH = sm_u32(sKh), kBL = sm_u32(sKl);
    const uint32_t vBH = sm_u32(sVh), vBL = sm_u32(sVl);

    for (int kv = 0; kv < Nq; kv += 64) {
        {
            const __nv_bfloat16* Kh = kh + gb + (size_t)kv * HD;
            const __nv_bfloat16* Kl = kl + gb + (size_t)kv * HD;
            const __nv_bfloat16* Vh = vh + gb + (size_t)kv * HD;
            const __nv_bfloat16* Vl = vl + gb + (size_t)kv * HD;
#pragma unroll
            for (int it = 0; it < 2; it++) {
                int i = tid + it * 256;
                int r = i >> 3, u = (i & 7) * 8;
                size_t go = (size_t)r * HD + u;
                int so = r * AS + u;
                *(uint4*)&sKh[so] = *(const uint4*)&Kh[go];
                *(uint4*)&sKl[so] = *(const uint4*)&Kl[go];
                *(uint4*)&sVh[so] = *(const uint4*)&Vh[go];
                *(uint4*)&sVl[so] = *(const uint4*)&Vl[go];
            }
        }
        __syncthreads();

        float s[8][4];
#pragma unroll
        for (int f = 0; f < 8; f++)
#pragma unroll
            for (int k = 0; k < 4; k++) s[f][k] = 0.f;
#pragma unroll
        for (int kk = 0; kk < 4; kk++) {
#pragma unroll
            for (int nf = 0; nf < 4; nf++) {
                uint32_t ad = (uint32_t)((nf * 16 + (lane & 15)) * AS + kk * 16 +
                                         ((lane >> 4) << 3)) * 2;
                uint32_t kb[4], kl4[4];
                ldsm4(kb, kBH + ad);
                ldsm4(kl4, kBL + ad);
                mma16816(s[nf * 2],     qfh[kk], kb[0],  kb[2]);
                mma16816(s[nf * 2],     qfh[kk], kl4[0], kl4[2]);
                mma16816(s[nf * 2],     qfl[kk], kb[0],  kb[2]);
                mma16816(s[nf * 2 + 1], qfh[kk], kb[1],  kb[3]);
                mma16816(s[nf * 2 + 1], qfh[kk], kl4[1], kl4[3]);
                mma16816(s[nf * 2 + 1], qfl[kk], kb[1],  kb[3]);
            }
        }

        float mx0 = -1e30f, mx1 = -1e30f;
#pragma unroll
        for (int f = 0; f < 8; f++) {
            mx0 = fmaxf(mx0, fmaxf(s[f][0], s[f][1]));
            mx1 = fmaxf(mx1, fmaxf(s[f][2], s[f][3]));
        }
        mx0 = fmaxf(mx0, __shfl_xor_sync(0xffffffffu, mx0, 1));
        mx0 = fmaxf(mx0, __shfl_xor_sync(0xffffffffu, mx0, 2));
        mx1 = fmaxf(mx1, __shfl_xor_sync(0xffffffffu, mx1, 1));
        mx1 = fmaxf(mx1, __shfl_xor_sync(0xffffffffu, mx1, 2));
        float mn0 = fmaxf(mr0, mx0), mn1 = fmaxf(mr1, mx1);
        float c0 = __expf(mr0 - mn0), c1 = __expf(mr1 - mn1);
        float rs0 = 0.f, rs1 = 0.f;
#pragma unroll
        for (int f = 0; f < 8; f++) {
            s[f][0] = __expf(s[f][0] - mn0);
            s[f][1] = __expf(s[f][1] - mn0);
            s[f][2] = __expf(s[f][2] - mn1);
            s[f][3] = __expf(s[f][3] - mn1);
            rs0 += s[f][0] + s[f][1];
            rs1 += s[f][2] + s[f][3];
        }
        rs0 += __shfl_xor_sync(0xffffffffu, rs0, 1);
        rs0 += __shfl_xor_sync(0xffffffffu, rs0, 2);
        rs1 += __shfl_xor_sync(0xffffffffu, rs1, 1);
        rs1 += __shfl_xor_sync(0xffffffffu, rs1, 2);
        lr0 = lr0 * c0 + rs0;
        lr1 = lr1 * c1 + rs1;
        mr0 = mn0;
        mr1 = mn1;
#pragma unroll
        for (int f = 0; f < 8; f++) {
            o[f][0] *= c0; o[f][1] *= c0; o[f][2] *= c1; o[f][3] *= c1;
        }

#pragma unroll
        for (int kk2 = 0; kk2 < 4; kk2++) {
            uint32_t pah[4], pal[4];
            {
                int f0 = kk2 * 2;
                float h0, l0, h1, l1;
                fsplit(s[f0][0], h0, l0);     fsplit(s[f0][1], h1, l1);
                pah[0] = bpack(h0, h1);       pal[0] = bpack(l0, l1);
                fsplit(s[f0][2], h0, l0);     fsplit(s[f0][3], h1, l1);
                pah[1] = bpack(h0, h1);       pal[1] = bpack(l0, l1);
                fsplit(s[f0 + 1][0], h0, l0); fsplit(s[f0 + 1][1], h1, l1);
                pah[2] = bpack(h0, h1);       pal[2] = bpack(l0, l1);
                fsplit(s[f0 + 1][2], h0, l0); fsplit(s[f0 + 1][3], h1, l1);
                pah[3] = bpack(h0, h1);       pal[3] = bpack(l0, l1);
            }
#pragma unroll
            for (int nf = 0; nf < 4; nf++) {
                uint32_t ad = (uint32_t)((kk2 * 16 + (lane & 15)) * AS + nf * 16 +
                                         ((lane >> 4) << 3)) * 2;
                uint32_t vb[4], vl4[4];
                ldsm4t(vb, vBH + ad);
                ldsm4t(vl4, vBL + ad);
                mma16816(o[nf * 2],     pah, vb[0],  vb[1]);
                mma16816(o[nf * 2],     pah, vl4[0], vl4[1]);
                mma16816(o[nf * 2],     pal, vb[0],  vb[1]);
                mma16816(o[nf * 2 + 1], pah, vb[2],  vb[3]);
                mma16816(o[nf * 2 + 1], pah, vl4[2], vl4[3]);
                mma16816(o[nf * 2 + 1], pal, vb[2],  vb[3]);
            }
        }
        __syncthreads();
    }

    float i0 = 1.f / lr0, i1 = 1.f / lr1;
    int rg = q0 + mrow + (lane >> 2);
#pragma unroll
    for (int f = 0; f < 8; f++) {
        int cc = f * 8 + ((lane & 3) << 1);
        *(float2*)&om[gb + (size_t)rg * HD + cc] =
            make_float2(o[f][0] * i0, o[f][1] * i0);
        *(float2*)&om[gb + (size_t)(rg + 8) * HD + cc] =
            make_float2(o[f][2] * i1, o[f][3] * i1);
    }
}

__global__ void mask_kernel(float* __restrict__ out)
{
    int i = blockIdx.x * blockDim.x + threadIdx.x;
    if (i < 2 * N0) {
        int lvl = i >> 11, n = i & (N0 - 1);
        out[i] = (lvl == 0 || n < N1) ? 1.f : 0.f;
    }
}

extern "C" void kernel_launch(void* const* d_in, const int* in_sizes, int n_in,
                              void* d_out, int out_size)
{
    (void)in_sizes; (void)n_in; (void)out_size;
    const float* inp0  = (const float*)d_in[0];
    const float* inp1  = (const float*)d_in[1];
    const float* amask = (const float*)d_in[2];
    const float* Wq0 = (const float*)d_in[3];
    const float* bq0 = (const float*)d_in[4];
    const float* Wk0 = (const float*)d_in[5];
    const float* bk0 = (const float*)d_in[6];
    const float* Wv0 = (const float*)d_in[7];
    const float* bv0 = (const float*)d_in[8];
    const float* Wq1 = (const float*)d_in[9];
    const float* bq1 = (const float*)d_in[10];
    const float* Wk1 = (const float*)d_in[11];
    const float* bk1 = (const float*)d_in[12];
    const float* Wv1 = (const float*)d_in[13];
    const float* bv1 = (const float*)d_in[14];
    const float* Wo  = (const float*)d_in[15];
    const float* bo  = (const float*)d_in[16];
    float* out = (float*)d_out;

    __nv_bfloat16 *qh0, *ql0, *kh0, *kl0, *vh0, *vl0;
    __nv_bfloat16 *qh1, *ql1, *kh1, *kl1, *vh1, *vl1;
    float *o0, *o1;
    cudaGetSymbolAddress((void**)&qh0, g_qh0);
    cudaGetSymbolAddress((void**)&ql0, g_ql0);
    cudaGetSymbolAddress((void**)&kh0, g_kh0);
    cudaGetSymbolAddress((void**)&kl0, g_kl0);
    cudaGetSymbolAddress((void**)&vh0, g_vh0);
    cudaGetSymbolAddress((void**)&vl0, g_vl0);
    cudaGetSymbolAddress((void**)&qh1, g_qh1);
    cudaGetSymbolAddress((void**)&ql1, g_ql1);
    cudaGetSymbolAddress((void**)&kh1, g_kh1);
    cudaGetSymbolAddress((void**)&kl1, g_kl1);
    cudaGetSymbolAddress((void**)&vh1, g_vh1);
    cudaGetSymbolAddress((void**)&vl1, g_vl1);
    cudaGetSymbolAddress((void**)&o0, g_o0);
    cudaGetSymbolAddress((void**)&o1, g_o1);

    cudaFuncSetAttribute(qkv_gemm, cudaFuncAttributeMaxDynamicSharedMemorySize,
                         GEMM_SMEM);
    cudaFuncSetAttribute(out_gemm, cudaFuncAttributeMaxDynamicSharedMemorySize,
                         GEMM_SMEM);
    dim3 blk(256);
    const int GS = GEMM_SMEM;

    // Fused Q/K/V projections per level
    qkv_gemm<<<dim3(9, 128), blk, GS>>>(inp0, 768, Wq0, Wk0, Wv0, 0,
                                        bq0, bk0, bv0,
                                        qh0, ql0, kh0, kl0, vh0, vl0,
                                        amask, N0);
    qkv_gemm<<<dim3(9, 64), blk, GS>>>(inp1, 1536, Wq1, Wk1, Wv1, 384,
                                       bq1 + 384, bk1 + 384, bv1 + 384,
                                       qh1, ql1, kh1, kl1, vh1, vl1,
                                       amask, N1);

    // Attention
    attn_mma<<<dim3(N0 / 128, B * NH), blk>>>(qh0, ql0, kh0, kl0, vh0, vl0, o0, N0);
    attn_mma<<<dim3(N1 / 128, B * NH), blk>>>(qh1, ql1, kh1, kl1, vh1, vl1, o1, N1);

    // Fused output projection (both levels, one kernel)
    out_gemm<<<dim3(6, 128), blk, GS>>>(o0, o1, Wo, bo, out);

    mask_kernel<<<16, 256>>>(out + OUT_ELEMS);
}

// round 8
// speedup vs baseline: 5.2164x; 1.3034x over previous
#include <cuda_runtime.h>
#include <cuda_bf16.h>
#include <stdint.h>

typedef __nv_bfloat16 bf;

#define B 8
#define N0 2048
#define N1 1024
#define HD 384
#define NH 6
#define M0 (B*N0)
#define M1 (B*N1)
#define OUT_ELEMS ((size_t)B*N0*768)

// ---- device-global scratch (allocation-free contract) ----
__device__ __align__(128) bf g_ih0[M0*768],  g_il0[M0*768];
__device__ __align__(128) bf g_ih1[M1*1536], g_il1[M1*1536];
__device__ __align__(128) bf g_wh0[3][768*768],  g_wl0[3][768*768];
__device__ __align__(128) bf g_wh1[3][1536*768], g_wl1[3][1536*768];
__device__ __align__(128) bf g_woh[1536*768], g_wol[1536*768];
__device__ __align__(128) bf g_qh0[M0*HD], g_ql0[M0*HD], g_kh0[M0*HD],
                             g_kl0[M0*HD], g_vh0[M0*HD], g_vl0[M0*HD];
__device__ __align__(128) bf g_qh1[M1*HD], g_ql1[M1*HD], g_kh1[M1*HD],
                             g_kl1[M1*HD], g_vh1[M1*HD], g_vl1[M1*HD];
__device__ __align__(128) bf g_oh0[M0*HD], g_ol0[M0*HD], g_oh1[M1*HD], g_ol1[M1*HD];

// ---- helpers ----
__device__ __forceinline__ uint32_t sm_u32(const void* p) {
    return (uint32_t)__cvta_generic_to_shared(p);
}
__device__ __forceinline__ void ldsm4(uint32_t r[4], uint32_t a) {
    asm volatile("ldmatrix.sync.aligned.m8n8.x4.shared.b16 {%0,%1,%2,%3}, [%4];"
        : "=r"(r[0]), "=r"(r[1]), "=r"(r[2]), "=r"(r[3]) : "r"(a));
}
__device__ __forceinline__ void ldsm4t(uint32_t r[4], uint32_t a) {
    asm volatile("ldmatrix.sync.aligned.m8n8.x4.trans.shared.b16 {%0,%1,%2,%3}, [%4];"
        : "=r"(r[0]), "=r"(r[1]), "=r"(r[2]), "=r"(r[3]) : "r"(a));
}
__device__ __forceinline__ void mma16816(float d[4], const uint32_t a[4],
                                          uint32_t b0, uint32_t b1) {
    asm volatile(
        "mma.sync.aligned.m16n8k16.row.col.f32.bf16.bf16.f32 "
        "{%0,%1,%2,%3}, {%4,%5,%6,%7}, {%8,%9}, {%0,%1,%2,%3};"
        : "+f"(d[0]), "+f"(d[1]), "+f"(d[2]), "+f"(d[3])
        : "r"(a[0]), "r"(a[1]), "r"(a[2]), "r"(a[3]), "r"(b0), "r"(b1));
}
__device__ __forceinline__ uint32_t bpack(float lo, float hi) {
    __nv_bfloat162 t = __floats2bfloat162_rn(lo, hi);
    return *reinterpret_cast<uint32_t*>(&t);
}
__device__ __forceinline__ void fsplit(float x, float& h, float& l) {
    bf b = __float2bfloat16(x);
    h = __bfloat162float(b);
    l = x - h;
}
__device__ __forceinline__ void cpa16(uint32_t d, const void* s) {
    asm volatile("cp.async.cg.shared.global [%0], [%1], 16;" :: "r"(d), "l"(s));
}
__device__ __forceinline__ void cp_commit() { asm volatile("cp.async.commit_group;"); }
__device__ __forceinline__ void cp_wait0()  { asm volatile("cp.async.wait_group 0;"); }

// ---- fp32 -> (hi, lo) bf16 split kernels ----
struct SJob  { const float* s; bf* h; bf* l; };
struct SJobs { SJob j[4]; };
__global__ void splitk(SJobs js, int n)
{
    SJob J = js.j[blockIdx.z];
    for (int i = (blockIdx.x * 256 + threadIdx.x) * 4; i < n; i += gridDim.x * 256 * 4) {
        float4 v = *(const float4*)(J.s + i);
        float h0,l0,h1,l1,h2,l2,h3,l3;
        fsplit(v.x,h0,l0); fsplit(v.y,h1,l1); fsplit(v.z,h2,l2); fsplit(v.w,h3,l3);
        *(uint2*)(J.h + i) = make_uint2(bpack(h0,h1), bpack(h2,h3));
        *(uint2*)(J.l + i) = make_uint2(bpack(l0,l1), bpack(l2,l3));
    }
}

// ---- GEMM core: CTA 128x128, 8 warps (2x4 of 64x32), k-stage 32,
//      cp.async double-buffered, bf16 hi/lo split -> 3 MMAs per k16 ----
#define GAS 40
#define GBS 136
#define GEMM_SMEM ((2*128*GAS + 2*32*GBS) * 2 * 2)

__device__ __forceinline__ void mma_ktile(
    uint32_t aBH, uint32_t aBL, uint32_t bBH, uint32_t bBL,
    int mrow, int ncol, int lane, float acc[4][4][4])
{
#pragma unroll
    for (int kk = 0; kk < 32; kk += 16) {
        uint32_t ah[4][4], al[4][4];
#pragma unroll
        for (int im = 0; im < 4; im++) {
            uint32_t ad = (uint32_t)((mrow + im*16 + (lane & 15)) * GAS +
                                     kk + ((lane >> 4) << 3)) * 2;
            ldsm4(ah[im], aBH + ad);
            ldsm4(al[im], aBL + ad);
        }
#pragma unroll
        for (int nf = 0; nf < 2; nf++) {
            uint32_t bd = (uint32_t)((kk + (lane & 15)) * GBS + ncol +
                                     nf*16 + ((lane >> 4) << 3)) * 2;
            uint32_t bh4[4], bl4[4];
            ldsm4t(bh4, bBH + bd);
            ldsm4t(bl4, bBL + bd);
#pragma unroll
            for (int im = 0; im < 4; im++) {
#pragma unroll
                for (int j = 0; j < 2; j++) {
                    float* d = acc[im][nf*2 + j];
                    mma16816(d, ah[im], bh4[2*j], bh4[2*j+1]);
                    mma16816(d, ah[im], bl4[2*j], bl4[2*j+1]);
                    mma16816(d, al[im], bh4[2*j], bh4[2*j+1]);
                }
            }
        }
    }
}

// issue one 128x32 A-tile + 32x128 B-tile via cp.async (pointers pre-offset)
__device__ __forceinline__ void gemm_cpa(
    const bf* aH, const bf* aL, int lda,
    const bf* wH, const bf* wL, int ldw,
    int tid, uint32_t dAh, uint32_t dAl, uint32_t dBh, uint32_t dBl)
{
    const int arow = tid >> 1, ak = (tid & 1) << 4;
    const size_t ao = (size_t)arow * lda + ak;
    const uint32_t ad = (uint32_t)(arow * GAS + ak) * 2;
    cpa16(dAh + ad, aH + ao);  cpa16(dAh + ad + 16, aH + ao + 8);
    cpa16(dAl + ad, aL + ao);  cpa16(dAl + ad + 16, aL + ao + 8);
    const int brow = tid >> 3, bc = (tid & 7) << 4;
    const size_t bo = (size_t)brow * ldw + bc;
    const uint32_t bd = (uint32_t)(brow * GBS + bc) * 2;
    cpa16(dBh + bd, wH + bo);  cpa16(dBh + bd + 16, wH + bo + 8);
    cpa16(dBl + bd, wL + bo);  cpa16(dBl + bd + 16, wL + bo + 8);
}

// ---- fused Q/K/V projection (one level): grid (9, M/128) ----
__global__ __launch_bounds__(256, 2) void qkv_gemm(
    const bf* __restrict__ Ah, const bf* __restrict__ Al, int K,
    const bf* __restrict__ W0h, const bf* __restrict__ W0l, int wOff,
    const float* __restrict__ bq, const float* __restrict__ bk,
    const float* __restrict__ bv,
    bf* qh, bf* ql, bf* kh, bf* kl, bf* vh, bf* vl,
    const float* __restrict__ mask, int nseq)
{
    extern __shared__ bf ds[];
    bf* Ahs = ds;
    bf* Als = Ahs + 2*128*GAS;
    bf* Bhs = Als + 2*128*GAS;
    bf* Bls = Bhs + 2*32*GBS;

    const int tid = threadIdx.x, lane = tid & 31, warp = tid >> 5;
    const int sel = blockIdx.x / 3, n0 = (blockIdx.x % 3) * 128;
    const int m0 = blockIdx.y * 128;
    const int mrow = (warp >> 2) * 64, ncol = (warp & 3) * 32;

    const bf* Wh = W0h + (size_t)sel * K * 768 + wOff + n0;
    const bf* Wl = W0l + (size_t)sel * K * 768 + wOff + n0;
    const float* bias = (sel == 0) ? bq : ((sel == 1) ? bk : bv);
    bf* Ch = (sel == 0) ? qh : ((sel == 1) ? kh : vh);
    bf* Cl = (sel == 0) ? ql : ((sel == 1) ? kl : vl);
    const bf* aH = Ah + (size_t)m0 * K;
    const bf* aL = Al + (size_t)m0 * K;

    float acc[4][4][4];
#pragma unroll
    for (int i = 0; i < 4; i++)
#pragma unroll
        for (int j = 0; j < 4; j++)
#pragma unroll
            for (int k = 0; k < 4; k++) acc[i][j][k] = 0.f;

    gemm_cpa(aH, aL, K, Wh, Wl, 768, tid,
             sm_u32(Ahs), sm_u32(Als), sm_u32(Bhs), sm_u32(Bls));
    cp_commit();

    int buf = 0;
    for (int k0 = 0; k0 < K; k0 += 32) {
        cp_wait0();
        __syncthreads();
        if (k0 + 32 < K) {
            int nb = buf ^ 1;
            gemm_cpa(aH + k0 + 32, aL + k0 + 32, K,
                     Wh + (size_t)(k0 + 32) * 768, Wl + (size_t)(k0 + 32) * 768, 768, tid,
                     sm_u32(Ahs + nb*128*GAS), sm_u32(Als + nb*128*GAS),
                     sm_u32(Bhs + nb*32*GBS),  sm_u32(Bls + nb*32*GBS));
            cp_commit();
        }
        mma_ktile(sm_u32(Ahs + buf*128*GAS), sm_u32(Als + buf*128*GAS),
                  sm_u32(Bhs + buf*32*GBS),  sm_u32(Bls + buf*32*GBS),
                  mrow, ncol, lane, acc);
        buf ^= 1;
    }

#pragma unroll
    for (int im = 0; im < 4; im++) {
        int r0g = m0 + mrow + im*16 + (lane >> 2);
#pragma unroll
        for (int f = 0; f < 4; f++) {
            int gcol = n0 + ncol + f*8 + ((lane & 3) << 1);
            float* d = acc[im][f];
#pragma unroll
            for (int hf = 0; hf < 2; hf++) {
                int rr = r0g + hf*8;
                float x0 = d[hf*2]     + bias[gcol];
                float x1 = d[hf*2 + 1] + bias[gcol + 1];
                if (sel == 0) {
                    const float* mk = mask + (rr / nseq) * 64;
                    x0 = x0 * 0.125f + mk[gcol & 63];
                    x1 = x1 * 0.125f + mk[(gcol + 1) & 63];
                }
                size_t o = (size_t)rr * HD + gcol;
                float h0,l0,h1,l1;
                fsplit(x0,h0,l0); fsplit(x1,h1,l1);
                *(uint32_t*)(Ch + o) = bpack(h0,h1);
                *(uint32_t*)(Cl + o) = bpack(l0,l1);
            }
        }
    }
}

// ---- fused output projection: grid (6, 128) ----
__global__ __launch_bounds__(256, 2) void out_gemm(
    const bf* __restrict__ o0h, const bf* __restrict__ o0l,
    const bf* __restrict__ o1h, const bf* __restrict__ o1l,
    const bf* __restrict__ Wh, const bf* __restrict__ Wl,
    const float* __restrict__ bo, float* __restrict__ out)
{
    extern __shared__ bf ds[];
    bf* Ahs = ds;
    bf* Als = Ahs + 2*128*GAS;
    bf* Bhs = Als + 2*128*GAS;
    bf* Bls = Bhs + 2*32*GBS;

    const int tid = threadIdx.x, lane = tid & 31, warp = tid >> 5;
    const int n0 = blockIdx.x * 128, m0 = blockIdx.y * 128;
    const int mrow = (warp >> 2) * 64, ncol = (warp & 3) * 32;

    const bool lower = (m0 & 2047) < 1024;
    const int nkt = lower ? 24 : 12;
    const int o1r0 = (m0 >> 11) * 1024 + (m0 & 2047);

    float acc[4][4][4];
#pragma unroll
    for (int i = 0; i < 4; i++)
#pragma unroll
        for (int j = 0; j < 4; j++)
#pragma unroll
            for (int k = 0; k < 4; k++) acc[i][j][k] = 0.f;

    auto issue = [&](int t, int nb) {
        const bf *aH, *aL; int kc, wr;
        if (t < 12) { aH = o0h + (size_t)m0*HD;   aL = o0l + (size_t)m0*HD;
                      kc = t*32;        wr = t*32; }
        else        { aH = o1h + (size_t)o1r0*HD; aL = o1l + (size_t)o1r0*HD;
                      kc = (t-12)*32;   wr = 768 + (t-12)*32; }
        gemm_cpa(aH + kc, aL + kc, HD,
                 Wh + (size_t)wr*768 + n0, Wl + (size_t)wr*768 + n0, 768, tid,
                 sm_u32(Ahs + nb*128*GAS), sm_u32(Als + nb*128*GAS),
                 sm_u32(Bhs + nb*32*GBS),  sm_u32(Bls + nb*32*GBS));
        cp_commit();
    };

    issue(0, 0);
    int buf = 0;
    for (int t = 0; t < nkt; t++) {
        cp_wait0();
        __syncthreads();
        if (t + 1 < nkt) issue(t + 1, buf ^ 1);
        mma_ktile(sm_u32(Ahs + buf*128*GAS), sm_u32(Als + buf*128*GAS),
                  sm_u32(Bhs + buf*32*GBS),  sm_u32(Bls + buf*32*GBS),
                  mrow, ncol, lane, acc);
        buf ^= 1;
    }

#pragma unroll
    for (int im = 0; im < 4; im++) {
        int r0g = m0 + mrow + im*16 + (lane >> 2);
#pragma unroll
        for (int f = 0; f < 4; f++) {
            int gcol = n0 + ncol + f*8 + ((lane & 3) << 1);
            float* d = acc[im][f];
#pragma unroll
            for (int hf = 0; hf < 2; hf++) {
                int rr = r0g + hf*8;
                out[(size_t)rr*768 + gcol]     = d[hf*2]     + bo[gcol];
                out[(size_t)rr*768 + gcol + 1] = d[hf*2 + 1] + bo[gcol + 1];
            }
        }
    }
}

// ---- flash attention: cp.async double-buffered KV, split bf16 output ----
#define AS 72
#define ABUF (4*64*AS)            // halves per KV buffer
#define ATTN_SMEM (2*ABUF*2)      // bytes

__global__ __launch_bounds__(256, 2) void attn_mma(
    const bf* __restrict__ qh, const bf* __restrict__ ql,
    const bf* __restrict__ kh, const bf* __restrict__ kl,
    const bf* __restrict__ vh, const bf* __restrict__ vl,
    bf* __restrict__ oh, bf* __restrict__ ol, int Nq)
{
    extern __shared__ bf smem[];

    const int tid = threadIdx.x, lane = tid & 31, warp = tid >> 5;
    const int b = blockIdx.y / NH, h = blockIdx.y % NH;
    const int q0 = blockIdx.x * 128;
    const size_t gb = (size_t)b * Nq * HD + (size_t)h * 64;
    const int mrow = warp * 16;

    // stage Q (hi at 0, lo at 2*64*AS), extract frags, release smem
    {
        const bf* Qh = qh + gb + (size_t)q0 * HD;
        const bf* Ql = ql + gb + (size_t)q0 * HD;
#pragma unroll
        for (int it = 0; it < 4; it++) {
            int i = tid + it * 256;
            int r = i >> 3, u = (i & 7) * 8;
            *(uint4*)&smem[r*AS + u]            = *(const uint4*)&Qh[(size_t)r*HD + u];
            *(uint4*)&smem[2*64*AS + r*AS + u]  = *(const uint4*)&Ql[(size_t)r*HD + u];
        }
    }
    __syncthreads();
    uint32_t qfh[4][4], qfl[4][4];
    {
        const uint32_t bh_ = sm_u32(smem);
        const uint32_t bl_ = sm_u32(smem + 2*64*AS);
        int row = mrow + (lane & 15);
#pragma unroll
        for (int kk = 0; kk < 4; kk++) {
            uint32_t off = (uint32_t)(row*AS + kk*16 + ((lane >> 4) << 3)) * 2;
            ldsm4(qfh[kk], bh_ + off);
            ldsm4(qfl[kk], bl_ + off);
        }
    }
    __syncthreads();

    auto kvload = [&](int kv, int nb) {
        const bf* Kh = kh + gb + (size_t)kv * HD;
        const bf* Kl = kl + gb + (size_t)kv * HD;
        const bf* Vh = vh + gb + (size_t)kv * HD;
        const bf* Vl = vl + gb + (size_t)kv * HD;
        uint32_t d = sm_u32(smem + nb * ABUF);
#pragma unroll
        for (int it = 0; it < 2; it++) {
            int i = tid + it * 256;
            int r = i >> 3, u = (i & 7) * 8;
            size_t go = (size_t)r * HD + u;
            uint32_t so = (uint32_t)(r*AS + u) * 2;
            cpa16(d + so,              Kh + go);
            cpa16(d + 64*AS*2 + so,    Kl + go);
            cpa16(d + 2*64*AS*2 + so,  Vh + go);
            cpa16(d + 3*64*AS*2 + so,  Vl + go);
        }
        cp_commit();
    };

    float o[8][4];
#pragma unroll
    for (int f = 0; f < 8; f++)
#pragma unroll
        for (int k = 0; k < 4; k++) o[f][k] = 0.f;
    float mr0 = -1e30f, mr1 = -1e30f, lr0 = 0.f, lr1 = 0.f;

    kvload(0, 0);
    int buf = 0;
    for (int kv = 0; kv < Nq; kv += 64) {
        cp_wait0();
        __syncthreads();
        if (kv + 64 < Nq) kvload(kv + 64, buf ^ 1);

        const uint32_t base = sm_u32(smem + buf * ABUF);
        const uint32_t kBH = base, kBL = base + 64*AS*2;
        const uint32_t vBH = base + 2*64*AS*2, vBL = base + 3*64*AS*2;

        float s[8][4];
#pragma unroll
        for (int f = 0; f < 8; f++)
#pragma unroll
            for (int k = 0; k < 4; k++) s[f][k] = 0.f;
#pragma unroll
        for (int kk = 0; kk < 4; kk++) {
#pragma unroll
            for (int nf = 0; nf < 4; nf++) {
                uint32_t ad = (uint32_t)((nf*16 + (lane & 15)) * AS + kk*16 +
                                         ((lane >> 4) << 3)) * 2;
                uint32_t kb[4], kl4[4];
                ldsm4(kb, kBH + ad);
                ldsm4(kl4, kBL + ad);
                mma16816(s[nf*2],     qfh[kk], kb[0],  kb[2]);
                mma16816(s[nf*2],     qfh[kk], kl4[0], kl4[2]);
                mma16816(s[nf*2],     qfl[kk], kb[0],  kb[2]);
                mma16816(s[nf*2 + 1], qfh[kk], kb[1],  kb[3]);
                mma16816(s[nf*2 + 1], qfh[kk], kl4[1], kl4[3]);
                mma16816(s[nf*2 + 1], qfl[kk], kb[1],  kb[3]);
            }
        }

        float mx0 = -1e30f, mx1 = -1e30f;
#pragma unroll
        for (int f = 0; f < 8; f++) {
            mx0 = fmaxf(mx0, fmaxf(s[f][0], s[f][1]));
            mx1 = fmaxf(mx1, fmaxf(s[f][2], s[f][3]));
        }
        mx0 = fmaxf(mx0, __shfl_xor_sync(0xffffffffu, mx0, 1));
        mx0 = fmaxf(mx0, __shfl_xor_sync(0xffffffffu, mx0, 2));
        mx1 = fmaxf(mx1, __shfl_xor_sync(0xffffffffu, mx1, 1));
        mx1 = fmaxf(mx1, __shfl_xor_sync(0xffffffffu, mx1, 2));
        float mn0 = fmaxf(mr0, mx0), mn1 = fmaxf(mr1, mx1);
        float c0 = __expf(mr0 - mn0), c1 = __expf(mr1 - mn1);
        float rs0 = 0.f, rs1 = 0.f;
#pragma unroll
        for (int f = 0; f < 8; f++) {
            s[f][0] = __expf(s[f][0] - mn0);
            s[f][1] = __expf(s[f][1] - mn0);
            s[f][2] = __expf(s[f][2] - mn1);
            s[f][3] = __expf(s[f][3] - mn1);
            rs0 += s[f][0] + s[f][1];
            rs1 += s[f][2] + s[f][3];
        }
        rs0 += __shfl_xor_sync(0xffffffffu, rs0, 1);
        rs0 += __shfl_xor_sync(0xffffffffu, rs0, 2);
        rs1 += __shfl_xor_sync(0xffffffffu, rs1, 1);
        rs1 += __shfl_xor_sync(0xffffffffu, rs1, 2);
        lr0 = lr0 * c0 + rs0;
        lr1 = lr1 * c1 + rs1;
        mr0 = mn0;
        mr1 = mn1;
#pragma unroll
        for (int f = 0; f < 8; f++) {
            o[f][0] *= c0; o[f][1] *= c0; o[f][2] *= c1; o[f][3] *= c1;
        }

#pragma unroll
        for (int kk2 = 0; kk2 < 4; kk2++) {
            uint32_t pah[4], pal[4];
            {
                int f0 = kk2 * 2;
                float h0,l0,h1,l1;
                fsplit(s[f0][0],h0,l0);     fsplit(s[f0][1],h1,l1);
                pah[0] = bpack(h0,h1);      pal[0] = bpack(l0,l1);
                fsplit(s[f0][2],h0,l0);     fsplit(s[f0][3],h1,l1);
                pah[1] = bpack(h0,h1);      pal[1] = bpack(l0,l1);
                fsplit(s[f0+1][0],h0,l0);   fsplit(s[f0+1][1],h1,l1);
                pah[2] = bpack(h0,h1);      pal[2] = bpack(l0,l1);
                fsplit(s[f0+1][2],h0,l0);   fsplit(s[f0+1][3],h1,l1);
                pah[3] = bpack(h0,h1);      pal[3] = bpack(l0,l1);
            }
#pragma unroll
            for (int nf = 0; nf < 4; nf++) {
                uint32_t ad = (uint32_t)((kk2*16 + (lane & 15)) * AS + nf*16 +
                                         ((lane >> 4) << 3)) * 2;
                uint32_t vb[4], vl4[4];
                ldsm4t(vb, vBH + ad);
                ldsm4t(vl4, vBL + ad);
                mma16816(o[nf*2],     pah, vb[0],  vb[1]);
                mma16816(o[nf*2],     pah, vl4[0], vl4[1]);
                mma16816(o[nf*2],     pal, vb[0],  vb[1]);
                mma16816(o[nf*2 + 1], pah, vb[2],  vb[3]);
                mma16816(o[nf*2 + 1], pah, vl4[2], vl4[3]);
                mma16816(o[nf*2 + 1], pal, vb[2],  vb[3]);
            }
        }
        buf ^= 1;
    }

    // normalize + split store
    float i0 = 1.f / lr0, i1 = 1.f / lr1;
    int rg = q0 + mrow + (lane >> 2);
#pragma unroll
    for (int f = 0; f < 8; f++) {
        int cc = f*8 + ((lane & 3) << 1);
        size_t p0 = gb + (size_t)rg*HD + cc;
        size_t p1 = gb + (size_t)(rg + 8)*HD + cc;
        float a0 = o[f][0]*i0, a1 = o[f][1]*i0;
        float b0 = o[f][2]*i1, b1 = o[f][3]*i1;
        float h0,l0,h1,l1;
        fsplit(a0,h0,l0); fsplit(a1,h1,l1);
        *(uint32_t*)(oh + p0) = bpack(h0,h1);
        *(uint32_t*)(ol + p0) = bpack(l0,l1);
        fsplit(b0,h0,l0); fsplit(b1,h1,l1);
        *(uint32_t*)(oh + p1) = bpack(h0,h1);
        *(uint32_t*)(ol + p1) = bpack(l0,l1);
    }
}

__global__ void mask_kernel(float* __restrict__ out)
{
    int i = blockIdx.x * blockDim.x + threadIdx.x;
    if (i < 2 * N0) {
        int lvl = i >> 11, n = i & (N0 - 1);
        out[i] = (lvl == 0 || n < N1) ? 1.f : 0.f;
    }
}

// ---------------------------------------------------------------------------
extern "C" void kernel_launch(void* const* d_in, const int* in_sizes, int n_in,
                              void* d_out, int out_size)
{
    (void)in_sizes; (void)n_in; (void)out_size;
    const float* inp0  = (const float*)d_in[0];
    const float* inp1  = (const float*)d_in[1];
    const float* amask = (const float*)d_in[2];
    const float* Wq0 = (const float*)d_in[3];
    const float* bq0 = (const float*)d_in[4];
    const float* Wk0 = (const float*)d_in[5];
    const float* bk0 = (const float*)d_in[6];
    const float* Wv0 = (const float*)d_in[7];
    const float* bv0 = (const float*)d_in[8];
    const float* Wq1 = (const float*)d_in[9];
    const float* bq1 = (const float*)d_in[10];
    const float* Wk1 = (const float*)d_in[11];
    const float* bk1 = (const float*)d_in[12];
    const float* Wv1 = (const float*)d_in[13];
    const float* bv1 = (const float*)d_in[14];
    const float* Wo  = (const float*)d_in[15];
    const float* bo  = (const float*)d_in[16];
    float* out = (float*)d_out;

    bf *ih0,*il0,*ih1,*il1, *wh0,*wl0,*wh1,*wl1, *woh,*wol;
    bf *qh0,*ql0,*kh0,*kl0,*vh0,*vl0, *qh1,*ql1,*kh1,*kl1,*vh1,*vl1;
    bf *oh0,*ol0,*oh1,*ol1;
    cudaGetSymbolAddress((void**)&ih0, g_ih0); cudaGetSymbolAddress((void**)&il0, g_il0);
    cudaGetSymbolAddress((void**)&ih1, g_ih1); cudaGetSymbolAddress((void**)&il1, g_il1);
    cudaGetSymbolAddress((void**)&wh0, g_wh0); cudaGetSymbolAddress((void**)&wl0, g_wl0);
    cudaGetSymbolAddress((void**)&wh1, g_wh1); cudaGetSymbolAddress((void**)&wl1, g_wl1);
    cudaGetSymbolAddress((void**)&woh, g_woh); cudaGetSymbolAddress((void**)&wol, g_wol);
    cudaGetSymbolAddress((void**)&qh0, g_qh0); cudaGetSymbolAddress((void**)&ql0, g_ql0);
    cudaGetSymbolAddress((void**)&kh0, g_kh0); cudaGetSymbolAddress((void**)&kl0, g_kl0);
    cudaGetSymbolAddress((void**)&vh0, g_vh0); cudaGetSymbolAddress((void**)&vl0, g_vl0);
    cudaGetSymbolAddress((void**)&qh1, g_qh1); cudaGetSymbolAddress((void**)&ql1, g_ql1);
    cudaGetSymbolAddress((void**)&kh1, g_kh1); cudaGetSymbolAddress((void**)&kl1, g_kl1);
    cudaGetSymbolAddress((void**)&vh1, g_vh1); cudaGetSymbolAddress((void**)&vl1, g_vl1);
    cudaGetSymbolAddress((void**)&oh0, g_oh0); cudaGetSymbolAddress((void**)&ol0, g_ol0);
    cudaGetSymbolAddress((void**)&oh1, g_oh1); cudaGetSymbolAddress((void**)&ol1, g_ol1);

    cudaFuncSetAttribute(qkv_gemm, cudaFuncAttributeMaxDynamicSharedMemorySize, GEMM_SMEM);
    cudaFuncSetAttribute(out_gemm, cudaFuncAttributeMaxDynamicSharedMemorySize, GEMM_SMEM);
    cudaFuncSetAttribute(attn_mma, cudaFuncAttributeMaxDynamicSharedMemorySize, ATTN_SMEM);

    // ---- split fp32 -> bf16 hi/lo ----
    SJobs ji = {{ {inp0, ih0, il0}, {inp1, ih1, il1}, {}, {} }};
    splitk<<<dim3(2048,1,2), 256>>>(ji, M0*768);
    SJobs j0 = {{ {Wq0, wh0, wl0},
                  {Wk0, wh0 + 768*768, wl0 + 768*768},
                  {Wv0, wh0 + 2*768*768, wl0 + 2*768*768}, {} }};
    splitk<<<dim3(256,1,3), 256>>>(j0, 768*768);
    SJobs j1 = {{ {Wq1, wh1, wl1},
                  {Wk1, wh1 + 1536*768, wl1 + 1536*768},
                  {Wv1, wh1 + 2*1536*768, wl1 + 2*1536*768},
                  {Wo, woh, wol} }};
    splitk<<<dim3(512,1,4), 256>>>(j1, 1536*768);

    dim3 blk(256);
    // ---- projections ----
    qkv_gemm<<<dim3(9, 128), blk, GEMM_SMEM>>>(ih0, il0, 768, wh0, wl0, 0,
        bq0, bk0, bv0, qh0, ql0, kh0, kl0, vh0, vl0, amask, N0);
    qkv_gemm<<<dim3(9, 64), blk, GEMM_SMEM>>>(ih1, il1, 1536, wh1, wl1, 384,
        bq1 + 384, bk1 + 384, bv1 + 384, qh1, ql1, kh1, kl1, vh1, vl1, amask, N1);

    // ---- attention ----
    attn_mma<<<dim3(N0/128, B*NH), blk, ATTN_SMEM>>>(qh0, ql0, kh0, kl0, vh0, vl0, oh0, ol0, N0);
    attn_mma<<<dim3(N1/128, B*NH), blk, ATTN_SMEM>>>(qh1, ql1, kh1, kl1, vh1, vl1, oh1, ol1, N1);

    // ---- output projection ----
    out_gemm<<<dim3(6, 128), blk, GEMM_SMEM>>>(oh0, ol0, oh1, ol1, woh, wol, bo, out);

    mask_kernel<<<16, 256>>>(out + OUT_ELEMS);
}

// round 9
// speedup vs baseline: 5.2181x; 1.0003x over previous
#include <cuda_runtime.h>
#include <cuda_bf16.h>
#include <stdint.h>

typedef __nv_bfloat16 bf;

#define B 8
#define N0 2048
#define N1 1024
#define HD 384
#define NH 6
#define M0 (B*N0)
#define M1 (B*N1)
#define OUT_ELEMS ((size_t)B*N0*768)

// ---- device-global scratch (allocation-free contract) ----
__device__ __align__(128) bf g_ih0[M0*768],  g_il0[M0*768];
__device__ __align__(128) bf g_ih1[M1*1536], g_il1[M1*1536];
__device__ __align__(128) bf g_wh0[3][768*768],  g_wl0[3][768*768];
__device__ __align__(128) bf g_wh1[3][1536*768], g_wl1[3][1536*768];
__device__ __align__(128) bf g_woh[1536*768], g_wol[1536*768];
__device__ __align__(128) bf g_qh0[M0*HD], g_ql0[M0*HD], g_kh0[M0*HD],
                             g_kl0[M0*HD], g_vh0[M0*HD], g_vl0[M0*HD];
__device__ __align__(128) bf g_qh1[M1*HD], g_ql1[M1*HD], g_kh1[M1*HD],
                             g_kl1[M1*HD], g_vh1[M1*HD], g_vl1[M1*HD];
__device__ __align__(128) bf g_oh0[M0*HD], g_ol0[M0*HD], g_oh1[M1*HD], g_ol1[M1*HD];

// ---- helpers ----
__device__ __forceinline__ uint32_t sm_u32(const void* p) {
    return (uint32_t)__cvta_generic_to_shared(p);
}
__device__ __forceinline__ void ldsm4(uint32_t r[4], uint32_t a) {
    asm volatile("ldmatrix.sync.aligned.m8n8.x4.shared.b16 {%0,%1,%2,%3}, [%4];"
        : "=r"(r[0]), "=r"(r[1]), "=r"(r[2]), "=r"(r[3]) : "r"(a));
}
__device__ __forceinline__ void ldsm4t(uint32_t r[4], uint32_t a) {
    asm volatile("ldmatrix.sync.aligned.m8n8.x4.trans.shared.b16 {%0,%1,%2,%3}, [%4];"
        : "=r"(r[0]), "=r"(r[1]), "=r"(r[2]), "=r"(r[3]) : "r"(a));
}
__device__ __forceinline__ void mma16816(float d[4], const uint32_t a[4],
                                          uint32_t b0, uint32_t b1) {
    asm volatile(
        "mma.sync.aligned.m16n8k16.row.col.f32.bf16.bf16.f32 "
        "{%0,%1,%2,%3}, {%4,%5,%6,%7}, {%8,%9}, {%0,%1,%2,%3};"
        : "+f"(d[0]), "+f"(d[1]), "+f"(d[2]), "+f"(d[3])
        : "r"(a[0]), "r"(a[1]), "r"(a[2]), "r"(a[3]), "r"(b0), "r"(b1));
}
__device__ __forceinline__ uint32_t bpack(float lo, float hi) {
    __nv_bfloat162 t = __floats2bfloat162_rn(lo, hi);
    return *reinterpret_cast<uint32_t*>(&t);
}
__device__ __forceinline__ void fsplit(float x, float& h, float& l) {
    bf b = __float2bfloat16(x);
    h = __bfloat162float(b);
    l = x - h;
}
__device__ __forceinline__ void cpa16(uint32_t d, const void* s) {
    asm volatile("cp.async.cg.shared.global [%0], [%1], 16;" :: "r"(d), "l"(s));
}
__device__ __forceinline__ void cp_commit() { asm volatile("cp.async.commit_group;"); }
__device__ __forceinline__ void cp_wait0()  { asm volatile("cp.async.wait_group 0;"); }

// ---- fp32 -> (hi, lo) bf16 split kernels ----
struct SJob  { const float* s; bf* h; bf* l; };
struct SJobs { SJob j[4]; };
__global__ void splitk(SJobs js, int n)
{
    SJob J = js.j[blockIdx.z];
    for (int i = (blockIdx.x * 256 + threadIdx.x) * 4; i < n; i += gridDim.x * 256 * 4) {
        float4 v = *(const float4*)(J.s + i);
        float h0,l0,h1,l1,h2,l2,h3,l3;
        fsplit(v.x,h0,l0); fsplit(v.y,h1,l1); fsplit(v.z,h2,l2); fsplit(v.w,h3,l3);
        *(uint2*)(J.h + i) = make_uint2(bpack(h0,h1), bpack(h2,h3));
        *(uint2*)(J.l + i) = make_uint2(bpack(l0,l1), bpack(l2,l3));
    }
}

// ---- GEMM core: CTA 128x128, 8 warps (2x4 of 64x32), k-stage 32,
//      cp.async double-buffered, bf16 hi/lo split -> 3 MMAs per k16 ----
#define GAS 40
#define GBS 136
#define GEMM_SMEM ((2*128*GAS + 2*32*GBS) * 2 * 2)

__device__ __forceinline__ void mma_ktile(
    uint32_t aBH, uint32_t aBL, uint32_t bBH, uint32_t bBL,
    int mrow, int ncol, int lane, float acc[4][4][4])
{
#pragma unroll
    for (int kk = 0; kk < 32; kk += 16) {
        uint32_t ah[4][4], al[4][4];
#pragma unroll
        for (int im = 0; im < 4; im++) {
            uint32_t ad = (uint32_t)((mrow + im*16 + (lane & 15)) * GAS +
                                     kk + ((lane >> 4) << 3)) * 2;
            ldsm4(ah[im], aBH + ad);
            ldsm4(al[im], aBL + ad);
        }
#pragma unroll
        for (int nf = 0; nf < 2; nf++) {
            uint32_t bd = (uint32_t)((kk + (lane & 15)) * GBS + ncol +
                                     nf*16 + ((lane >> 4) << 3)) * 2;
            uint32_t bh4[4], bl4[4];
            ldsm4t(bh4, bBH + bd);
            ldsm4t(bl4, bBL + bd);
#pragma unroll
            for (int im = 0; im < 4; im++) {
#pragma unroll
                for (int j = 0; j < 2; j++) {
                    float* d = acc[im][nf*2 + j];
                    mma16816(d, ah[im], bh4[2*j], bh4[2*j+1]);
                    mma16816(d, ah[im], bl4[2*j], bl4[2*j+1]);
                    mma16816(d, al[im], bh4[2*j], bh4[2*j+1]);
                }
            }
        }
    }
}

// issue one 128x32 A-tile + 32x128 B-tile via cp.async (pointers pre-offset)
__device__ __forceinline__ void gemm_cpa(
    const bf* aH, const bf* aL, int lda,
    const bf* wH, const bf* wL, int ldw,
    int tid, uint32_t dAh, uint32_t dAl, uint32_t dBh, uint32_t dBl)
{
    const int arow = tid >> 1, ak = (tid & 1) << 4;
    const size_t ao = (size_t)arow * lda + ak;
    const uint32_t ad = (uint32_t)(arow * GAS + ak) * 2;
    cpa16(dAh + ad, aH + ao);  cpa16(dAh + ad + 16, aH + ao + 8);
    cpa16(dAl + ad, aL + ao);  cpa16(dAl + ad + 16, aL + ao + 8);
    const int brow = tid >> 3, bc = (tid & 7) << 4;
    const size_t bo = (size_t)brow * ldw + bc;
    const uint32_t bd = (uint32_t)(brow * GBS + bc) * 2;
    cpa16(dBh + bd, wH + bo);  cpa16(dBh + bd + 16, wH + bo + 8);
    cpa16(dBl + bd, wL + bo);  cpa16(dBl + bd + 16, wL + bo + 8);
}

// ---- fused Q/K/V projection (one level): grid (9, M/128) ----
__global__ __launch_bounds__(256, 2) void qkv_gemm(
    const bf* __restrict__ Ah, const bf* __restrict__ Al, int K,
    const bf* __restrict__ W0h, const bf* __restrict__ W0l, int wOff,
    const float* __restrict__ bq, const float* __restrict__ bk,
    const float* __restrict__ bv,
    bf* qh, bf* ql, bf* kh, bf* kl, bf* vh, bf* vl,
    const float* __restrict__ mask, int nseq)
{
    extern __shared__ bf ds[];
    bf* Ahs = ds;
    bf* Als = Ahs + 2*128*GAS;
    bf* Bhs = Als + 2*128*GAS;
    bf* Bls = Bhs + 2*32*GBS;

    const int tid = threadIdx.x, lane = tid & 31, warp = tid >> 5;
    const int sel = blockIdx.x / 3, n0 = (blockIdx.x % 3) * 128;
    const int m0 = blockIdx.y * 128;
    const int mrow = (warp >> 2) * 64, ncol = (warp & 3) * 32;

    const bf* Wh = W0h + (size_t)sel * K * 768 + wOff + n0;
    const bf* Wl = W0l + (size_t)sel * K * 768 + wOff + n0;
    const float* bias = (sel == 0) ? bq : ((sel == 1) ? bk : bv);
    bf* Ch = (sel == 0) ? qh : ((sel == 1) ? kh : vh);
    bf* Cl = (sel == 0) ? ql : ((sel == 1) ? kl : vl);
    const bf* aH = Ah + (size_t)m0 * K;
    const bf* aL = Al + (size_t)m0 * K;

    float acc[4][4][4];
#pragma unroll
    for (int i = 0; i < 4; i++)
#pragma unroll
        for (int j = 0; j < 4; j++)
#pragma unroll
            for (int k = 0; k < 4; k++) acc[i][j][k] = 0.f;

    gemm_cpa(aH, aL, K, Wh, Wl, 768, tid,
             sm_u32(Ahs), sm_u32(Als), sm_u32(Bhs), sm_u32(Bls));
    cp_commit();

    int buf = 0;
    for (int k0 = 0; k0 < K; k0 += 32) {
        cp_wait0();
        __syncthreads();
        if (k0 + 32 < K) {
            int nb = buf ^ 1;
            gemm_cpa(aH + k0 + 32, aL + k0 + 32, K,
                     Wh + (size_t)(k0 + 32) * 768, Wl + (size_t)(k0 + 32) * 768, 768, tid,
                     sm_u32(Ahs + nb*128*GAS), sm_u32(Als + nb*128*GAS),
                     sm_u32(Bhs + nb*32*GBS),  sm_u32(Bls + nb*32*GBS));
            cp_commit();
        }
        mma_ktile(sm_u32(Ahs + buf*128*GAS), sm_u32(Als + buf*128*GAS),
                  sm_u32(Bhs + buf*32*GBS),  sm_u32(Bls + buf*32*GBS),
                  mrow, ncol, lane, acc);
        buf ^= 1;
    }

#pragma unroll
    for (int im = 0; im < 4; im++) {
        int r0g = m0 + mrow + im*16 + (lane >> 2);
#pragma unroll
        for (int f = 0; f < 4; f++) {
            int gcol = n0 + ncol + f*8 + ((lane & 3) << 1);
            float* d = acc[im][f];
#pragma unroll
            for (int hf = 0; hf < 2; hf++) {
                int rr = r0g + hf*8;
                float x0 = d[hf*2]     + bias[gcol];
                float x1 = d[hf*2 + 1] + bias[gcol + 1];
                if (sel == 0) {
                    const float* mk = mask + (rr / nseq) * 64;
                    x0 = x0 * 0.125f + mk[gcol & 63];
                    x1 = x1 * 0.125f + mk[(gcol + 1) & 63];
                }
                size_t o = (size_t)rr * HD + gcol;
                float h0,l0,h1,l1;
                fsplit(x0,h0,l0); fsplit(x1,h1,l1);
                *(uint32_t*)(Ch + o) = bpack(h0,h1);
                *(uint32_t*)(Cl + o) = bpack(l0,l1);
            }
        }
    }
}

// ---- fused output projection: grid (6, 128) ----
__global__ __launch_bounds__(256, 2) void out_gemm(
    const bf* __restrict__ o0h, const bf* __restrict__ o0l,
    const bf* __restrict__ o1h, const bf* __restrict__ o1l,
    const bf* __restrict__ Wh, const bf* __restrict__ Wl,
    const float* __restrict__ bo, float* __restrict__ out)
{
    extern __shared__ bf ds[];
    bf* Ahs = ds;
    bf* Als = Ahs + 2*128*GAS;
    bf* Bhs = Als + 2*128*GAS;
    bf* Bls = Bhs + 2*32*GBS;

    const int tid = threadIdx.x, lane = tid & 31, warp = tid >> 5;
    const int n0 = blockIdx.x * 128, m0 = blockIdx.y * 128;
    const int mrow = (warp >> 2) * 64, ncol = (warp & 3) * 32;

    const bool lower = (m0 & 2047) < 1024;
    const int nkt = lower ? 24 : 12;
    const int o1r0 = (m0 >> 11) * 1024 + (m0 & 2047);

    float acc[4][4][4];
#pragma unroll
    for (int i = 0; i < 4; i++)
#pragma unroll
        for (int j = 0; j < 4; j++)
#pragma unroll
            for (int k = 0; k < 4; k++) acc[i][j][k] = 0.f;

    auto issue = [&](int t, int nb) {
        const bf *aH, *aL; int kc, wr;
        if (t < 12) { aH = o0h + (size_t)m0*HD;   aL = o0l + (size_t)m0*HD;
                      kc = t*32;        wr = t*32; }
        else        { aH = o1h + (size_t)o1r0*HD; aL = o1l + (size_t)o1r0*HD;
                      kc = (t-12)*32;   wr = 768 + (t-12)*32; }
        gemm_cpa(aH + kc, aL + kc, HD,
                 Wh + (size_t)wr*768 + n0, Wl + (size_t)wr*768 + n0, 768, tid,
                 sm_u32(Ahs + nb*128*GAS), sm_u32(Als + nb*128*GAS),
                 sm_u32(Bhs + nb*32*GBS),  sm_u32(Bls + nb*32*GBS));
        cp_commit();
    };

    issue(0, 0);
    int buf = 0;
    for (int t = 0; t < nkt; t++) {
        cp_wait0();
        __syncthreads();
        if (t + 1 < nkt) issue(t + 1, buf ^ 1);
        mma_ktile(sm_u32(Ahs + buf*128*GAS), sm_u32(Als + buf*128*GAS),
                  sm_u32(Bhs + buf*32*GBS),  sm_u32(Bls + buf*32*GBS),
                  mrow, ncol, lane, acc);
        buf ^= 1;
    }

#pragma unroll
    for (int im = 0; im < 4; im++) {
        int r0g = m0 + mrow + im*16 + (lane >> 2);
#pragma unroll
        for (int f = 0; f < 4; f++) {
            int gcol = n0 + ncol + f*8 + ((lane & 3) << 1);
            float* d = acc[im][f];
#pragma unroll
            for (int hf = 0; hf < 2; hf++) {
                int rr = r0g + hf*8;
                out[(size_t)rr*768 + gcol]     = d[hf*2]     + bo[gcol];
                out[(size_t)rr*768 + gcol + 1] = d[hf*2 + 1] + bo[gcol + 1];
            }
        }
    }
}

// ---- flash attention: cp.async double-buffered KV, split bf16 output ----
#define AS 72
#define ABUF (4*64*AS)            // halves per KV buffer
#define ATTN_SMEM (2*ABUF*2)      // bytes

__global__ __launch_bounds__(256, 2) void attn_mma(
    const bf* __restrict__ qh, const bf* __restrict__ ql,
    const bf* __restrict__ kh, const bf* __restrict__ kl,
    const bf* __restrict__ vh, const bf* __restrict__ vl,
    bf* __restrict__ oh, bf* __restrict__ ol, int Nq)
{
    extern __shared__ bf smem[];

    const int tid = threadIdx.x, lane = tid & 31, warp = tid >> 5;
    const int b = blockIdx.y / NH, h = blockIdx.y % NH;
    const int q0 = blockIdx.x * 128;
    const size_t gb = (size_t)b * Nq * HD + (size_t)h * 64;
    const int mrow = warp * 16;

    // stage Q (hi at 0, lo at 2*64*AS), extract frags, release smem
    {
        const bf* Qh = qh + gb + (size_t)q0 * HD;
        const bf* Ql = ql + gb + (size_t)q0 * HD;
#pragma unroll
        for (int it = 0; it < 4; it++) {
            int i = tid + it * 256;
            int r = i >> 3, u = (i & 7) * 8;
            *(uint4*)&smem[r*AS + u]            = *(const uint4*)&Qh[(size_t)r*HD + u];
            *(uint4*)&smem[2*64*AS + r*AS + u]  = *(const uint4*)&Ql[(size_t)r*HD + u];
        }
    }
    __syncthreads();
    uint32_t qfh[4][4], qfl[4][4];
    {
        const uint32_t bh_ = sm_u32(smem);
        const uint32_t bl_ = sm_u32(smem + 2*64*AS);
        int row = mrow + (lane & 15);
#pragma unroll
        for (int kk = 0; kk < 4; kk++) {
            uint32_t off = (uint32_t)(row*AS + kk*16 + ((lane >> 4) << 3)) * 2;
            ldsm4(qfh[kk], bh_ + off);
            ldsm4(qfl[kk], bl_ + off);
        }
    }
    __syncthreads();

    auto kvload = [&](int kv, int nb) {
        const bf* Kh = kh + gb + (size_t)kv * HD;
        const bf* Kl = kl + gb + (size_t)kv * HD;
        const bf* Vh = vh + gb + (size_t)kv * HD;
        const bf* Vl = vl + gb + (size_t)kv * HD;
        uint32_t d = sm_u32(smem + nb * ABUF);
#pragma unroll
        for (int it = 0; it < 2; it++) {
            int i = tid + it * 256;
            int r = i >> 3, u = (i & 7) * 8;
            size_t go = (size_t)r * HD + u;
            uint32_t so = (uint32_t)(r*AS + u) * 2;
            cpa16(d + so,              Kh + go);
            cpa16(d + 64*AS*2 + so,    Kl + go);
            cpa16(d + 2*64*AS*2 + so,  Vh + go);
            cpa16(d + 3*64*AS*2 + so,  Vl + go);
        }
        cp_commit();
    };

    float o[8][4];
#pragma unroll
    for (int f = 0; f < 8; f++)
#pragma unroll
        for (int k = 0; k < 4; k++) o[f][k] = 0.f;
    float mr0 = -1e30f, mr1 = -1e30f, lr0 = 0.f, lr1 = 0.f;

    kvload(0, 0);
    int buf = 0;
    for (int kv = 0; kv < Nq; kv += 64) {
        cp_wait0();
        __syncthreads();
        if (kv + 64 < Nq) kvload(kv + 64, buf ^ 1);

        const uint32_t base = sm_u32(smem + buf * ABUF);
        const uint32_t kBH = base, kBL = base + 64*AS*2;
        const uint32_t vBH = base + 2*64*AS*2, vBL = base + 3*64*AS*2;

        float s[8][4];
#pragma unroll
        for (int f = 0; f < 8; f++)
#pragma unroll
            for (int k = 0; k < 4; k++) s[f][k] = 0.f;
#pragma unroll
        for (int kk = 0; kk < 4; kk++) {
#pragma unroll
            for (int nf = 0; nf < 4; nf++) {
                uint32_t ad = (uint32_t)((nf*16 + (lane & 15)) * AS + kk*16 +
                                         ((lane >> 4) << 3)) * 2;
                uint32_t kb[4], kl4[4];
                ldsm4(kb, kBH + ad);
                ldsm4(kl4, kBL + ad);
                mma16816(s[nf*2],     qfh[kk], kb[0],  kb[2]);
                mma16816(s[nf*2],     qfh[kk], kl4[0], kl4[2]);
                mma16816(s[nf*2],     qfl[kk], kb[0],  kb[2]);
                mma16816(s[nf*2 + 1], qfh[kk], kb[1],  kb[3]);
                mma16816(s[nf*2 + 1], qfh[kk], kl4[1], kl4[3]);
                mma16816(s[nf*2 + 1], qfl[kk], kb[1],  kb[3]);
            }
        }

        float mx0 = -1e30f, mx1 = -1e30f;
#pragma unroll
        for (int f = 0; f < 8; f++) {
            mx0 = fmaxf(mx0, fmaxf(s[f][0], s[f][1]));
            mx1 = fmaxf(mx1, fmaxf(s[f][2], s[f][3]));
        }
        mx0 = fmaxf(mx0, __shfl_xor_sync(0xffffffffu, mx0, 1));
        mx0 = fmaxf(mx0, __shfl_xor_sync(0xffffffffu, mx0, 2));
        mx1 = fmaxf(mx1, __shfl_xor_sync(0xffffffffu, mx1, 1));
        mx1 = fmaxf(mx1, __shfl_xor_sync(0xffffffffu, mx1, 2));
        float mn0 = fmaxf(mr0, mx0), mn1 = fmaxf(mr1, mx1);
        float c0 = __expf(mr0 - mn0), c1 = __expf(mr1 - mn1);
        float rs0 = 0.f, rs1 = 0.f;
#pragma unroll
        for (int f = 0; f < 8; f++) {
            s[f][0] = __expf(s[f][0] - mn0);
            s[f][1] = __expf(s[f][1] - mn0);
            s[f][2] = __expf(s[f][2] - mn1);
            s[f][3] = __expf(s[f][3] - mn1);
            rs0 += s[f][0] + s[f][1];
            rs1 += s[f][2] + s[f][3];
        }
        rs0 += __shfl_xor_sync(0xffffffffu, rs0, 1);
        rs0 += __shfl_xor_sync(0xffffffffu, rs0, 2);
        rs1 += __shfl_xor_sync(0xffffffffu, rs1, 1);
        rs1 += __shfl_xor_sync(0xffffffffu, rs1, 2);
        lr0 = lr0 * c0 + rs0;
        lr1 = lr1 * c1 + rs1;
        mr0 = mn0;
        mr1 = mn1;
#pragma unroll
        for (int f = 0; f < 8; f++) {
            o[f][0] *= c0; o[f][1] *= c0; o[f][2] *= c1; o[f][3] *= c1;
        }

#pragma unroll
        for (int kk2 = 0; kk2 < 4; kk2++) {
            uint32_t pah[4], pal[4];
            {
                int f0 = kk2 * 2;
                float h0,l0,h1,l1;
                fsplit(s[f0][0],h0,l0);     fsplit(s[f0][1],h1,l1);
                pah[0] = bpack(h0,h1);      pal[0] = bpack(l0,l1);
                fsplit(s[f0][2],h0,l0);     fsplit(s[f0][3],h1,l1);
                pah[1] = bpack(h0,h1);      pal[1] = bpack(l0,l1);
                fsplit(s[f0+1][0],h0,l0);   fsplit(s[f0+1][1],h1,l1);
                pah[2] = bpack(h0,h1);      pal[2] = bpack(l0,l1);
                fsplit(s[f0+1][2],h0,l0);   fsplit(s[f0+1][3],h1,l1);
                pah[3] = bpack(h0,h1);      pal[3] = bpack(l0,l1);
            }
#pragma unroll
            for (int nf = 0; nf < 4; nf++) {
                uint32_t ad = (uint32_t)((kk2*16 + (lane & 15)) * AS + nf*16 +
                                         ((lane >> 4) << 3)) * 2;
                uint32_t vb[4], vl4[4];
                ldsm4t(vb, vBH + ad);
                ldsm4t(vl4, vBL + ad);
                mma16816(o[nf*2],     pah, vb[0],  vb[1]);
                mma16816(o[nf*2],     pah, vl4[0], vl4[1]);
                mma16816(o[nf*2],     pal, vb[0],  vb[1]);
                mma16816(o[nf*2 + 1], pah, vb[2],  vb[3]);
                mma16816(o[nf*2 + 1], pah, vl4[2], vl4[3]);
                mma16816(o[nf*2 + 1], pal, vb[2],  vb[3]);
            }
        }
        buf ^= 1;
    }

    // normalize + split store
    float i0 = 1.f / lr0, i1 = 1.f / lr1;
    int rg = q0 + mrow + (lane >> 2);
#pragma unroll
    for (int f = 0; f < 8; f++) {
        int cc = f*8 + ((lane & 3) << 1);
        size_t p0 = gb + (size_t)rg*HD + cc;
        size_t p1 = gb + (size_t)(rg + 8)*HD + cc;
        float a0 = o[f][0]*i0, a1 = o[f][1]*i0;
        float b0 = o[f][2]*i1, b1 = o[f][3]*i1;
        float h0,l0,h1,l1;
        fsplit(a0,h0,l0); fsplit(a1,h1,l1);
        *(uint32_t*)(oh + p0) = bpack(h0,h1);
        *(uint32_t*)(ol + p0) = bpack(l0,l1);
        fsplit(b0,h0,l0); fsplit(b1,h1,l1);
        *(uint32_t*)(oh + p1) = bpack(h0,h1);
        *(uint32_t*)(ol + p1) = bpack(l0,l1);
    }
}

__global__ void mask_kernel(float* __restrict__ out)
{
    int i = blockIdx.x * blockDim.x + threadIdx.x;
    if (i < 2 * N0) {
        int lvl = i >> 11, n = i & (N0 - 1);
        out[i] = (lvl == 0 || n < N1) ? 1.f : 0.f;
    }
}

// ---------------------------------------------------------------------------
extern "C" void kernel_launch(void* const* d_in, const int* in_sizes, int n_in,
                              void* d_out, int out_size)
{
    (void)in_sizes; (void)n_in; (void)out_size;
    const float* inp0  = (const float*)d_in[0];
    const float* inp1  = (const float*)d_in[1];
    const float* amask = (const float*)d_in[2];
    const float* Wq0 = (const float*)d_in[3];
    const float* bq0 = (const float*)d_in[4];
    const float* Wk0 = (const float*)d_in[5];
    const float* bk0 = (const float*)d_in[6];
    const float* Wv0 = (const float*)d_in[7];
    const float* bv0 = (const float*)d_in[8];
    const float* Wq1 = (const float*)d_in[9];
    const float* bq1 = (const float*)d_in[10];
    const float* Wk1 = (const float*)d_in[11];
    const float* bk1 = (const float*)d_in[12];
    const float* Wv1 = (const float*)d_in[13];
    const float* bv1 = (const float*)d_in[14];
    const float* Wo  = (const float*)d_in[15];
    const float* bo  = (const float*)d_in[16];
    float* out = (float*)d_out;

    bf *ih0,*il0,*ih1,*il1, *wh0,*wl0,*wh1,*wl1, *woh,*wol;
    bf *qh0,*ql0,*kh0,*kl0,*vh0,*vl0, *qh1,*ql1,*kh1,*kl1,*vh1,*vl1;
    bf *oh0,*ol0,*oh1,*ol1;
    cudaGetSymbolAddress((void**)&ih0, g_ih0); cudaGetSymbolAddress((void**)&il0, g_il0);
    cudaGetSymbolAddress((void**)&ih1, g_ih1); cudaGetSymbolAddress((void**)&il1, g_il1);
    cudaGetSymbolAddress((void**)&wh0, g_wh0); cudaGetSymbolAddress((void**)&wl0, g_wl0);
    cudaGetSymbolAddress((void**)&wh1, g_wh1); cudaGetSymbolAddress((void**)&wl1, g_wl1);
    cudaGetSymbolAddress((void**)&woh, g_woh); cudaGetSymbolAddress((void**)&wol, g_wol);
    cudaGetSymbolAddress((void**)&qh0, g_qh0); cudaGetSymbolAddress((void**)&ql0, g_ql0);
    cudaGetSymbolAddress((void**)&kh0, g_kh0); cudaGetSymbolAddress((void**)&kl0, g_kl0);
    cudaGetSymbolAddress((void**)&vh0, g_vh0); cudaGetSymbolAddress((void**)&vl0, g_vl0);
    cudaGetSymbolAddress((void**)&qh1, g_qh1); cudaGetSymbolAddress((void**)&ql1, g_ql1);
    cudaGetSymbolAddress((void**)&kh1, g_kh1); cudaGetSymbolAddress((void**)&kl1, g_kl1);
    cudaGetSymbolAddress((void**)&vh1, g_vh1); cudaGetSymbolAddress((void**)&vl1, g_vl1);
    cudaGetSymbolAddress((void**)&oh0, g_oh0); cudaGetSymbolAddress((void**)&ol0, g_ol0);
    cudaGetSymbolAddress((void**)&oh1, g_oh1); cudaGetSymbolAddress((void**)&ol1, g_ol1);

    cudaFuncSetAttribute(qkv_gemm, cudaFuncAttributeMaxDynamicSharedMemorySize, GEMM_SMEM);
    cudaFuncSetAttribute(out_gemm, cudaFuncAttributeMaxDynamicSharedMemorySize, GEMM_SMEM);
    cudaFuncSetAttribute(attn_mma, cudaFuncAttributeMaxDynamicSharedMemorySize, ATTN_SMEM);

    // ---- split fp32 -> bf16 hi/lo ----
    SJobs ji = {{ {inp0, ih0, il0}, {inp1, ih1, il1}, {}, {} }};
    splitk<<<dim3(2048,1,2), 256>>>(ji, M0*768);
    SJobs j0 = {{ {Wq0, wh0, wl0},
                  {Wk0, wh0 + 768*768, wl0 + 768*768},
                  {Wv0, wh0 + 2*768*768, wl0 + 2*768*768}, {} }};
    splitk<<<dim3(256,1,3), 256>>>(j0, 768*768);
    SJobs j1 = {{ {Wq1, wh1, wl1},
                  {Wk1, wh1 + 1536*768, wl1 + 1536*768},
                  {Wv1, wh1 + 2*1536*768, wl1 + 2*1536*768},
                  {Wo, woh, wol} }};
    splitk<<<dim3(512,1,4), 256>>>(j1, 1536*768);

    dim3 blk(256);
    // ---- projections ----
    qkv_gemm<<<dim3(9, 128), blk, GEMM_SMEM>>>(ih0, il0, 768, wh0, wl0, 0,
        bq0, bk0, bv0, qh0, ql0, kh0, kl0, vh0, vl0, amask, N0);
    qkv_gemm<<<dim3(9, 64), blk, GEMM_SMEM>>>(ih1, il1, 1536, wh1, wl1, 384,
        bq1 + 384, bk1 + 384, bv1 + 384, qh1, ql1, kh1, kl1, vh1, vl1, amask, N1);

    // ---- attention ----
    attn_mma<<<dim3(N0/128, B*NH), blk, ATTN_SMEM>>>(qh0, ql0, kh0, kl0, vh0, vl0, oh0, ol0, N0);
    attn_mma<<<dim3(N1/128, B*NH), blk, ATTN_SMEM>>>(qh1, ql1, kh1, kl1, vh1, vl1, oh1, ol1, N1);

    // ---- output projection ----
    out_gemm<<<dim3(6, 128), blk, GEMM_SMEM>>>(oh0, ol0, oh1, ol1, woh, wol, bo, out);

    mask_kernel<<<16, 256>>>(out + OUT_ELEMS);
}

// round 11
// speedup vs baseline: 5.6010x; 1.0734x over previous
#include <cuda_runtime.h>
#include <cuda_bf16.h>
#include <cuda_fp16.h>
#include <stdint.h>
typedef __nv_bfloat16 bf;
typedef __half hf;

#define B 8
#define N0 2048
#define N1 1024
#define HD 384
#define NH 6
#define M0 (B*N0)
#define M1 (B*N1)
#define OUT_ELEMS ((size_t)B*N0*768)

__device__ __align__(128) bf g_ih0[M0*768],  g_il0[M0*768];
__device__ __align__(128) bf g_ih1[M1*1536], g_il1[M1*1536];
__device__ __align__(128) bf g_wh0[3][768*768],  g_wl0[3][768*768];
__device__ __align__(128) bf g_wh1[3][1536*768], g_wl1[3][1536*768];
__device__ __align__(128) hf g_wo[1536*768];                       // fp16 single
__device__ __align__(128) bf g_qh0[M0*HD], g_ql0[M0*HD], g_kh0[M0*HD], g_kl0[M0*HD];
__device__ __align__(128) hf g_v0[M0*HD];
__device__ __align__(128) bf g_qh1[M1*HD], g_ql1[M1*HD], g_kh1[M1*HD], g_kl1[M1*HD];
__device__ __align__(128) hf g_v1[M1*HD];
__device__ __align__(128) hf g_oh0[M0*HD], g_ol0[M0*HD], g_oh1[M1*HD], g_ol1[M1*HD];

__device__ __forceinline__ uint32_t sm_u32(const void* p) {
    return (uint32_t)__cvta_generic_to_shared(p);
}
__device__ __forceinline__ void ldsm4(uint32_t r[4], uint32_t a) {
    asm volatile("ldmatrix.sync.aligned.m8n8.x4.shared.b16 {%0,%1,%2,%3}, [%4];"
        : "=r"(r[0]), "=r"(r[1]), "=r"(r[2]), "=r"(r[3]) : "r"(a));
}
__device__ __forceinline__ void ldsm4t(uint32_t r[4], uint32_t a) {
    asm volatile("ldmatrix.sync.aligned.m8n8.x4.trans.shared.b16 {%0,%1,%2,%3}, [%4];"
        : "=r"(r[0]), "=r"(r[1]), "=r"(r[2]), "=r"(r[3]) : "r"(a));
}
// bf16 mma
__device__ __forceinline__ void mma_bf(float d[4], const uint32_t a[4],
                                       uint32_t b0, uint32_t b1) {
    asm volatile("mma.sync.aligned.m16n8k16.row.col.f32.bf16.bf16.f32 "
        "{%0,%1,%2,%3}, {%4,%5,%6,%7}, {%8,%9}, {%0,%1,%2,%3};"
        : "+f"(d[0]), "+f"(d[1]), "+f"(d[2]), "+f"(d[3])
        : "r"(a[0]), "r"(a[1]), "r"(a[2]), "r"(a[3]), "r"(b0), "r"(b1));
}
// fp16 mma
__device__ __forceinline__ void mma_hf(float d[4], const uint32_t a[4],
                                       uint32_t b0, uint32_t b1) {
    asm volatile("mma.sync.aligned.m16n8k16.row.col.f32.f16.f16.f32 "
        "{%0,%1,%2,%3}, {%4,%5,%6,%7}, {%8,%9}, {%0,%1,%2,%3};"
        : "+f"(d[0]), "+f"(d[1]), "+f"(d[2]), "+f"(d[3])
        : "r"(a[0]), "r"(a[1]), "r"(a[2]), "r"(a[3]), "r"(b0), "r"(b1));
}
__device__ __forceinline__ uint32_t bpack(float lo, float hi) {
    __nv_bfloat162 t = __floats2bfloat162_rn(lo, hi);
    return *reinterpret_cast<uint32_t*>(&t);
}
__device__ __forceinline__ void fsplit(float x, float& h, float& l) {
    bf b = __float2bfloat16(x);
    h = __bfloat162float(b);
    l = x - h;
}
__device__ __forceinline__ uint32_t hpack(float lo, float hi) {
    __half2 t = __floats2half2_rn(lo, hi);   // lo -> .x (element 0)
    return *reinterpret_cast<uint32_t*>(&t);
}
__device__ __forceinline__ void hsplit(float x, float& h, float& l) {
    hf b = __float2half_rn(x);
    h = __half2float(b);
    l = x - h;
}
__device__ __forceinline__ void cpa16(uint32_t d, const void* s) {
    asm volatile("cp.async.cg.shared.global [%0], [%1], 16;" :: "r"(d), "l"(s));
}
__device__ __forceinline__ void cp_commit() { asm volatile("cp.async.commit_group;"); }
__device__ __forceinline__ void cp_wait0()  { asm volatile("cp.async.wait_group 0;"); }
__device__ __forceinline__ void cp_wait1()  { asm volatile("cp.async.wait_group 1;"); }

// ---- prep kernels ----
struct SJob  { const float* s; bf* h; bf* l; };
struct SJobs { SJob j[3]; };
__global__ void splitk(SJobs js, int n) {
    SJob J = js.j[blockIdx.z];
    for (int i = (blockIdx.x*256 + threadIdx.x)*4; i < n; i += gridDim.x*256*4) {
        float4 v = *(const float4*)(J.s + i);
        float h0,l0,h1,l1,h2,l2,h3,l3;
        fsplit(v.x,h0,l0); fsplit(v.y,h1,l1); fsplit(v.z,h2,l2); fsplit(v.w,h3,l3);
        *(uint2*)(J.h + i) = make_uint2(bpack(h0,h1), bpack(h2,h3));
        *(uint2*)(J.l + i) = make_uint2(bpack(l0,l1), bpack(l2,l3));
    }
}
__global__ void cvtk(const float* __restrict__ s, hf* __restrict__ d, int n) {
    for (int i = (blockIdx.x*256 + threadIdx.x)*4; i < n; i += gridDim.x*256*4) {
        float4 v = *(const float4*)(s + i);
        *(uint2*)(d + i) = make_uint2(hpack(v.x, v.y), hpack(v.z, v.w));
    }
}

// ---- bf16 3-term GEMM core (qkv): CTA 128x128, 8 warps, k-stage 32 ----
#define GAS 40
#define GBS 136
#define GEMM_SMEM ((2*128*GAS + 2*32*GBS) * 2 * 2)

__device__ __forceinline__ void mma_ktile(
    uint32_t aBH, uint32_t aBL, uint32_t bBH, uint32_t bBL,
    int mrow, int ncol, int lane, float acc[4][4][4])
{
#pragma unroll
    for (int kk = 0; kk < 32; kk += 16) {
        uint32_t ah[4][4], al[4][4];
#pragma unroll
        for (int im = 0; im < 4; im++) {
            uint32_t ad = (uint32_t)((mrow + im*16 + (lane & 15)) * GAS +
                                     kk + ((lane >> 4) << 3)) * 2;
            ldsm4(ah[im], aBH + ad);
            ldsm4(al[im], aBL + ad);
        }
#pragma unroll
        for (int nf = 0; nf < 2; nf++) {
            uint32_t bd = (uint32_t)((kk + (lane & 15)) * GBS + ncol +
                                     nf*16 + ((lane >> 4) << 3)) * 2;
            uint32_t bh4[4], bl4[4];
            ldsm4t(bh4, bBH + bd);
            ldsm4t(bl4, bBL + bd);
#pragma unroll
            for (int im = 0; im < 4; im++) {
#pragma unroll
                for (int j = 0; j < 2; j++) {
                    float* d = acc[im][nf*2 + j];
                    mma_bf(d, ah[im], bh4[2*j], bh4[2*j+1]);
                    mma_bf(d, ah[im], bl4[2*j], bl4[2*j+1]);
                    mma_bf(d, al[im], bh4[2*j], bh4[2*j+1]);
                }
            }
        }
    }
}
__device__ __forceinline__ void gemm_cpa(
    const bf* aH, const bf* aL, int lda,
    const bf* wH, const bf* wL, int ldw,
    int tid, uint32_t dAh, uint32_t dAl, uint32_t dBh, uint32_t dBl)
{
    const int arow = tid >> 1, ak = (tid & 1) << 4;
    const size_t ao = (size_t)arow * lda + ak;
    const uint32_t ad = (uint32_t)(arow * GAS + ak) * 2;
    cpa16(dAh + ad, aH + ao);  cpa16(dAh + ad + 16, aH + ao + 8);
    cpa16(dAl + ad, aL + ao);  cpa16(dAl + ad + 16, aL + ao + 8);
    const int brow = tid >> 3, bc = (tid & 7) << 4;
    const size_t bo = (size_t)brow * ldw + bc;
    const uint32_t bd = (uint32_t)(brow * GBS + bc) * 2;
    cpa16(dBh + bd, wH + bo);  cpa16(dBh + bd + 16, wH + bo + 8);
    cpa16(dBl + bd, wL + bo);  cpa16(dBl + bd + 16, wL + bo + 8);
}

// ---- fused Q/K/V projection (bf16 3-term; v stored single fp16) ----
__global__ __launch_bounds__(256, 2) void qkv_gemm(
    const bf* __restrict__ Ah, const bf* __restrict__ Al, int K,
    const bf* __restrict__ W0h, const bf* __restrict__ W0l, int wOff,
    const float* __restrict__ bq, const float* __restrict__ bk,
    const float* __restrict__ bv,
    bf* qh, bf* ql, bf* kh, bf* kl, hf* v,
    const float* __restrict__ mask, int nseq)
{
    extern __shared__ bf ds[];
    bf* Ahs = ds;
    bf* Als = Ahs + 2*128*GAS;
    bf* Bhs = Als + 2*128*GAS;
    bf* Bls = Bhs + 2*32*GBS;

    const int tid = threadIdx.x, lane = tid & 31, warp = tid >> 5;
    const int sel = blockIdx.x / 3, n0 = (blockIdx.x % 3) * 128;
    const int m0 = blockIdx.y * 128;
    const int mrow = (warp >> 2) * 64, ncol = (warp & 3) * 32;

    const bf* Wh = W0h + (size_t)sel * K * 768 + wOff + n0;
    const bf* Wl = W0l + (size_t)sel * K * 768 + wOff + n0;
    const float* bias = (sel == 0) ? bq : ((sel == 1) ? bk : bv);
    const bf* aH = Ah + (size_t)m0 * K;
    const bf* aL = Al + (size_t)m0 * K;

    float acc[4][4][4];
#pragma unroll
    for (int i = 0; i < 4; i++)
#pragma unroll
        for (int j = 0; j < 4; j++)
#pragma unroll
            for (int k = 0; k < 4; k++) acc[i][j][k] = 0.f;

    gemm_cpa(aH, aL, K, Wh, Wl, 768, tid,
             sm_u32(Ahs), sm_u32(Als), sm_u32(Bhs), sm_u32(Bls));
    cp_commit();

    int buf = 0;
    for (int k0 = 0; k0 < K; k0 += 32) {
        cp_wait0();
        __syncthreads();
        if (k0 + 32 < K) {
            int nb = buf ^ 1;
            gemm_cpa(aH + k0 + 32, aL + k0 + 32, K,
                     Wh + (size_t)(k0 + 32)*768, Wl + (size_t)(k0 + 32)*768, 768, tid,
                     sm_u32(Ahs + nb*128*GAS), sm_u32(Als + nb*128*GAS),
                     sm_u32(Bhs + nb*32*GBS),  sm_u32(Bls + nb*32*GBS));
            cp_commit();
        }
        mma_ktile(sm_u32(Ahs + buf*128*GAS), sm_u32(Als + buf*128*GAS),
                  sm_u32(Bhs + buf*32*GBS),  sm_u32(Bls + buf*32*GBS),
                  mrow, ncol, lane, acc);
        buf ^= 1;
    }

#pragma unroll
    for (int im = 0; im < 4; im++) {
        int r0g = m0 + mrow + im*16 + (lane >> 2);
#pragma unroll
        for (int f = 0; f < 4; f++) {
            int gcol = n0 + ncol + f*8 + ((lane & 3) << 1);
            float* d = acc[im][f];
#pragma unroll
            for (int hfi = 0; hfi < 2; hfi++) {
                int rr = r0g + hfi*8;
                float x0 = d[hfi*2]     + bias[gcol];
                float x1 = d[hfi*2 + 1] + bias[gcol + 1];
                size_t o = (size_t)rr * HD + gcol;
                if (sel == 2) {
                    *(uint32_t*)(v + o) = hpack(x0, x1);
                } else {
                    bf *Ch = (sel == 0) ? qh : kh;
                    bf *Cl = (sel == 0) ? ql : kl;
                    if (sel == 0) {
                        const float* mk = mask + (rr / nseq) * 64;
                        x0 = x0*0.125f + mk[gcol & 63];
                        x1 = x1*0.125f + mk[(gcol + 1) & 63];
                    }
                    float h0,l0,h1,l1;
                    fsplit(x0,h0,l0); fsplit(x1,h1,l1);
                    *(uint32_t*)(Ch + o) = bpack(h0,h1);
                    *(uint32_t*)(Cl + o) = bpack(l0,l1);
                }
            }
        }
    }
}

// ---- fp16 2-term GEMM core (out): A h/l fp16 exact, B single fp16 ----
__device__ __forceinline__ void mma_ktile_h(
    uint32_t aBH, uint32_t aBL, uint32_t bB,
    int mrow, int ncol, int lane, float acc[4][4][4])
{
#pragma unroll
    for (int kk = 0; kk < 32; kk += 16) {
        uint32_t ah[4][4], al[4][4];
#pragma unroll
        for (int im = 0; im < 4; im++) {
            uint32_t ad = (uint32_t)((mrow + im*16 + (lane & 15)) * GAS +
                                     kk + ((lane >> 4) << 3)) * 2;
            ldsm4(ah[im], aBH + ad);
            ldsm4(al[im], aBL + ad);
        }
#pragma unroll
        for (int nf = 0; nf < 2; nf++) {
            uint32_t bd = (uint32_t)((kk + (lane & 15)) * GBS + ncol +
                                     nf*16 + ((lane >> 4) << 3)) * 2;
            uint32_t b4[4];
            ldsm4t(b4, bB + bd);
#pragma unroll
            for (int im = 0; im < 4; im++) {
#pragma unroll
                for (int j = 0; j < 2; j++) {
                    float* d = acc[im][nf*2 + j];
                    mma_hf(d, ah[im], b4[2*j], b4[2*j+1]);
                    mma_hf(d, al[im], b4[2*j], b4[2*j+1]);
                }
            }
        }
    }
}
__device__ __forceinline__ void gemm_cpa2(
    const hf* aH, const hf* aL, int lda,
    const hf* w, int ldw, int tid,
    uint32_t dAh, uint32_t dAl, uint32_t dB)
{
    const int arow = tid >> 1, ak = (tid & 1) << 4;
    const size_t ao = (size_t)arow * lda + ak;
    const uint32_t ad = (uint32_t)(arow * GAS + ak) * 2;
    cpa16(dAh + ad, aH + ao);  cpa16(dAh + ad + 16, aH + ao + 8);
    cpa16(dAl + ad, aL + ao);  cpa16(dAl + ad + 16, aL + ao + 8);
    const int brow = tid >> 3, bc = (tid & 7) << 4;
    const size_t bo = (size_t)brow * ldw + bc;
    const uint32_t bd = (uint32_t)(brow * GBS + bc) * 2;
    cpa16(dB + bd, w + bo);  cpa16(dB + bd + 16, w + bo + 8);
}

#define OST 29184                    // bytes per out stage: (2*128*GAS + 32*GBS)*2
#define OUT_SMEM (3*OST)

__global__ __launch_bounds__(256, 2) void out_gemm(
    const hf* __restrict__ o0h, const hf* __restrict__ o0l,
    const hf* __restrict__ o1h, const hf* __restrict__ o1l,
    const hf* __restrict__ Wo, const float* __restrict__ bo,
    float* __restrict__ out)
{
    extern __shared__ char dsc[];
    const int tid = threadIdx.x, lane = tid & 31, warp = tid >> 5;
    const int n0 = blockIdx.x * 128, m0 = blockIdx.y * 128;
    const int mrow = (warp >> 2) * 64, ncol = (warp & 3) * 32;

    const bool lower = (m0 & 2047) < 1024;
    const int nkt = lower ? 24 : 12;
    const int o1r0 = (m0 >> 11) * 1024 + (m0 & 2047);
    const uint32_t sb = sm_u32(dsc);

    float acc[4][4][4];
#pragma unroll
    for (int i = 0; i < 4; i++)
#pragma unroll
        for (int j = 0; j < 4; j++)
#pragma unroll
            for (int k = 0; k < 4; k++) acc[i][j][k] = 0.f;

    auto issue = [&](int t) {
        const hf *aH, *aL; int kc, wr;
        if (t < 12) { aH = o0h + (size_t)m0*HD;   aL = o0l + (size_t)m0*HD;
                      kc = t*32;      wr = t*32; }
        else        { aH = o1h + (size_t)o1r0*HD; aL = o1l + (size_t)o1r0*HD;
                      kc = (t-12)*32; wr = 768 + (t-12)*32; }
        uint32_t s = sb + (t % 3) * OST;
        gemm_cpa2(aH + kc, aL + kc, HD, Wo + (size_t)wr*768 + n0, 768, tid,
                  s, s + 128*GAS*2, s + 2*128*GAS*2);
        cp_commit();
    };

    issue(0); issue(1);
    for (int t = 0; t < nkt; t++) {
        if (t + 1 < nkt) cp_wait1(); else cp_wait0();
        __syncthreads();
        if (t + 2 < nkt) issue(t + 2);
        uint32_t s = sb + (t % 3) * OST;
        mma_ktile_h(s, s + 128*GAS*2, s + 2*128*GAS*2, mrow, ncol, lane, acc);
        __syncthreads();
    }

#pragma unroll
    for (int im = 0; im < 4; im++) {
        int r0g = m0 + mrow + im*16 + (lane >> 2);
#pragma unroll
        for (int f = 0; f < 4; f++) {
            int gcol = n0 + ncol + f*8 + ((lane & 3) << 1);
            float* d = acc[im][f];
#pragma unroll
            for (int hfi = 0; hfi < 2; hfi++) {
                int rr = r0g + hfi*8;
                out[(size_t)rr*768 + gcol]     = d[hfi*2]     + bo[gcol];
                out[(size_t)rr*768 + gcol + 1] = d[hfi*2 + 1] + bo[gcol + 1];
            }
        }
    }
}

// ---- flash attention: S = bf16 3-term; P·V = fp16 2-term; 3-stage KV ----
#define AS 72
#define KLB (64*AS*2)          // bytes per 64xAS region
#define SBUF (3*KLB)           // Kh, Kl, V
#define ATTN_SMEM (3*SBUF)

__global__ __launch_bounds__(256, 2) void attn_mma(
    const bf* __restrict__ qh, const bf* __restrict__ ql,
    const bf* __restrict__ kh, const bf* __restrict__ kl,
    const hf* __restrict__ v,
    hf* __restrict__ oh, hf* __restrict__ ol, int Nq)
{
    extern __shared__ char smc[];
    bf* smem = (bf*)smc;
    const int tid = threadIdx.x, lane = tid & 31, warp = tid >> 5;
    const int b = blockIdx.y / NH, h = blockIdx.y % NH;
    const int q0 = blockIdx.x * 128;
    const size_t gb = (size_t)b*Nq*HD + (size_t)h*64;
    const int mrow = warp * 16;

    // stage Q (hi at 0, lo at 128*AS), extract frags
    {
        const bf* Qh = qh + gb + (size_t)q0*HD;
        const bf* Ql = ql + gb + (size_t)q0*HD;
#pragma unroll
        for (int it = 0; it < 4; it++) {
            int i = tid + it*256, r = i >> 3, u = (i & 7)*8;
            *(uint4*)&smem[r*AS + u]          = *(const uint4*)&Qh[(size_t)r*HD + u];
            *(uint4*)&smem[128*AS + r*AS + u] = *(const uint4*)&Ql[(size_t)r*HD + u];
        }
    }
    __syncthreads();
    uint32_t qfh[4][4], qfl[4][4];
    {
        const uint32_t bh_ = sm_u32(smem), bl_ = sm_u32(smem) + 128*AS*2;
        int row = mrow + (lane & 15);
#pragma unroll
        for (int kk = 0; kk < 4; kk++) {
            uint32_t off = (uint32_t)(row*AS + kk*16 + ((lane >> 4) << 3))*2;
            ldsm4(qfh[kk], bh_ + off);
            ldsm4(qfl[kk], bl_ + off);
        }
    }
    __syncthreads();

    const uint32_t base0 = sm_u32(smc);
    auto kvload = [&](int s) {
        int kv = s * 64;
        const bf* Kh = kh + gb + (size_t)kv*HD;
        const bf* Kl = kl + gb + (size_t)kv*HD;
        const hf* V  = v  + gb + (size_t)kv*HD;
        uint32_t d = base0 + (s % 3) * SBUF;
#pragma unroll
        for (int it = 0; it < 2; it++) {
            int i = tid + it*256, r = i >> 3, u = (i & 7)*8;
            size_t go = (size_t)r*HD + u;
            uint32_t so = (uint32_t)(r*AS + u)*2;
            cpa16(d + so,         Kh + go);
            cpa16(d + KLB + so,   Kl + go);
            cpa16(d + 2*KLB + so, V  + go);
        }
        cp_commit();
    };

    float o[8][4];
#pragma unroll
    for (int f = 0; f < 8; f++)
#pragma unroll
        for (int k = 0; k < 4; k++) o[f][k] = 0.f;
    float mr0 = -1e30f, mr1 = -1e30f, lr0 = 0.f, lr1 = 0.f;

    const int S = Nq / 64;
    kvload(0); kvload(1);
    for (int t = 0; t < S; t++) {
        if (t + 1 < S) cp_wait1(); else cp_wait0();
        __syncthreads();
        if (t + 2 < S) kvload(t + 2);

        const uint32_t bb = base0 + (t % 3) * SBUF;
        const uint32_t kBH = bb, kBL = bb + KLB, vB = bb + 2*KLB;

        float s[8][4];
#pragma unroll
        for (int f = 0; f < 8; f++)
#pragma unroll
            for (int k = 0; k < 4; k++) s[f][k] = 0.f;
#pragma unroll
        for (int kk = 0; kk < 4; kk++) {
#pragma unroll
            for (int nf = 0; nf < 4; nf++) {
                uint32_t ad = (uint32_t)((nf*16 + (lane & 15))*AS + kk*16 +
                                         ((lane >> 4) << 3))*2;
                uint32_t kb[4], kl4[4];
                ldsm4(kb, kBH + ad); ldsm4(kl4, kBL + ad);
                mma_bf(s[nf*2],   qfh[kk], kb[0],  kb[2]);
                mma_bf(s[nf*2],   qfh[kk], kl4[0], kl4[2]);
                mma_bf(s[nf*2],   qfl[kk], kb[0],  kb[2]);
                mma_bf(s[nf*2+1], qfh[kk], kb[1],  kb[3]);
                mma_bf(s[nf*2+1], qfh[kk], kl4[1], kl4[3]);
                mma_bf(s[nf*2+1], qfl[kk], kb[1],  kb[3]);
            }
        }

        float mx0 = -1e30f, mx1 = -1e30f;
#pragma unroll
        for (int f = 0; f < 8; f++) {
            mx0 = fmaxf(mx0, fmaxf(s[f][0], s[f][1]));
            mx1 = fmaxf(mx1, fmaxf(s[f][2], s[f][3]));
        }
        mx0 = fmaxf(mx0, __shfl_xor_sync(~0u, mx0, 1));
        mx0 = fmaxf(mx0, __shfl_xor_sync(~0u, mx0, 2));
        mx1 = fmaxf(mx1, __shfl_xor_sync(~0u, mx1, 1));
        mx1 = fmaxf(mx1, __shfl_xor_sync(~0u, mx1, 2));
        float mn0 = fmaxf(mr0, mx0), mn1 = fmaxf(mr1, mx1);
        float c0 = __expf(mr0 - mn0), c1 = __expf(mr1 - mn1);
        float rs0 = 0.f, rs1 = 0.f;
#pragma unroll
        for (int f = 0; f < 8; f++) {
            s[f][0] = __expf(s[f][0] - mn0); s[f][1] = __expf(s[f][1] - mn0);
            s[f][2] = __expf(s[f][2] - mn1); s[f][3] = __expf(s[f][3] - mn1);
            rs0 += s[f][0] + s[f][1]; rs1 += s[f][2] + s[f][3];
        }
        rs0 += __shfl_xor_sync(~0u, rs0, 1); rs0 += __shfl_xor_sync(~0u, rs0, 2);
        rs1 += __shfl_xor_sync(~0u, rs1, 1); rs1 += __shfl_xor_sync(~0u, rs1, 2);
        lr0 = lr0*c0 + rs0; lr1 = lr1*c1 + rs1;
        mr0 = mn0; mr1 = mn1;
#pragma unroll
        for (int f = 0; f < 8; f++) {
            o[f][0] *= c0; o[f][1] *= c0; o[f][2] *= c1; o[f][3] *= c1;
        }

        // O += P @ V : P split fp16 h/l (exact), V single fp16
#pragma unroll
        for (int kk2 = 0; kk2 < 4; kk2++) {
            uint32_t pah[4], pal[4];
            {
                int f0 = kk2*2;
                float h0,l0,h1,l1;
                hsplit(s[f0][0],h0,l0);   hsplit(s[f0][1],h1,l1);
                pah[0] = hpack(h0,h1);    pal[0] = hpack(l0,l1);
                hsplit(s[f0][2],h0,l0);   hsplit(s[f0][3],h1,l1);
                pah[1] = hpack(h0,h1);    pal[1] = hpack(l0,l1);
                hsplit(s[f0+1][0],h0,l0); hsplit(s[f0+1][1],h1,l1);
                pah[2] = hpack(h0,h1);    pal[2] = hpack(l0,l1);
                hsplit(s[f0+1][2],h0,l0); hsplit(s[f0+1][3],h1,l1);
                pah[3] = hpack(h0,h1);    pal[3] = hpack(l0,l1);
            }
#pragma unroll
            for (int nf = 0; nf < 4; nf++) {
                uint32_t ad = (uint32_t)((kk2*16 + (lane & 15))*AS + nf*16 +
                                         ((lane >> 4) << 3))*2;
                uint32_t vb[4];
                ldsm4t(vb, vB + ad);
                mma_hf(o[nf*2],   pah, vb[0], vb[1]);
                mma_hf(o[nf*2],   pal, vb[0], vb[1]);
                mma_hf(o[nf*2+1], pah, vb[2], vb[3]);
                mma_hf(o[nf*2+1], pal, vb[2], vb[3]);
            }
        }
    }

    float i0 = 1.f/lr0, i1 = 1.f/lr1;
    int rg = q0 + mrow + (lane >> 2);
#pragma unroll
    for (int f = 0; f < 8; f++) {
        int cc = f*8 + ((lane & 3) << 1);
        size_t p0 = gb + (size_t)rg*HD + cc, p1 = gb + (size_t)(rg+8)*HD + cc;
        float h0,l0,h1,l1;
        hsplit(o[f][0]*i0,h0,l0); hsplit(o[f][1]*i0,h1,l1);
        *(uint32_t*)(oh + p0) = hpack(h0,h1); *(uint32_t*)(ol + p0) = hpack(l0,l1);
        hsplit(o[f][2]*i1,h0,l0); hsplit(o[f][3]*i1,h1,l1);
        *(uint32_t*)(oh + p1) = hpack(h0,h1); *(uint32_t*)(ol + p1) = hpack(l0,l1);
    }
}

__global__ void mask_kernel(float* __restrict__ out) {
    int i = blockIdx.x*blockDim.x + threadIdx.x;
    if (i < 2*N0) {
        int lvl = i >> 11, n = i & (N0 - 1);
        out[i] = (lvl == 0 || n < N1) ? 1.f : 0.f;
    }
}

extern "C" void kernel_launch(void* const* d_in, const int* in_sizes, int n_in,
                              void* d_out, int out_size)
{
    (void)in_sizes; (void)n_in; (void)out_size;
    const float* inp0 = (const float*)d_in[0];
    const float* inp1 = (const float*)d_in[1];
    const float* amask = (const float*)d_in[2];
    const float *Wq0 = (const float*)d_in[3],  *bq0 = (const float*)d_in[4];
    const float *Wk0 = (const float*)d_in[5],  *bk0 = (const float*)d_in[6];
    const float *Wv0 = (const float*)d_in[7],  *bv0 = (const float*)d_in[8];
    const float *Wq1 = (const float*)d_in[9],  *bq1 = (const float*)d_in[10];
    const float *Wk1 = (const float*)d_in[11], *bk1 = (const float*)d_in[12];
    const float *Wv1 = (const float*)d_in[13], *bv1 = (const float*)d_in[14];
    const float *Wo  = (const float*)d_in[15], *bo  = (const float*)d_in[16];
    float* out = (float*)d_out;

    bf *ih0,*il0,*ih1,*il1,*wh0,*wl0,*wh1,*wl1;
    bf *qh0,*ql0,*kh0,*kl0,*qh1,*ql1,*kh1,*kl1;
    hf *wo,*v0,*v1,*oh0,*ol0,*oh1,*ol1;
    cudaGetSymbolAddress((void**)&ih0,g_ih0); cudaGetSymbolAddress((void**)&il0,g_il0);
    cudaGetSymbolAddress((void**)&ih1,g_ih1); cudaGetSymbolAddress((void**)&il1,g_il1);
    cudaGetSymbolAddress((void**)&wh0,g_wh0); cudaGetSymbolAddress((void**)&wl0,g_wl0);
    cudaGetSymbolAddress((void**)&wh1,g_wh1); cudaGetSymbolAddress((void**)&wl1,g_wl1);
    cudaGetSymbolAddress((void**)&wo, g_wo);
    cudaGetSymbolAddress((void**)&qh0,g_qh0); cudaGetSymbolAddress((void**)&ql0,g_ql0);
    cudaGetSymbolAddress((void**)&kh0,g_kh0); cudaGetSymbolAddress((void**)&kl0,g_kl0);
    cudaGetSymbolAddress((void**)&v0, g_v0);
    cudaGetSymbolAddress((void**)&qh1,g_qh1); cudaGetSymbolAddress((void**)&ql1,g_ql1);
    cudaGetSymbolAddress((void**)&kh1,g_kh1); cudaGetSymbolAddress((void**)&kl1,g_kl1);
    cudaGetSymbolAddress((void**)&v1, g_v1);
    cudaGetSymbolAddress((void**)&oh0,g_oh0); cudaGetSymbolAddress((void**)&ol0,g_ol0);
    cudaGetSymbolAddress((void**)&oh1,g_oh1); cudaGetSymbolAddress((void**)&ol1,g_ol1);

    cudaFuncSetAttribute(qkv_gemm, cudaFuncAttributeMaxDynamicSharedMemorySize, GEMM_SMEM);
    cudaFuncSetAttribute(out_gemm, cudaFuncAttributeMaxDynamicSharedMemorySize, OUT_SMEM);
    cudaFuncSetAttribute(attn_mma, cudaFuncAttributeMaxDynamicSharedMemorySize, ATTN_SMEM);

    // prep: split inputs + weights (bf16 h/l), Wo -> fp16
    SJobs ji = {{ {inp0, ih0, il0}, {inp1, ih1, il1}, {} }};
    splitk<<<dim3(2048,1,2), 256>>>(ji, M0*768);
    SJobs j0 = {{ {Wq0, wh0, wl0},
                  {Wk0, wh0 + 768*768, wl0 + 768*768},
                  {Wv0, wh0 + 2*768*768, wl0 + 2*768*768} }};
    splitk<<<dim3(256,1,3), 256>>>(j0, 768*768);
    SJobs j1 = {{ {Wq1, wh1, wl1},
                  {Wk1, wh1 + 1536*768, wl1 + 1536*768},
                  {Wv1, wh1 + 2*1536*768, wl1 + 2*1536*768} }};
    splitk<<<dim3(512,1,3), 256>>>(j1, 1536*768);
    cvtk<<<512, 256>>>(Wo, wo, 1536*768);

    dim3 blk(256);
    qkv_gemm<<<dim3(9, 128), blk, GEMM_SMEM>>>(ih0, il0, 768, wh0, wl0, 0,
        bq0, bk0, bv0, qh0, ql0, kh0, kl0, v0, amask, N0);
    qkv_gemm<<<dim3(9, 64), blk, GEMM_SMEM>>>(ih1, il1, 1536, wh1, wl1, 384,
        bq1 + 384, bk1 + 384, bv1 + 384, qh1, ql1, kh1, kl1, v1, amask, N1);

    attn_mma<<<dim3(N0/128, B*NH), blk, ATTN_SMEM>>>(qh0, ql0, kh0, kl0, v0, oh0, ol0, N0);
    attn_mma<<<dim3(N1/128, B*NH), blk, ATTN_SMEM>>>(qh1, ql1, kh1, kl1, v1, oh1, ol1, N1);

    out_gemm<<<dim3(6, 128), blk, OUT_SMEM>>>(oh0, ol0, oh1, ol1, wo, bo, out);
    mask_kernel<<<16, 256>>>(out + OUT_ELEMS);
}

// round 12
// speedup vs baseline: 5.6376x; 1.0065x over previous
#include <cuda_runtime.h>
#include <cuda_bf16.h>
#include <cuda_fp16.h>
#include <stdint.h>
typedef __nv_bfloat16 bf;
typedef __half hf;

#define B 8
#define N0 2048
#define N1 1024
#define HD 384
#define NH 6
#define M0 (B*N0)
#define M1 (B*N1)
#define OUT_ELEMS ((size_t)B*N0*768)

__device__ __align__(128) bf g_ih0[M0*768],  g_il0[M0*768];
__device__ __align__(128) bf g_ih1[M1*1536], g_il1[M1*1536];
__device__ __align__(128) hf g_if0[M0*768],  g_if1[M1*1536];       // fp16 single inputs
__device__ __align__(128) bf g_wh0[2][768*768],  g_wl0[2][768*768];   // Wq0, Wk0 h/l
__device__ __align__(128) bf g_wh1[2][1536*768], g_wl1[2][1536*768];  // Wq1, Wk1 h/l
__device__ __align__(128) hf g_wv0f[768*768], g_wv1f[1536*768];    // Wv fp16 single
__device__ __align__(128) hf g_wo[1536*768];                       // Wo fp16 single
__device__ __align__(128) bf g_qh0[M0*HD], g_ql0[M0*HD], g_kh0[M0*HD], g_kl0[M0*HD];
__device__ __align__(128) hf g_v0[M0*HD];
__device__ __align__(128) bf g_qh1[M1*HD], g_ql1[M1*HD], g_kh1[M1*HD], g_kl1[M1*HD];
__device__ __align__(128) hf g_v1[M1*HD];
__device__ __align__(128) hf g_oh0[M0*HD], g_ol0[M0*HD], g_oh1[M1*HD], g_ol1[M1*HD];

__device__ __forceinline__ uint32_t sm_u32(const void* p) {
    return (uint32_t)__cvta_generic_to_shared(p);
}
__device__ __forceinline__ void ldsm4(uint32_t r[4], uint32_t a) {
    asm volatile("ldmatrix.sync.aligned.m8n8.x4.shared.b16 {%0,%1,%2,%3}, [%4];"
        : "=r"(r[0]), "=r"(r[1]), "=r"(r[2]), "=r"(r[3]) : "r"(a));
}
__device__ __forceinline__ void ldsm4t(uint32_t r[4], uint32_t a) {
    asm volatile("ldmatrix.sync.aligned.m8n8.x4.trans.shared.b16 {%0,%1,%2,%3}, [%4];"
        : "=r"(r[0]), "=r"(r[1]), "=r"(r[2]), "=r"(r[3]) : "r"(a));
}
__device__ __forceinline__ void mma_bf(float d[4], const uint32_t a[4],
                                       uint32_t b0, uint32_t b1) {
    asm volatile("mma.sync.aligned.m16n8k16.row.col.f32.bf16.bf16.f32 "
        "{%0,%1,%2,%3}, {%4,%5,%6,%7}, {%8,%9}, {%0,%1,%2,%3};"
        : "+f"(d[0]), "+f"(d[1]), "+f"(d[2]), "+f"(d[3])
        : "r"(a[0]), "r"(a[1]), "r"(a[2]), "r"(a[3]), "r"(b0), "r"(b1));
}
__device__ __forceinline__ void mma_hf(float d[4], const uint32_t a[4],
                                       uint32_t b0, uint32_t b1) {
    asm volatile("mma.sync.aligned.m16n8k16.row.col.f32.f16.f16.f32 "
        "{%0,%1,%2,%3}, {%4,%5,%6,%7}, {%8,%9}, {%0,%1,%2,%3};"
        : "+f"(d[0]), "+f"(d[1]), "+f"(d[2]), "+f"(d[3])
        : "r"(a[0]), "r"(a[1]), "r"(a[2]), "r"(a[3]), "r"(b0), "r"(b1));
}
__device__ __forceinline__ uint32_t bpack(float lo, float hi) {
    __nv_bfloat162 t = __floats2bfloat162_rn(lo, hi);
    return *reinterpret_cast<uint32_t*>(&t);
}
__device__ __forceinline__ void fsplit(float x, float& h, float& l) {
    bf b = __float2bfloat16(x);
    h = __bfloat162float(b);
    l = x - h;
}
__device__ __forceinline__ uint32_t hpack(float lo, float hi) {
    __half2 t = __floats2half2_rn(lo, hi);
    return *reinterpret_cast<uint32_t*>(&t);
}
__device__ __forceinline__ void hsplit(float x, float& h, float& l) {
    hf b = __float2half_rn(x);
    h = __half2float(b);
    l = x - h;
}
__device__ __forceinline__ void cpa16(uint32_t d, const void* s) {
    asm volatile("cp.async.cg.shared.global [%0], [%1], 16;" :: "r"(d), "l"(s));
}
__device__ __forceinline__ void cp_commit() { asm volatile("cp.async.commit_group;"); }
__device__ __forceinline__ void cp_wait0()  { asm volatile("cp.async.wait_group 0;"); }
__device__ __forceinline__ void cp_wait1()  { asm volatile("cp.async.wait_group 1;"); }

// ---- prep kernels ----
struct SJob  { const float* s; bf* h; bf* l; };
struct SJobs { SJob j[2]; };
__global__ void splitk(SJobs js, int n) {
    SJob J = js.j[blockIdx.z];
    for (int i = (blockIdx.x*256 + threadIdx.x)*4; i < n; i += gridDim.x*256*4) {
        float4 v = *(const float4*)(J.s + i);
        float h0,l0,h1,l1,h2,l2,h3,l3;
        fsplit(v.x,h0,l0); fsplit(v.y,h1,l1); fsplit(v.z,h2,l2); fsplit(v.w,h3,l3);
        *(uint2*)(J.h + i) = make_uint2(bpack(h0,h1), bpack(h2,h3));
        *(uint2*)(J.l + i) = make_uint2(bpack(l0,l1), bpack(l2,l3));
    }
}
struct S3Job  { const float* s; bf* h; bf* l; hf* f; };
struct S3Jobs { S3Job j[2]; };
__global__ void split3(S3Jobs js, int n) {
    S3Job J = js.j[blockIdx.z];
    for (int i = (blockIdx.x*256 + threadIdx.x)*4; i < n; i += gridDim.x*256*4) {
        float4 v = *(const float4*)(J.s + i);
        float h0,l0,h1,l1,h2,l2,h3,l3;
        fsplit(v.x,h0,l0); fsplit(v.y,h1,l1); fsplit(v.z,h2,l2); fsplit(v.w,h3,l3);
        *(uint2*)(J.h + i) = make_uint2(bpack(h0,h1), bpack(h2,h3));
        *(uint2*)(J.l + i) = make_uint2(bpack(l0,l1), bpack(l2,l3));
        *(uint2*)(J.f + i) = make_uint2(hpack(v.x,v.y), hpack(v.z,v.w));
    }
}
__global__ void cvtk(const float* __restrict__ s, hf* __restrict__ d, int n) {
    for (int i = (blockIdx.x*256 + threadIdx.x)*4; i < n; i += gridDim.x*256*4) {
        float4 v = *(const float4*)(s + i);
        *(uint2*)(d + i) = make_uint2(hpack(v.x, v.y), hpack(v.z, v.w));
    }
}

// ---- shared tile constants ----
#define GAS 40
#define GBS 136
#define GEMM_SMEM ((2*128*GAS + 2*32*GBS) * 2 * 2)

// bf16 3-term ktile
__device__ __forceinline__ void mma_ktile(
    uint32_t aBH, uint32_t aBL, uint32_t bBH, uint32_t bBL,
    int mrow, int ncol, int lane, float acc[4][4][4])
{
#pragma unroll
    for (int kk = 0; kk < 32; kk += 16) {
        uint32_t ah[4][4], al[4][4];
#pragma unroll
        for (int im = 0; im < 4; im++) {
            uint32_t ad = (uint32_t)((mrow + im*16 + (lane & 15)) * GAS +
                                     kk + ((lane >> 4) << 3)) * 2;
            ldsm4(ah[im], aBH + ad);
            ldsm4(al[im], aBL + ad);
        }
#pragma unroll
        for (int nf = 0; nf < 2; nf++) {
            uint32_t bd = (uint32_t)((kk + (lane & 15)) * GBS + ncol +
                                     nf*16 + ((lane >> 4) << 3)) * 2;
            uint32_t bh4[4], bl4[4];
            ldsm4t(bh4, bBH + bd);
            ldsm4t(bl4, bBL + bd);
#pragma unroll
            for (int im = 0; im < 4; im++) {
#pragma unroll
                for (int j = 0; j < 2; j++) {
                    float* d = acc[im][nf*2 + j];
                    mma_bf(d, ah[im], bh4[2*j], bh4[2*j+1]);
                    mma_bf(d, ah[im], bl4[2*j], bl4[2*j+1]);
                    mma_bf(d, al[im], bh4[2*j], bh4[2*j+1]);
                }
            }
        }
    }
}
__device__ __forceinline__ void gemm_cpa(
    const bf* aH, const bf* aL, int lda,
    const bf* wH, const bf* wL, int ldw,
    int tid, uint32_t dAh, uint32_t dAl, uint32_t dBh, uint32_t dBl)
{
    const int arow = tid >> 1, ak = (tid & 1) << 4;
    const size_t ao = (size_t)arow * lda + ak;
    const uint32_t ad = (uint32_t)(arow * GAS + ak) * 2;
    cpa16(dAh + ad, aH + ao);  cpa16(dAh + ad + 16, aH + ao + 8);
    cpa16(dAl + ad, aL + ao);  cpa16(dAl + ad + 16, aL + ao + 8);
    const int brow = tid >> 3, bc = (tid & 7) << 4;
    const size_t bo = (size_t)brow * ldw + bc;
    const uint32_t bd = (uint32_t)(brow * GBS + bc) * 2;
    cpa16(dBh + bd, wH + bo);  cpa16(dBh + bd + 16, wH + bo + 8);
    cpa16(dBl + bd, wL + bo);  cpa16(dBl + bd + 16, wL + bo + 8);
}

// ---- Q/K projection (bf16 3-term): grid (6, M/128), sel = bx/3 in {0,1} ----
__global__ __launch_bounds__(256, 2) void qkv_gemm(
    const bf* __restrict__ Ah, const bf* __restrict__ Al, int K,
    const bf* __restrict__ W0h, const bf* __restrict__ W0l, int wOff,
    const float* __restrict__ bq, const float* __restrict__ bk,
    bf* qh, bf* ql, bf* kh, bf* kl,
    const float* __restrict__ mask, int nseq)
{
    extern __shared__ bf ds[];
    bf* Ahs = ds;
    bf* Als = Ahs + 2*128*GAS;
    bf* Bhs = Als + 2*128*GAS;
    bf* Bls = Bhs + 2*32*GBS;

    const int tid = threadIdx.x, lane = tid & 31, warp = tid >> 5;
    const int sel = blockIdx.x / 3, n0 = (blockIdx.x % 3) * 128;
    const int m0 = blockIdx.y * 128;
    const int mrow = (warp >> 2) * 64, ncol = (warp & 3) * 32;

    const bf* Wh = W0h + (size_t)sel * K * 768 + wOff + n0;
    const bf* Wl = W0l + (size_t)sel * K * 768 + wOff + n0;
    const float* bias = (sel == 0) ? bq : bk;
    bf* Ch = (sel == 0) ? qh : kh;
    bf* Cl = (sel == 0) ? ql : kl;
    const bf* aH = Ah + (size_t)m0 * K;
    const bf* aL = Al + (size_t)m0 * K;

    float acc[4][4][4];
#pragma unroll
    for (int i = 0; i < 4; i++)
#pragma unroll
        for (int j = 0; j < 4; j++)
#pragma unroll
            for (int k = 0; k < 4; k++) acc[i][j][k] = 0.f;

    gemm_cpa(aH, aL, K, Wh, Wl, 768, tid,
             sm_u32(Ahs), sm_u32(Als), sm_u32(Bhs), sm_u32(Bls));
    cp_commit();

    int buf = 0;
    for (int k0 = 0; k0 < K; k0 += 32) {
        cp_wait0();
        __syncthreads();
        if (k0 + 32 < K) {
            int nb = buf ^ 1;
            gemm_cpa(aH + k0 + 32, aL + k0 + 32, K,
                     Wh + (size_t)(k0 + 32)*768, Wl + (size_t)(k0 + 32)*768, 768, tid,
                     sm_u32(Ahs + nb*128*GAS), sm_u32(Als + nb*128*GAS),
                     sm_u32(Bhs + nb*32*GBS),  sm_u32(Bls + nb*32*GBS));
            cp_commit();
        }
        mma_ktile(sm_u32(Ahs + buf*128*GAS), sm_u32(Als + buf*128*GAS),
                  sm_u32(Bhs + buf*32*GBS),  sm_u32(Bls + buf*32*GBS),
                  mrow, ncol, lane, acc);
        buf ^= 1;
    }

#pragma unroll
    for (int im = 0; im < 4; im++) {
        int r0g = m0 + mrow + im*16 + (lane >> 2);
#pragma unroll
        for (int f = 0; f < 4; f++) {
            int gcol = n0 + ncol + f*8 + ((lane & 3) << 1);
            float* d = acc[im][f];
#pragma unroll
            for (int hfi = 0; hfi < 2; hfi++) {
                int rr = r0g + hfi*8;
                float x0 = d[hfi*2]     + bias[gcol];
                float x1 = d[hfi*2 + 1] + bias[gcol + 1];
                if (sel == 0) {
                    const float* mk = mask + (rr / nseq) * 64;
                    x0 = x0*0.125f + mk[gcol & 63];
                    x1 = x1*0.125f + mk[(gcol + 1) & 63];
                }
                size_t o = (size_t)rr * HD + gcol;
                float h0,l0,h1,l1;
                fsplit(x0,h0,l0); fsplit(x1,h1,l1);
                *(uint32_t*)(Ch + o) = bpack(h0,h1);
                *(uint32_t*)(Cl + o) = bpack(l0,l1);
            }
        }
    }
}

// ---- fp16 1-term ktile (v_gemm) ----
__device__ __forceinline__ void mma_ktile_h1(
    uint32_t aB, uint32_t bB, int mrow, int ncol, int lane, float acc[4][4][4])
{
#pragma unroll
    for (int kk = 0; kk < 32; kk += 16) {
        uint32_t ah[4][4];
#pragma unroll
        for (int im = 0; im < 4; im++) {
            uint32_t ad = (uint32_t)((mrow + im*16 + (lane & 15)) * GAS +
                                     kk + ((lane >> 4) << 3)) * 2;
            ldsm4(ah[im], aB + ad);
        }
#pragma unroll
        for (int nf = 0; nf < 2; nf++) {
            uint32_t bd = (uint32_t)((kk + (lane & 15)) * GBS + ncol +
                                     nf*16 + ((lane >> 4) << 3)) * 2;
            uint32_t b4[4];
            ldsm4t(b4, bB + bd);
#pragma unroll
            for (int im = 0; im < 4; im++) {
#pragma unroll
                for (int j = 0; j < 2; j++)
                    mma_hf(acc[im][nf*2 + j], ah[im], b4[2*j], b4[2*j+1]);
            }
        }
    }
}

#define VST ((128*GAS + 32*GBS) * 2)   // 18944 B per stage
#define V_SMEM (3*VST)

// ---- V projection (fp16 x fp16, 1 MMA/k16): grid (3, M/128) ----
__global__ __launch_bounds__(256, 2) void v_gemm(
    const hf* __restrict__ A, int K,
    const hf* __restrict__ Wv, int wOff,
    const float* __restrict__ bv, hf* __restrict__ v)
{
    extern __shared__ char dsc[];
    const int tid = threadIdx.x, lane = tid & 31, warp = tid >> 5;
    const int n0 = blockIdx.x * 128, m0 = blockIdx.y * 128;
    const int mrow = (warp >> 2) * 64, ncol = (warp & 3) * 32;
    const uint32_t sb = sm_u32(dsc);

    float acc[4][4][4];
#pragma unroll
    for (int i = 0; i < 4; i++)
#pragma unroll
        for (int j = 0; j < 4; j++)
#pragma unroll
            for (int k = 0; k < 4; k++) acc[i][j][k] = 0.f;

    auto issue = [&](int t) {
        uint32_t s = sb + (t % 3) * VST;
        const hf* a = A + (size_t)m0 * K + t*32;
        const hf* w = Wv + (size_t)(t*32) * 768 + wOff + n0;
        const int arow = tid >> 1, ak = (tid & 1) << 4;
        const size_t ao = (size_t)arow * K + ak;
        const uint32_t ad = (uint32_t)(arow * GAS + ak) * 2;
        cpa16(s + ad, a + ao);  cpa16(s + ad + 16, a + ao + 8);
        const int brow = tid >> 3, bc = (tid & 7) << 4;
        const size_t bo = (size_t)brow * 768 + bc;
        const uint32_t bd = (uint32_t)(brow * GBS + bc) * 2 + 128*GAS*2;
        cpa16(s + bd, w + bo);  cpa16(s + bd + 16, w + bo + 8);
        cp_commit();
    };

    const int nkt = K / 32;
    issue(0); issue(1);
    for (int t = 0; t < nkt; t++) {
        if (t + 1 < nkt) cp_wait1(); else cp_wait0();
        __syncthreads();
        if (t + 2 < nkt) issue(t + 2);
        uint32_t s = sb + (t % 3) * VST;
        mma_ktile_h1(s, s + 128*GAS*2, mrow, ncol, lane, acc);
        __syncthreads();
    }

#pragma unroll
    for (int im = 0; im < 4; im++) {
        int r0g = m0 + mrow + im*16 + (lane >> 2);
#pragma unroll
        for (int f = 0; f < 4; f++) {
            int gcol = n0 + ncol + f*8 + ((lane & 3) << 1);
            float* d = acc[im][f];
#pragma unroll
            for (int hfi = 0; hfi < 2; hfi++) {
                int rr = r0g + hfi*8;
                *(uint32_t*)(v + (size_t)rr*HD + gcol) =
                    hpack(d[hfi*2] + bv[gcol], d[hfi*2 + 1] + bv[gcol + 1]);
            }
        }
    }
}

// ---- fp16 2-term ktile (out_gemm) ----
__device__ __forceinline__ void mma_ktile_h(
    uint32_t aBH, uint32_t aBL, uint32_t bB,
    int mrow, int ncol, int lane, float acc[4][4][4])
{
#pragma unroll
    for (int kk = 0; kk < 32; kk += 16) {
        uint32_t ah[4][4], al[4][4];
#pragma unroll
        for (int im = 0; im < 4; im++) {
            uint32_t ad = (uint32_t)((mrow + im*16 + (lane & 15)) * GAS +
                                     kk + ((lane >> 4) << 3)) * 2;
            ldsm4(ah[im], aBH + ad);
            ldsm4(al[im], aBL + ad);
        }
#pragma unroll
        for (int nf = 0; nf < 2; nf++) {
            uint32_t bd = (uint32_t)((kk + (lane & 15)) * GBS + ncol +
                                     nf*16 + ((lane >> 4) << 3)) * 2;
            uint32_t b4[4];
            ldsm4t(b4, bB + bd);
#pragma unroll
            for (int im = 0; im < 4; im++) {
#pragma unroll
                for (int j = 0; j < 2; j++) {
                    float* d = acc[im][nf*2 + j];
                    mma_hf(d, ah[im], b4[2*j], b4[2*j+1]);
                    mma_hf(d, al[im], b4[2*j], b4[2*j+1]);
                }
            }
        }
    }
}
__device__ __forceinline__ void gemm_cpa2(
    const hf* aH, const hf* aL, int lda,
    const hf* w, int ldw, int tid,
    uint32_t dAh, uint32_t dAl, uint32_t dB)
{
    const int arow = tid >> 1, ak = (tid & 1) << 4;
    const size_t ao = (size_t)arow * lda + ak;
    const uint32_t ad = (uint32_t)(arow * GAS + ak) * 2;
    cpa16(dAh + ad, aH + ao);  cpa16(dAh + ad + 16, aH + ao + 8);
    cpa16(dAl + ad, aL + ao);  cpa16(dAl + ad + 16, aL + ao + 8);
    const int brow = tid >> 3, bc = (tid & 7) << 4;
    const size_t bo = (size_t)brow * ldw + bc;
    const uint32_t bd = (uint32_t)(brow * GBS + bc) * 2;
    cpa16(dB + bd, w + bo);  cpa16(dB + bd + 16, w + bo + 8);
}

#define OST 29184
#define OUT_SMEM (3*OST)

__global__ __launch_bounds__(256, 2) void out_gemm(
    const hf* __restrict__ o0h, const hf* __restrict__ o0l,
    const hf* __restrict__ o1h, const hf* __restrict__ o1l,
    const hf* __restrict__ Wo, const float* __restrict__ bo,
    float* __restrict__ out)
{
    extern __shared__ char dsc[];
    const int tid = threadIdx.x, lane = tid & 31, warp = tid >> 5;
    const int n0 = blockIdx.x * 128, m0 = blockIdx.y * 128;
    const int mrow = (warp >> 2) * 64, ncol = (warp & 3) * 32;

    const bool lower = (m0 & 2047) < 1024;
    const int nkt = lower ? 24 : 12;
    const int o1r0 = (m0 >> 11) * 1024 + (m0 & 2047);
    const uint32_t sb = sm_u32(dsc);

    float acc[4][4][4];
#pragma unroll
    for (int i = 0; i < 4; i++)
#pragma unroll
        for (int j = 0; j < 4; j++)
#pragma unroll
            for (int k = 0; k < 4; k++) acc[i][j][k] = 0.f;

    auto issue = [&](int t) {
        const hf *aH, *aL; int kc, wr;
        if (t < 12) { aH = o0h + (size_t)m0*HD;   aL = o0l + (size_t)m0*HD;
                      kc = t*32;      wr = t*32; }
        else        { aH = o1h + (size_t)o1r0*HD; aL = o1l + (size_t)o1r0*HD;
                      kc = (t-12)*32; wr = 768 + (t-12)*32; }
        uint32_t s = sb + (t % 3) * OST;
        gemm_cpa2(aH + kc, aL + kc, HD, Wo + (size_t)wr*768 + n0, 768, tid,
                  s, s + 128*GAS*2, s + 2*128*GAS*2);
        cp_commit();
    };

    issue(0); issue(1);
    for (int t = 0; t < nkt; t++) {
        if (t + 1 < nkt) cp_wait1(); else cp_wait0();
        __syncthreads();
        if (t + 2 < nkt) issue(t + 2);
        uint32_t s = sb + (t % 3) * OST;
        mma_ktile_h(s, s + 128*GAS*2, s + 2*128*GAS*2, mrow, ncol, lane, acc);
        __syncthreads();
    }

#pragma unroll
    for (int im = 0; im < 4; im++) {
        int r0g = m0 + mrow + im*16 + (lane >> 2);
#pragma unroll
        for (int f = 0; f < 4; f++) {
            int gcol = n0 + ncol + f*8 + ((lane & 3) << 1);
            float* d = acc[im][f];
#pragma unroll
            for (int hfi = 0; hfi < 2; hfi++) {
                int rr = r0g + hfi*8;
                out[(size_t)rr*768 + gcol]     = d[hfi*2]     + bo[gcol];
                out[(size_t)rr*768 + gcol + 1] = d[hfi*2 + 1] + bo[gcol + 1];
            }
        }
    }
}

// ---- flash attention: S bf16 3-term; P·V fp16 2-term; 3-stage KV ----
#define AS 72
#define KLB (64*AS*2)
#define SBUF (3*KLB)
#define ATTN_SMEM (3*SBUF)

__global__ __launch_bounds__(256, 2) void attn_mma(
    const bf* __restrict__ qh, const bf* __restrict__ ql,
    const bf* __restrict__ kh, const bf* __restrict__ kl,
    const hf* __restrict__ v,
    hf* __restrict__ oh, hf* __restrict__ ol, int Nq)
{
    extern __shared__ char smc[];
    bf* smem = (bf*)smc;
    const int tid = threadIdx.x, lane = tid & 31, warp = tid >> 5;
    const int b = blockIdx.y / NH, h = blockIdx.y % NH;
    const int q0 = blockIdx.x * 128;
    const size_t gb = (size_t)b*Nq*HD + (size_t)h*64;
    const int mrow = warp * 16;

    {
        const bf* Qh = qh + gb + (size_t)q0*HD;
        const bf* Ql = ql + gb + (size_t)q0*HD;
#pragma unroll
        for (int it = 0; it < 4; it++) {
            int i = tid + it*256, r = i >> 3, u = (i & 7)*8;
            *(uint4*)&smem[r*AS + u]          = *(const uint4*)&Qh[(size_t)r*HD + u];
            *(uint4*)&smem[128*AS + r*AS + u] = *(const uint4*)&Ql[(size_t)r*HD + u];
        }
    }
    __syncthreads();
    uint32_t qfh[4][4], qfl[4][4];
    {
        const uint32_t bh_ = sm_u32(smem), bl_ = sm_u32(smem) + 128*AS*2;
        int row = mrow + (lane & 15);
#pragma unroll
        for (int kk = 0; kk < 4; kk++) {
            uint32_t off = (uint32_t)(row*AS + kk*16 + ((lane >> 4) << 3))*2;
            ldsm4(qfh[kk], bh_ + off);
            ldsm4(qfl[kk], bl_ + off);
        }
    }
    __syncthreads();

    const uint32_t base0 = sm_u32(smc);
    auto kvload = [&](int s) {
        int kv = s * 64;
        const bf* Kh = kh + gb + (size_t)kv*HD;
        const bf* Kl = kl + gb + (size_t)kv*HD;
        const hf* V  = v  + gb + (size_t)kv*HD;
        uint32_t d = base0 + (s % 3) * SBUF;
#pragma unroll
        for (int it = 0; it < 2; it++) {
            int i = tid + it*256, r = i >> 3, u = (i & 7)*8;
            size_t go = (size_t)r*HD + u;
            uint32_t so = (uint32_t)(r*AS + u)*2;
            cpa16(d + so,         Kh + go);
            cpa16(d + KLB + so,   Kl + go);
            cpa16(d + 2*KLB + so, V  + go);
        }
        cp_commit();
    };

    float o[8][4];
#pragma unroll
    for (int f = 0; f < 8; f++)
#pragma unroll
        for (int k = 0; k < 4; k++) o[f][k] = 0.f;
    float mr0 = -1e30f, mr1 = -1e30f, lr0 = 0.f, lr1 = 0.f;

    const int S = Nq / 64;
    kvload(0); kvload(1);
    for (int t = 0; t < S; t++) {
        if (t + 1 < S) cp_wait1(); else cp_wait0();
        __syncthreads();
        if (t + 2 < S) kvload(t + 2);

        const uint32_t bb = base0 + (t % 3) * SBUF;
        const uint32_t kBH = bb, kBL = bb + KLB, vB = bb + 2*KLB;

        float s[8][4];
#pragma unroll
        for (int f = 0; f < 8; f++)
#pragma unroll
            for (int k = 0; k < 4; k++) s[f][k] = 0.f;
#pragma unroll
        for (int kk = 0; kk < 4; kk++) {
#pragma unroll
            for (int nf = 0; nf < 4; nf++) {
                uint32_t ad = (uint32_t)((nf*16 + (lane & 15))*AS + kk*16 +
                                         ((lane >> 4) << 3))*2;
                uint32_t kb[4], kl4[4];
                ldsm4(kb, kBH + ad); ldsm4(kl4, kBL + ad);
                mma_bf(s[nf*2],   qfh[kk], kb[0],  kb[2]);
                mma_bf(s[nf*2],   qfh[kk], kl4[0], kl4[2]);
                mma_bf(s[nf*2],   qfl[kk], kb[0],  kb[2]);
                mma_bf(s[nf*2+1], qfh[kk], kb[1],  kb[3]);
                mma_bf(s[nf*2+1], qfh[kk], kl4[1], kl4[3]);
                mma_bf(s[nf*2+1], qfl[kk], kb[1],  kb[3]);
            }
        }

        float mx0 = -1e30f, mx1 = -1e30f;
#pragma unroll
        for (int f = 0; f < 8; f++) {
            mx0 = fmaxf(mx0, fmaxf(s[f][0], s[f][1]));
            mx1 = fmaxf(mx1, fmaxf(s[f][2], s[f][3]));
        }
        mx0 = fmaxf(mx0, __shfl_xor_sync(~0u, mx0, 1));
        mx0 = fmaxf(mx0, __shfl_xor_sync(~0u, mx0, 2));
        mx1 = fmaxf(mx1, __shfl_xor_sync(~0u, mx1, 1));
        mx1 = fmaxf(mx1, __shfl_xor_sync(~0u, mx1, 2));
        float mn0 = fmaxf(mr0, mx0), mn1 = fmaxf(mr1, mx1);
        float c0 = __expf(mr0 - mn0), c1 = __expf(mr1 - mn1);
        float rs0 = 0.f, rs1 = 0.f;
#pragma unroll
        for (int f = 0; f < 8; f++) {
            s[f][0] = __expf(s[f][0] - mn0); s[f][1] = __expf(s[f][1] - mn0);
            s[f][2] = __expf(s[f][2] - mn1); s[f][3] = __expf(s[f][3] - mn1);
            rs0 += s[f][0] + s[f][1]; rs1 += s[f][2] + s[f][3];
        }
        rs0 += __shfl_xor_sync(~0u, rs0, 1); rs0 += __shfl_xor_sync(~0u, rs0, 2);
        rs1 += __shfl_xor_sync(~0u, rs1, 1); rs1 += __shfl_xor_sync(~0u, rs1, 2);
        lr0 = lr0*c0 + rs0; lr1 = lr1*c1 + rs1;
        mr0 = mn0; mr1 = mn1;
#pragma unroll
        for (int f = 0; f < 8; f++) {
            o[f][0] *= c0; o[f][1] *= c0; o[f][2] *= c1; o[f][3] *= c1;
        }

#pragma unroll
        for (int kk2 = 0; kk2 < 4; kk2++) {
            uint32_t pah[4], pal[4];
            {
                int f0 = kk2*2;
                float h0,l0,h1,l1;
                hsplit(s[f0][0],h0,l0);   hsplit(s[f0][1],h1,l1);
                pah[0] = hpack(h0,h1);    pal[0] = hpack(l0,l1);
                hsplit(s[f0][2],h0,l0);   hsplit(s[f0][3],h1,l1);
                pah[1] = hpack(h0,h1);    pal[1] = hpack(l0,l1);
                hsplit(s[f0+1][0],h0,l0); hsplit(s[f0+1][1],h1,l1);
                pah[2] = hpack(h0,h1);    pal[2] = hpack(l0,l1);
                hsplit(s[f0+1][2],h0,l0); hsplit(s[f0+1][3],h1,l1);
                pah[3] = hpack(h0,h1);    pal[3] = hpack(l0,l1);
            }
#pragma unroll
            for (int nf = 0; nf < 4; nf++) {
                uint32_t ad = (uint32_t)((kk2*16 + (lane & 15))*AS + nf*16 +
                                         ((lane >> 4) << 3))*2;
                uint32_t vb[4];
                ldsm4t(vb, vB + ad);
                mma_hf(o[nf*2],   pah, vb[0], vb[1]);
                mma_hf(o[nf*2],   pal, vb[0], vb[1]);
                mma_hf(o[nf*2+1], pah, vb[2], vb[3]);
                mma_hf(o[nf*2+1], pal, vb[2], vb[3]);
            }
        }
    }

    float i0 = 1.f/lr0, i1 = 1.f/lr1;
    int rg = q0 + mrow + (lane >> 2);
#pragma unroll
    for (int f = 0; f < 8; f++) {
        int cc = f*8 + ((lane & 3) << 1);
        size_t p0 = gb + (size_t)rg*HD + cc, p1 = gb + (size_t)(rg+8)*HD + cc;
        float h0,l0,h1,l1;
        hsplit(o[f][0]*i0,h0,l0); hsplit(o[f][1]*i0,h1,l1);
        *(uint32_t*)(oh + p0) = hpack(h0,h1); *(uint32_t*)(ol + p0) = hpack(l0,l1);
        hsplit(o[f][2]*i1,h0,l0); hsplit(o[f][3]*i1,h1,l1);
        *(uint32_t*)(oh + p1) = hpack(h0,h1); *(uint32_t*)(ol + p1) = hpack(l0,l1);
    }
}

__global__ void mask_kernel(float* __restrict__ out) {
    int i = blockIdx.x*blockDim.x + threadIdx.x;
    if (i < 2*N0) {
        int lvl = i >> 11, n = i & (N0 - 1);
        out[i] = (lvl == 0 || n < N1) ? 1.f : 0.f;
    }
}

extern "C" void kernel_launch(void* const* d_in, const int* in_sizes, int n_in,
                              void* d_out, int out_size)
{
    (void)in_sizes; (void)n_in; (void)out_size;
    const float* inp0 = (const float*)d_in[0];
    const float* inp1 = (const float*)d_in[1];
    const float* amask = (const float*)d_in[2];
    const float *Wq0 = (const float*)d_in[3],  *bq0 = (const float*)d_in[4];
    const float *Wk0 = (const float*)d_in[5],  *bk0 = (const float*)d_in[6];
    const float *Wv0 = (const float*)d_in[7],  *bv0 = (const float*)d_in[8];
    const float *Wq1 = (const float*)d_in[9],  *bq1 = (const float*)d_in[10];
    const float *Wk1 = (const float*)d_in[11], *bk1 = (const float*)d_in[12];
    const float *Wv1 = (const float*)d_in[13], *bv1 = (const float*)d_in[14];
    const float *Wo  = (const float*)d_in[15], *bo  = (const float*)d_in[16];
    float* out = (float*)d_out;

    bf *ih0,*il0,*ih1,*il1,*wh0,*wl0,*wh1,*wl1;
    bf *qh0,*ql0,*kh0,*kl0,*qh1,*ql1,*kh1,*kl1;
    hf *if0,*if1,*wv0f,*wv1f,*wo,*v0,*v1,*oh0,*ol0,*oh1,*ol1;
    cudaGetSymbolAddress((void**)&ih0,g_ih0); cudaGetSymbolAddress((void**)&il0,g_il0);
    cudaGetSymbolAddress((void**)&ih1,g_ih1); cudaGetSymbolAddress((void**)&il1,g_il1);
    cudaGetSymbolAddress((void**)&if0,g_if0); cudaGetSymbolAddress((void**)&if1,g_if1);
    cudaGetSymbolAddress((void**)&wh0,g_wh0); cudaGetSymbolAddress((void**)&wl0,g_wl0);
    cudaGetSymbolAddress((void**)&wh1,g_wh1); cudaGetSymbolAddress((void**)&wl1,g_wl1);
    cudaGetSymbolAddress((void**)&wv0f,g_wv0f); cudaGetSymbolAddress((void**)&wv1f,g_wv1f);
    cudaGetSymbolAddress((void**)&wo, g_wo);
    cudaGetSymbolAddress((void**)&qh0,g_qh0); cudaGetSymbolAddress((void**)&ql0,g_ql0);
    cudaGetSymbolAddress((void**)&kh0,g_kh0); cudaGetSymbolAddress((void**)&kl0,g_kl0);
    cudaGetSymbolAddress((void**)&v0, g_v0);
    cudaGetSymbolAddress((void**)&qh1,g_qh1); cudaGetSymbolAddress((void**)&ql1,g_ql1);
    cudaGetSymbolAddress((void**)&kh1,g_kh1); cudaGetSymbolAddress((void**)&kl1,g_kl1);
    cudaGetSymbolAddress((void**)&v1, g_v1);
    cudaGetSymbolAddress((void**)&oh0,g_oh0); cudaGetSymbolAddress((void**)&ol0,g_ol0);
    cudaGetSymbolAddress((void**)&oh1,g_oh1); cudaGetSymbolAddress((void**)&ol1,g_ol1);

    cudaFuncSetAttribute(qkv_gemm, cudaFuncAttributeMaxDynamicSharedMemorySize, GEMM_SMEM);
    cudaFuncSetAttribute(v_gemm,   cudaFuncAttributeMaxDynamicSharedMemorySize, V_SMEM);
    cudaFuncSetAttribute(out_gemm, cudaFuncAttributeMaxDynamicSharedMemorySize, OUT_SMEM);
    cudaFuncSetAttribute(attn_mma, cudaFuncAttributeMaxDynamicSharedMemorySize, ATTN_SMEM);

    // prep
    S3Jobs j3 = {{ {inp0, ih0, il0, if0}, {inp1, ih1, il1, if1} }};
    split3<<<dim3(2048,1,2), 256>>>(j3, M0*768);
    SJobs j0 = {{ {Wq0, wh0, wl0}, {Wk0, wh0 + 768*768, wl0 + 768*768} }};
    splitk<<<dim3(256,1,2), 256>>>(j0, 768*768);
    SJobs j1 = {{ {Wq1, wh1, wl1}, {Wk1, wh1 + 1536*768, wl1 + 1536*768} }};
    splitk<<<dim3(512,1,2), 256>>>(j1, 1536*768);
    cvtk<<<512, 256>>>(Wo, wo, 1536*768);
    cvtk<<<256, 256>>>(Wv0, wv0f, 768*768);
    cvtk<<<512, 256>>>(Wv1, wv1f, 1536*768);

    dim3 blk(256);
    // q/k projections (bf16 3-term) + v projections (fp16 1-term)
    qkv_gemm<<<dim3(6, 128), blk, GEMM_SMEM>>>(ih0, il0, 768, wh0, wl0, 0,
        bq0, bk0, qh0, ql0, kh0, kl0, amask, N0);
    qkv_gemm<<<dim3(6, 64), blk, GEMM_SMEM>>>(ih1, il1, 1536, wh1, wl1, 384,
        bq1 + 384, bk1 + 384, qh1, ql1, kh1, kl1, amask, N1);
    v_gemm<<<dim3(3, 128), blk, V_SMEM>>>(if0, 768, wv0f, 0, bv0, v0);
    v_gemm<<<dim3(3, 64), blk, V_SMEM>>>(if1, 1536, wv1f, 384, bv1 + 384, v1);

    attn_mma<<<dim3(N0/128, B*NH), blk, ATTN_SMEM>>>(qh0, ql0, kh0, kl0, v0, oh0, ol0, N0);
    attn_mma<<<dim3(N1/128, B*NH), blk, ATTN_SMEM>>>(qh1, ql1, kh1, kl1, v1, oh1, ol1, N1);

    out_gemm<<<dim3(6, 128), blk, OUT_SMEM>>>(oh0, ol0, oh1, ol1, wo, bo, out);
    mask_kernel<<<16, 256>>>(out + OUT_ELEMS);
}

// round 13
// speedup vs baseline: 7.0667x; 1.2535x over previous
#include <cuda_runtime.h>
#include <cuda_bf16.h>
#include <cuda_fp16.h>
#include <stdint.h>
typedef __nv_bfloat16 bf;
typedef __half hf;

#define B 8
#define N0 2048
#define N1 1024
#define HD 384
#define NH 6
#define M0 (B*N0)
#define M1 (B*N1)
#define MT (M0+M1)
#define OUT_ELEMS ((size_t)B*N0*768)

__device__ __align__(128) bf g_ih0[M0*768],  g_il0[M0*768];
__device__ __align__(128) bf g_ih1[M1*1536], g_il1[M1*1536];
__device__ __align__(128) hf g_if0[M0*768],  g_if1[M1*1536];
__device__ __align__(128) bf g_wh0[2][768*768],  g_wl0[2][768*768];
__device__ __align__(128) bf g_wh1[2][1536*768], g_wl1[2][1536*768];
__device__ __align__(128) hf g_wv0f[768*768], g_wv1f[1536*768], g_wo[1536*768];
__device__ __align__(128) bf g_qh[MT*HD], g_ql[MT*HD], g_kh[MT*HD], g_kl[MT*HD];
__device__ __align__(128) hf g_v[MT*HD];
__device__ __align__(128) hf g_o[MT*HD];

__device__ __forceinline__ uint32_t sm_u32(const void* p) {
    return (uint32_t)__cvta_generic_to_shared(p);
}
__device__ __forceinline__ void ldsm4(uint32_t r[4], uint32_t a) {
    asm volatile("ldmatrix.sync.aligned.m8n8.x4.shared.b16 {%0,%1,%2,%3}, [%4];"
        : "=r"(r[0]), "=r"(r[1]), "=r"(r[2]), "=r"(r[3]) : "r"(a));
}
__device__ __forceinline__ void ldsm4t(uint32_t r[4], uint32_t a) {
    asm volatile("ldmatrix.sync.aligned.m8n8.x4.trans.shared.b16 {%0,%1,%2,%3}, [%4];"
        : "=r"(r[0]), "=r"(r[1]), "=r"(r[2]), "=r"(r[3]) : "r"(a));
}
__device__ __forceinline__ void mma_bf(float d[4], const uint32_t a[4],
                                       uint32_t b0, uint32_t b1) {
    asm volatile("mma.sync.aligned.m16n8k16.row.col.f32.bf16.bf16.f32 "
        "{%0,%1,%2,%3}, {%4,%5,%6,%7}, {%8,%9}, {%0,%1,%2,%3};"
        : "+f"(d[0]), "+f"(d[1]), "+f"(d[2]), "+f"(d[3])
        : "r"(a[0]), "r"(a[1]), "r"(a[2]), "r"(a[3]), "r"(b0), "r"(b1));
}
__device__ __forceinline__ void mma_hf(float d[4], const uint32_t a[4],
                                       uint32_t b0, uint32_t b1) {
    asm volatile("mma.sync.aligned.m16n8k16.row.col.f32.f16.f16.f32 "
        "{%0,%1,%2,%3}, {%4,%5,%6,%7}, {%8,%9}, {%0,%1,%2,%3};"
        : "+f"(d[0]), "+f"(d[1]), "+f"(d[2]), "+f"(d[3])
        : "r"(a[0]), "r"(a[1]), "r"(a[2]), "r"(a[3]), "r"(b0), "r"(b1));
}
__device__ __forceinline__ uint32_t bpack(float lo, float hi) {
    __nv_bfloat162 t = __floats2bfloat162_rn(lo, hi);
    return *reinterpret_cast<uint32_t*>(&t);
}
__device__ __forceinline__ void fsplit(float x, float& h, float& l) {
    bf b = __float2bfloat16(x);
    h = __bfloat162float(b);
    l = x - h;
}
__device__ __forceinline__ uint32_t hpack(float lo, float hi) {
    __half2 t = __floats2half2_rn(lo, hi);
    return *reinterpret_cast<uint32_t*>(&t);
}
__device__ __forceinline__ void cpa16(uint32_t d, const void* s) {
    asm volatile("cp.async.cg.shared.global [%0], [%1], 16;" :: "r"(d), "l"(s));
}
__device__ __forceinline__ void cp_commit() { asm volatile("cp.async.commit_group;"); }
__device__ __forceinline__ void cp_wait0()  { asm volatile("cp.async.wait_group 0;"); }
__device__ __forceinline__ void cp_wait1()  { asm volatile("cp.async.wait_group 1;"); }

// ---- prep kernels ----
struct SJob  { const float* s; bf* h; bf* l; };
struct SJobs { SJob j[2]; };
__global__ void splitk(SJobs js, int n) {
    SJob J = js.j[blockIdx.z];
    for (int i = (blockIdx.x*256 + threadIdx.x)*4; i < n; i += gridDim.x*256*4) {
        float4 v = *(const float4*)(J.s + i);
        float h0,l0,h1,l1,h2,l2,h3,l3;
        fsplit(v.x,h0,l0); fsplit(v.y,h1,l1); fsplit(v.z,h2,l2); fsplit(v.w,h3,l3);
        *(uint2*)(J.h + i) = make_uint2(bpack(h0,h1), bpack(h2,h3));
        *(uint2*)(J.l + i) = make_uint2(bpack(l0,l1), bpack(l2,l3));
    }
}
struct S3Job  { const float* s; bf* h; bf* l; hf* f; };
struct S3Jobs { S3Job j[2]; };
__global__ void split3(S3Jobs js, int n) {
    S3Job J = js.j[blockIdx.z];
    for (int i = (blockIdx.x*256 + threadIdx.x)*4; i < n; i += gridDim.x*256*4) {
        float4 v = *(const float4*)(J.s + i);
        float h0,l0,h1,l1,h2,l2,h3,l3;
        fsplit(v.x,h0,l0); fsplit(v.y,h1,l1); fsplit(v.z,h2,l2); fsplit(v.w,h3,l3);
        *(uint2*)(J.h + i) = make_uint2(bpack(h0,h1), bpack(h2,h3));
        *(uint2*)(J.l + i) = make_uint2(bpack(l0,l1), bpack(l2,l3));
        *(uint2*)(J.f + i) = make_uint2(hpack(v.x,v.y), hpack(v.z,v.w));
    }
}
struct CJob  { const float* s; hf* d; int n; };
struct CJobs { CJob j[3]; };
__global__ void cvt3(CJobs js) {
    CJob J = js.j[blockIdx.z];
    for (int i = (blockIdx.x*256 + threadIdx.x)*4; i < J.n; i += gridDim.x*256*4) {
        float4 v = *(const float4*)(J.s + i);
        *(uint2*)(J.d + i) = make_uint2(hpack(v.x, v.y), hpack(v.z, v.w));
    }
}

// ---- tile constants ----
#define GAS 40
#define GBS 136
#define GEMM_SMEM ((2*128*GAS + 2*32*GBS) * 2 * 2)

// bf16 3-term ktile
__device__ __forceinline__ void mma_ktile(
    uint32_t aBH, uint32_t aBL, uint32_t bBH, uint32_t bBL,
    int mrow, int ncol, int lane, float acc[4][4][4])
{
#pragma unroll
    for (int kk = 0; kk < 32; kk += 16) {
        uint32_t ah[4][4], al[4][4];
#pragma unroll
        for (int im = 0; im < 4; im++) {
            uint32_t ad = (uint32_t)((mrow + im*16 + (lane & 15)) * GAS +
                                     kk + ((lane >> 4) << 3)) * 2;
            ldsm4(ah[im], aBH + ad);
            ldsm4(al[im], aBL + ad);
        }
#pragma unroll
        for (int nf = 0; nf < 2; nf++) {
            uint32_t bd = (uint32_t)((kk + (lane & 15)) * GBS + ncol +
                                     nf*16 + ((lane >> 4) << 3)) * 2;
            uint32_t bh4[4], bl4[4];
            ldsm4t(bh4, bBH + bd);
            ldsm4t(bl4, bBL + bd);
#pragma unroll
            for (int im = 0; im < 4; im++) {
#pragma unroll
                for (int j = 0; j < 2; j++) {
                    float* d = acc[im][nf*2 + j];
                    mma_bf(d, ah[im], bh4[2*j], bh4[2*j+1]);
                    mma_bf(d, ah[im], bl4[2*j], bl4[2*j+1]);
                    mma_bf(d, al[im], bh4[2*j], bh4[2*j+1]);
                }
            }
        }
    }
}
__device__ __forceinline__ void gemm_cpa(
    const bf* aH, const bf* aL, int lda,
    const bf* wH, const bf* wL, int ldw,
    int tid, uint32_t dAh, uint32_t dAl, uint32_t dBh, uint32_t dBl)
{
    const int arow = tid >> 1, ak = (tid & 1) << 4;
    const size_t ao = (size_t)arow * lda + ak;
    const uint32_t ad = (uint32_t)(arow * GAS + ak) * 2;
    cpa16(dAh + ad, aH + ao);  cpa16(dAh + ad + 16, aH + ao + 8);
    cpa16(dAl + ad, aL + ao);  cpa16(dAl + ad + 16, aL + ao + 8);
    const int brow = tid >> 3, bc = (tid & 7) << 4;
    const size_t bo = (size_t)brow * ldw + bc;
    const uint32_t bd = (uint32_t)(brow * GBS + bc) * 2;
    cpa16(dBh + bd, wH + bo);  cpa16(dBh + bd + 16, wH + bo + 8);
    cpa16(dBl + bd, wL + bo);  cpa16(dBl + bd + 16, wL + bo + 8);
}

// ---- merged Q/K projection (both levels): grid (6, 192) ----
struct QLv {
    const bf *Ah, *Al, *Wh, *Wl;
    const float *bq, *bk;
    int K, nseq, wOff;
    long orow;
};
__global__ __launch_bounds__(256, 2) void qkv_gemm(
    QLv L0, QLv L1,
    bf* __restrict__ qh, bf* __restrict__ ql,
    bf* __restrict__ kh, bf* __restrict__ kl,
    const float* __restrict__ mask)
{
    extern __shared__ bf ds[];
    bf* Ahs = ds;
    bf* Als = Ahs + 2*128*GAS;
    bf* Bhs = Als + 2*128*GAS;
    bf* Bls = Bhs + 2*32*GBS;

    const int tid = threadIdx.x, lane = tid & 31, warp = tid >> 5;
    const QLv L = (blockIdx.y < 128) ? L0 : L1;
    const int myb = (blockIdx.y < 128) ? blockIdx.y : blockIdx.y - 128;
    const int sel = blockIdx.x / 3, n0 = (blockIdx.x % 3) * 128;
    const int m0 = myb * 128;
    const int K = L.K;
    const int mrow = (warp >> 2) * 64, ncol = (warp & 3) * 32;

    const bf* Wh = L.Wh + (size_t)sel * K * 768 + L.wOff + n0;
    const bf* Wl = L.Wl + (size_t)sel * K * 768 + L.wOff + n0;
    const float* bias = (sel == 0) ? L.bq : L.bk;
    bf* Ch = (sel == 0) ? qh : kh;
    bf* Cl = (sel == 0) ? ql : kl;
    const bf* aH = L.Ah + (size_t)m0 * K;
    const bf* aL = L.Al + (size_t)m0 * K;

    float acc[4][4][4];
#pragma unroll
    for (int i = 0; i < 4; i++)
#pragma unroll
        for (int j = 0; j < 4; j++)
#pragma unroll
            for (int k = 0; k < 4; k++) acc[i][j][k] = 0.f;

    gemm_cpa(aH, aL, K, Wh, Wl, 768, tid,
             sm_u32(Ahs), sm_u32(Als), sm_u32(Bhs), sm_u32(Bls));
    cp_commit();

    int buf = 0;
    for (int k0 = 0; k0 < K; k0 += 32) {
        cp_wait0();
        __syncthreads();
        if (k0 + 32 < K) {
            int nb = buf ^ 1;
            gemm_cpa(aH + k0 + 32, aL + k0 + 32, K,
                     Wh + (size_t)(k0 + 32)*768, Wl + (size_t)(k0 + 32)*768, 768, tid,
                     sm_u32(Ahs + nb*128*GAS), sm_u32(Als + nb*128*GAS),
                     sm_u32(Bhs + nb*32*GBS),  sm_u32(Bls + nb*32*GBS));
            cp_commit();
        }
        mma_ktile(sm_u32(Ahs + buf*128*GAS), sm_u32(Als + buf*128*GAS),
                  sm_u32(Bhs + buf*32*GBS),  sm_u32(Bls + buf*32*GBS),
                  mrow, ncol, lane, acc);
        buf ^= 1;
    }

#pragma unroll
    for (int im = 0; im < 4; im++) {
        int r0g = m0 + mrow + im*16 + (lane >> 2);
#pragma unroll
        for (int f = 0; f < 4; f++) {
            int gcol = n0 + ncol + f*8 + ((lane & 3) << 1);
            float* d = acc[im][f];
#pragma unroll
            for (int hfi = 0; hfi < 2; hfi++) {
                int rr = r0g + hfi*8;
                float x0 = d[hfi*2]     + bias[gcol];
                float x1 = d[hfi*2 + 1] + bias[gcol + 1];
                if (sel == 0) {
                    const float* mk = mask + (rr / L.nseq) * 64;
                    x0 = x0*0.125f + mk[gcol & 63];
                    x1 = x1*0.125f + mk[(gcol + 1) & 63];
                }
                size_t o = (size_t)(L.orow + rr) * HD + gcol;
                float h0,l0,h1,l1;
                fsplit(x0,h0,l0); fsplit(x1,h1,l1);
                *(uint32_t*)(Ch + o) = bpack(h0,h1);
                *(uint32_t*)(Cl + o) = bpack(l0,l1);
            }
        }
    }
}

// ---- fp16 1-term ktile ----
__device__ __forceinline__ void mma_ktile_h1(
    uint32_t aB, uint32_t bB, int mrow, int ncol, int lane, float acc[4][4][4])
{
#pragma unroll
    for (int kk = 0; kk < 32; kk += 16) {
        uint32_t ah[4][4];
#pragma unroll
        for (int im = 0; im < 4; im++) {
            uint32_t ad = (uint32_t)((mrow + im*16 + (lane & 15)) * GAS +
                                     kk + ((lane >> 4) << 3)) * 2;
            ldsm4(ah[im], aB + ad);
        }
#pragma unroll
        for (int nf = 0; nf < 2; nf++) {
            uint32_t bd = (uint32_t)((kk + (lane & 15)) * GBS + ncol +
                                     nf*16 + ((lane >> 4) << 3)) * 2;
            uint32_t b4[4];
            ldsm4t(b4, bB + bd);
#pragma unroll
            for (int im = 0; im < 4; im++) {
#pragma unroll
                for (int j = 0; j < 2; j++)
                    mma_hf(acc[im][nf*2 + j], ah[im], b4[2*j], b4[2*j+1]);
            }
        }
    }
}

#define VST ((128*GAS + 32*GBS) * 2)
#define V_SMEM (3*VST)

// ---- merged V projection (fp16 1-term): grid (3, 192) ----
struct VLv { const hf *A, *Wv; const float* bv; int K, wOff; long orow; };
__global__ __launch_bounds__(256, 2) void v_gemm(VLv L0, VLv L1, hf* __restrict__ v)
{
    extern __shared__ char dsc[];
    const int tid = threadIdx.x, lane = tid & 31, warp = tid >> 5;
    const VLv L = (blockIdx.y < 128) ? L0 : L1;
    const int myb = (blockIdx.y < 128) ? blockIdx.y : blockIdx.y - 128;
    const int n0 = blockIdx.x * 128, m0 = myb * 128;
    const int K = L.K;
    const int mrow = (warp >> 2) * 64, ncol = (warp & 3) * 32;
    const uint32_t sb = sm_u32(dsc);

    float acc[4][4][4];
#pragma unroll
    for (int i = 0; i < 4; i++)
#pragma unroll
        for (int j = 0; j < 4; j++)
#pragma unroll
            for (int k = 0; k < 4; k++) acc[i][j][k] = 0.f;

    auto issue = [&](int t) {
        uint32_t s = sb + (t % 3) * VST;
        const hf* a = L.A + (size_t)m0 * K + t*32;
        const hf* w = L.Wv + (size_t)(t*32) * 768 + L.wOff + n0;
        const int arow = tid >> 1, ak = (tid & 1) << 4;
        const size_t ao = (size_t)arow * K + ak;
        const uint32_t ad = (uint32_t)(arow * GAS + ak) * 2;
        cpa16(s + ad, a + ao);  cpa16(s + ad + 16, a + ao + 8);
        const int brow = tid >> 3, bc = (tid & 7) << 4;
        const size_t bo = (size_t)brow * 768 + bc;
        const uint32_t bd = (uint32_t)(brow * GBS + bc) * 2 + 128*GAS*2;
        cpa16(s + bd, w + bo);  cpa16(s + bd + 16, w + bo + 8);
        cp_commit();
    };

    const int nkt = K / 32;
    issue(0); issue(1);
    for (int t = 0; t < nkt; t++) {
        if (t + 1 < nkt) cp_wait1(); else cp_wait0();
        __syncthreads();
        if (t + 2 < nkt) issue(t + 2);
        uint32_t s = sb + (t % 3) * VST;
        mma_ktile_h1(s, s + 128*GAS*2, mrow, ncol, lane, acc);
        __syncthreads();
    }

#pragma unroll
    for (int im = 0; im < 4; im++) {
        int r0g = m0 + mrow + im*16 + (lane >> 2);
#pragma unroll
        for (int f = 0; f < 4; f++) {
            int gcol = n0 + ncol + f*8 + ((lane & 3) << 1);
            float* d = acc[im][f];
#pragma unroll
            for (int hfi = 0; hfi < 2; hfi++) {
                int rr = r0g + hfi*8;
                *(uint32_t*)(v + (size_t)(L.orow + rr)*HD + gcol) =
                    hpack(d[hfi*2] + L.bv[gcol], d[hfi*2 + 1] + L.bv[gcol + 1]);
            }
        }
    }
}

#define OST VST
#define OUT_SMEM (3*OST)

// ---- output projection (fp16 1-term A): grid (6, 128) ----
__global__ __launch_bounds__(256, 2) void out_gemm(
    const hf* __restrict__ o, const hf* __restrict__ Wo,
    const float* __restrict__ bo, float* __restrict__ out)
{
    extern __shared__ char dsc[];
    const int tid = threadIdx.x, lane = tid & 31, warp = tid >> 5;
    const int n0 = blockIdx.x * 128, m0 = blockIdx.y * 128;
    const int mrow = (warp >> 2) * 64, ncol = (warp & 3) * 32;

    const bool lower = (m0 & 2047) < 1024;
    const int nkt = lower ? 24 : 12;
    const long o1r0 = (long)M0 + (m0 >> 11) * 1024 + (m0 & 2047);
    const uint32_t sb = sm_u32(dsc);

    float acc[4][4][4];
#pragma unroll
    for (int i = 0; i < 4; i++)
#pragma unroll
        for (int j = 0; j < 4; j++)
#pragma unroll
            for (int k = 0; k < 4; k++) acc[i][j][k] = 0.f;

    auto issue = [&](int t) {
        const hf* a; int kc, wr;
        if (t < 12) { a = o + (size_t)m0*HD;   kc = t*32;      wr = t*32; }
        else        { a = o + (size_t)o1r0*HD; kc = (t-12)*32; wr = 768 + (t-12)*32; }
        uint32_t s = sb + (t % 3) * OST;
        const hf* ap = a + kc;
        const hf* w = Wo + (size_t)wr*768 + n0;
        const int arow = tid >> 1, ak = (tid & 1) << 4;
        const size_t ao = (size_t)arow * HD + ak;
        const uint32_t ad = (uint32_t)(arow * GAS + ak) * 2;
        cpa16(s + ad, ap + ao);  cpa16(s + ad + 16, ap + ao + 8);
        const int brow = tid >> 3, bc = (tid & 7) << 4;
        const size_t bo_ = (size_t)brow * 768 + bc;
        const uint32_t bd = (uint32_t)(brow * GBS + bc) * 2 + 128*GAS*2;
        cpa16(s + bd, w + bo_);  cpa16(s + bd + 16, w + bo_ + 8);
        cp_commit();
    };

    issue(0); issue(1);
    for (int t = 0; t < nkt; t++) {
        if (t + 1 < nkt) cp_wait1(); else cp_wait0();
        __syncthreads();
        if (t + 2 < nkt) issue(t + 2);
        uint32_t s = sb + (t % 3) * OST;
        mma_ktile_h1(s, s + 128*GAS*2, mrow, ncol, lane, acc);
        __syncthreads();
    }

#pragma unroll
    for (int im = 0; im < 4; im++) {
        int r0g = m0 + mrow + im*16 + (lane >> 2);
#pragma unroll
        for (int f = 0; f < 4; f++) {
            int gcol = n0 + ncol + f*8 + ((lane & 3) << 1);
            float* d = acc[im][f];
#pragma unroll
            for (int hfi = 0; hfi < 2; hfi++) {
                int rr = r0g + hfi*8;
                out[(size_t)rr*768 + gcol]     = d[hfi*2]     + bo[gcol];
                out[(size_t)rr*768 + gcol + 1] = d[hfi*2 + 1] + bo[gcol + 1];
            }
        }
    }
}

// ---- merged flash attention: grid (24, 48); x<16 level0, else level1 ----
#define AS 72
#define KLB (64*AS*2)
#define SBUF (3*KLB)
#define ATTN_SMEM (3*SBUF)

__global__ __launch_bounds__(256, 2) void attn_mma(
    const bf* __restrict__ qh, const bf* __restrict__ ql,
    const bf* __restrict__ kh, const bf* __restrict__ kl,
    const hf* __restrict__ v, hf* __restrict__ om)
{
    extern __shared__ char smc[];
    bf* smem = (bf*)smc;
    const int tid = threadIdx.x, lane = tid & 31, warp = tid >> 5;
    const int lvl = blockIdx.x >= 16;
    const int qt = lvl ? blockIdx.x - 16 : blockIdx.x;
    const int Nq = lvl ? N1 : N0;
    const size_t lbase = lvl ? (size_t)M0 * HD : 0;
    const int b = blockIdx.y / NH, h = blockIdx.y % NH;
    const int q0 = qt * 128;
    const size_t gb = lbase + (size_t)b*Nq*HD + (size_t)h*64;
    const int mrow = warp * 16;

    {
        const bf* Qh = qh + gb + (size_t)q0*HD;
        const bf* Ql = ql + gb + (size_t)q0*HD;
#pragma unroll
        for (int it = 0; it < 4; it++) {
            int i = tid + it*256, r = i >> 3, u = (i & 7)*8;
            *(uint4*)&smem[r*AS + u]          = *(const uint4*)&Qh[(size_t)r*HD + u];
            *(uint4*)&smem[128*AS + r*AS + u] = *(const uint4*)&Ql[(size_t)r*HD + u];
        }
    }
    __syncthreads();
    uint32_t qfh[4][4], qfl[4][4];
    {
        const uint32_t bh_ = sm_u32(smem), bl_ = sm_u32(smem) + 128*AS*2;
        int row = mrow + (lane & 15);
#pragma unroll
        for (int kk = 0; kk < 4; kk++) {
            uint32_t off = (uint32_t)(row*AS + kk*16 + ((lane >> 4) << 3))*2;
            ldsm4(qfh[kk], bh_ + off);
            ldsm4(qfl[kk], bl_ + off);
        }
    }
    __syncthreads();

    const uint32_t base0 = sm_u32(smc);
    auto kvload = [&](int s) {
        int kv = s * 64;
        const bf* Kh = kh + gb + (size_t)kv*HD;
        const bf* Kl = kl + gb + (size_t)kv*HD;
        const hf* V  = v  + gb + (size_t)kv*HD;
        uint32_t d = base0 + (s % 3) * SBUF;
#pragma unroll
        for (int it = 0; it < 2; it++) {
            int i = tid + it*256, r = i >> 3, u = (i & 7)*8;
            size_t go = (size_t)r*HD + u;
            uint32_t so = (uint32_t)(r*AS + u)*2;
            cpa16(d + so,         Kh + go);
            cpa16(d + KLB + so,   Kl + go);
            cpa16(d + 2*KLB + so, V  + go);
        }
        cp_commit();
    };

    float o[8][4];
#pragma unroll
    for (int f = 0; f < 8; f++)
#pragma unroll
        for (int k = 0; k < 4; k++) o[f][k] = 0.f;
    float mr0 = -1e30f, mr1 = -1e30f, lr0 = 0.f, lr1 = 0.f;

    const int S = Nq / 64;
    kvload(0); kvload(1);
    for (int t = 0; t < S; t++) {
        if (t + 1 < S) cp_wait1(); else cp_wait0();
        __syncthreads();
        if (t + 2 < S) kvload(t + 2);

        const uint32_t bb = base0 + (t % 3) * SBUF;
        const uint32_t kBH = bb, kBL = bb + KLB, vB = bb + 2*KLB;

        float s[8][4];
#pragma unroll
        for (int f = 0; f < 8; f++)
#pragma unroll
            for (int k = 0; k < 4; k++) s[f][k] = 0.f;
#pragma unroll
        for (int kk = 0; kk < 4; kk++) {
#pragma unroll
            for (int nf = 0; nf < 4; nf++) {
                uint32_t ad = (uint32_t)((nf*16 + (lane & 15))*AS + kk*16 +
                                         ((lane >> 4) << 3))*2;
                uint32_t kb[4], kl4[4];
                ldsm4(kb, kBH + ad); ldsm4(kl4, kBL + ad);
                mma_bf(s[nf*2],   qfh[kk], kb[0],  kb[2]);
                mma_bf(s[nf*2],   qfh[kk], kl4[0], kl4[2]);
                mma_bf(s[nf*2],   qfl[kk], kb[0],  kb[2]);
                mma_bf(s[nf*2+1], qfh[kk], kb[1],  kb[3]);
                mma_bf(s[nf*2+1], qfh[kk], kl4[1], kl4[3]);
                mma_bf(s[nf*2+1], qfl[kk], kb[1],  kb[3]);
            }
        }

        float mx0 = -1e30f, mx1 = -1e30f;
#pragma unroll
        for (int f = 0; f < 8; f++) {
            mx0 = fmaxf(mx0, fmaxf(s[f][0], s[f][1]));
            mx1 = fmaxf(mx1, fmaxf(s[f][2], s[f][3]));
        }
        mx0 = fmaxf(mx0, __shfl_xor_sync(~0u, mx0, 1));
        mx0 = fmaxf(mx0, __shfl_xor_sync(~0u, mx0, 2));
        mx1 = fmaxf(mx1, __shfl_xor_sync(~0u, mx1, 1));
        mx1 = fmaxf(mx1, __shfl_xor_sync(~0u, mx1, 2));
        float mn0 = fmaxf(mr0, mx0), mn1 = fmaxf(mr1, mx1);
        float c0 = __expf(mr0 - mn0), c1 = __expf(mr1 - mn1);
        float rs0 = 0.f, rs1 = 0.f;
#pragma unroll
        for (int f = 0; f < 8; f++) {
            s[f][0] = __expf(s[f][0] - mn0); s[f][1] = __expf(s[f][1] - mn0);
            s[f][2] = __expf(s[f][2] - mn1); s[f][3] = __expf(s[f][3] - mn1);
            rs0 += s[f][0] + s[f][1]; rs1 += s[f][2] + s[f][3];
        }
        rs0 += __shfl_xor_sync(~0u, rs0, 1); rs0 += __shfl_xor_sync(~0u, rs0, 2);
        rs1 += __shfl_xor_sync(~0u, rs1, 1); rs1 += __shfl_xor_sync(~0u, rs1, 2);
        lr0 = lr0*c0 + rs0; lr1 = lr1*c1 + rs1;
        mr0 = mn0; mr1 = mn1;
#pragma unroll
        for (int f = 0; f < 8; f++) {
            o[f][0] *= c0; o[f][1] *= c0; o[f][2] *= c1; o[f][3] *= c1;
        }

        // O += P @ V : P single fp16 (rounding ~2^-11, linear path)
#pragma unroll
        for (int kk2 = 0; kk2 < 4; kk2++) {
            uint32_t pa[4];
            {
                int f0 = kk2*2;
                pa[0] = hpack(s[f0][0],   s[f0][1]);
                pa[1] = hpack(s[f0][2],   s[f0][3]);
                pa[2] = hpack(s[f0+1][0], s[f0+1][1]);
                pa[3] = hpack(s[f0+1][2], s[f0+1][3]);
            }
#pragma unroll
            for (int nf = 0; nf < 4; nf++) {
                uint32_t ad = (uint32_t)((kk2*16 + (lane & 15))*AS + nf*16 +
                                         ((lane >> 4) << 3))*2;
                uint32_t vb[4];
                ldsm4t(vb, vB + ad);
                mma_hf(o[nf*2],   pa, vb[0], vb[1]);
                mma_hf(o[nf*2+1], pa, vb[2], vb[3]);
            }
        }
    }

    float i0 = 1.f/lr0, i1 = 1.f/lr1;
    int rg = q0 + mrow + (lane >> 2);
#pragma unroll
    for (int f = 0; f < 8; f++) {
        int cc = f*8 + ((lane & 3) << 1);
        *(uint32_t*)(om + gb + (size_t)rg*HD + cc)     = hpack(o[f][0]*i0, o[f][1]*i0);
        *(uint32_t*)(om + gb + (size_t)(rg+8)*HD + cc) = hpack(o[f][2]*i1, o[f][3]*i1);
    }
}

__global__ void mask_kernel(float* __restrict__ out) {
    int i = blockIdx.x*blockDim.x + threadIdx.x;
    if (i < 2*N0) {
        int lvl = i >> 11, n = i & (N0 - 1);
        out[i] = (lvl == 0 || n < N1) ? 1.f : 0.f;
    }
}

extern "C" void kernel_launch(void* const* d_in, const int* in_sizes, int n_in,
                              void* d_out, int out_size)
{
    (void)in_sizes; (void)n_in; (void)out_size;
    const float* inp0 = (const float*)d_in[0];
    const float* inp1 = (const float*)d_in[1];
    const float* amask = (const float*)d_in[2];
    const float *Wq0 = (const float*)d_in[3],  *bq0 = (const float*)d_in[4];
    const float *Wk0 = (const float*)d_in[5],  *bk0 = (const float*)d_in[6];
    const float *Wv0 = (const float*)d_in[7],  *bv0 = (const float*)d_in[8];
    const float *Wq1 = (const float*)d_in[9],  *bq1 = (const float*)d_in[10];
    const float *Wk1 = (const float*)d_in[11], *bk1 = (const float*)d_in[12];
    const float *Wv1 = (const float*)d_in[13], *bv1 = (const float*)d_in[14];
    const float *Wo  = (const float*)d_in[15], *bo  = (const float*)d_in[16];
    float* out = (float*)d_out;

    bf *ih0,*il0,*ih1,*il1,*wh0,*wl0,*wh1,*wl1,*qh,*ql,*kh,*kl;
    hf *if0,*if1,*wv0f,*wv1f,*wo,*v,*o;
    cudaGetSymbolAddress((void**)&ih0,g_ih0); cudaGetSymbolAddress((void**)&il0,g_il0);
    cudaGetSymbolAddress((void**)&ih1,g_ih1); cudaGetSymbolAddress((void**)&il1,g_il1);
    cudaGetSymbolAddress((void**)&if0,g_if0); cudaGetSymbolAddress((void**)&if1,g_if1);
    cudaGetSymbolAddress((void**)&wh0,g_wh0); cudaGetSymbolAddress((void**)&wl0,g_wl0);
    cudaGetSymbolAddress((void**)&wh1,g_wh1); cudaGetSymbolAddress((void**)&wl1,g_wl1);
    cudaGetSymbolAddress((void**)&wv0f,g_wv0f); cudaGetSymbolAddress((void**)&wv1f,g_wv1f);
    cudaGetSymbolAddress((void**)&wo,g_wo);
    cudaGetSymbolAddress((void**)&qh,g_qh); cudaGetSymbolAddress((void**)&ql,g_ql);
    cudaGetSymbolAddress((void**)&kh,g_kh); cudaGetSymbolAddress((void**)&kl,g_kl);
    cudaGetSymbolAddress((void**)&v,g_v);   cudaGetSymbolAddress((void**)&o,g_o);

    cudaFuncSetAttribute(qkv_gemm, cudaFuncAttributeMaxDynamicSharedMemorySize, GEMM_SMEM);
    cudaFuncSetAttribute(v_gemm,   cudaFuncAttributeMaxDynamicSharedMemorySize, V_SMEM);
    cudaFuncSetAttribute(out_gemm, cudaFuncAttributeMaxDynamicSharedMemorySize, OUT_SMEM);
    cudaFuncSetAttribute(attn_mma, cudaFuncAttributeMaxDynamicSharedMemorySize, ATTN_SMEM);

    // prep
    S3Jobs j3 = {{ {inp0, ih0, il0, if0}, {inp1, ih1, il1, if1} }};
    split3<<<dim3(2048,1,2), 256>>>(j3, M0*768);
    SJobs j0 = {{ {Wq0, wh0, wl0}, {Wk0, wh0 + 768*768, wl0 + 768*768} }};
    splitk<<<dim3(256,1,2), 256>>>(j0, 768*768);
    SJobs j1 = {{ {Wq1, wh1, wl1}, {Wk1, wh1 + 1536*768, wl1 + 1536*768} }};
    splitk<<<dim3(512,1,2), 256>>>(j1, 1536*768);
    CJobs jc = {{ {Wo, wo, 1536*768}, {Wv0, wv0f, 768*768}, {Wv1, wv1f, 1536*768} }};
    cvt3<<<dim3(512,1,3), 256>>>(jc);

    dim3 blk(256);
    QLv ql0 = {ih0, il0, wh0, wl0, bq0, bk0, 768, N0, 0, 0};
    QLv ql1 = {ih1, il1, wh1, wl1, bq1 + 384, bk1 + 384, 1536, N1, 384, M0};
    qkv_gemm<<<dim3(6, 192), blk, GEMM_SMEM>>>(ql0, ql1, qh, ql, kh, kl, amask);

    VLv vl0 = {if0, wv0f, bv0, 768, 0, 0};
    VLv vl1 = {if1, wv1f, bv1 + 384, 1536, 384, M0};
    v_gemm<<<dim3(3, 192), blk, V_SMEM>>>(vl0, vl1, v);

    attn_mma<<<dim3(24, 48), blk, ATTN_SMEM>>>(qh, ql, kh, kl, v, o);

    out_gemm<<<dim3(6, 128), blk, OUT_SMEM>>>(o, wo, bo, out);
    mask_kernel<<<16, 256>>>(out + OUT_ELEMS);
}